// round 8
// baseline (speedup 1.0000x reference)
#include <cuda_runtime.h>
#include <cuda_bf16.h>
#include <cstdint>

static constexpr int B_   = 8;
static constexpr int C_   = 256;
static constexpr int CQK_ = 32;
static constexpr int N_   = 4096;

// Scratch
__device__ float g_o[(size_t)B_ * C_ * N_];
__device__ __align__(256) __nv_bfloat16 g_qh[(size_t)B_ * N_ * CQK_];
__device__ __align__(256) __nv_bfloat16 g_ql[(size_t)B_ * N_ * CQK_];
__device__ __align__(256) __nv_bfloat16 g_kh[(size_t)B_ * N_ * CQK_];
__device__ __align__(256) __nv_bfloat16 g_kl[(size_t)B_ * N_ * CQK_];
__device__ __align__(256) __nv_bfloat16 g_vh[(size_t)B_ * C_ * N_];

// ---------------- packed f32x2 ----------------
using u64_t = unsigned long long;
__device__ __forceinline__ u64_t pack2(float lo, float hi) {
    u64_t r; asm("mov.b64 %0, {%1, %2};" : "=l"(r) : "f"(lo), "f"(hi)); return r;
}
__device__ __forceinline__ u64_t bcast2(float x) { return pack2(x, x); }
__device__ __forceinline__ u64_t fma2(u64_t a, u64_t b, u64_t c) {
    u64_t d; asm("fma.rn.f32x2 %0, %1, %2, %3;" : "=l"(d) : "l"(a), "l"(b), "l"(c)); return d;
}
__device__ __forceinline__ float2 unpack2(u64_t a) {
    float2 f; asm("mov.b64 {%0, %1}, %2;" : "=f"(f.x), "=f"(f.y) : "l"(a)); return f;
}

// ---------------- mma / ldmatrix / cp.async ----------------
__device__ __forceinline__ uint32_t smem_u32(const void* p) {
    uint32_t a;
    asm("{ .reg .u64 t; cvta.to.shared.u64 t, %1; cvt.u32.u64 %0, t; }" : "=r"(a) : "l"(p));
    return a;
}
__device__ __forceinline__ void cpa16(uint32_t dst, const void* src) {
    asm volatile("cp.async.cg.shared.global [%0], [%1], 16;" :: "r"(dst), "l"(src) : "memory");
}
#define CPA_COMMIT() asm volatile("cp.async.commit_group;" ::: "memory")
#define CPA_WAIT(n)  asm volatile("cp.async.wait_group %0;" :: "n"(n) : "memory")

__device__ __forceinline__ void ldsm4(uint32_t addr, uint32_t* r) {
    asm volatile("ldmatrix.sync.aligned.m8n8.x4.shared.b16 {%0,%1,%2,%3}, [%4];"
                 : "=r"(r[0]), "=r"(r[1]), "=r"(r[2]), "=r"(r[3]) : "r"(addr));
}
__device__ __forceinline__ void mma16816(float* d, const uint32_t* a, uint32_t b0, uint32_t b1) {
    asm volatile("mma.sync.aligned.m16n8k16.row.col.f32.bf16.bf16.f32 "
                 "{%0,%1,%2,%3}, {%4,%5,%6,%7}, {%8,%9}, {%0,%1,%2,%3};"
                 : "+f"(d[0]), "+f"(d[1]), "+f"(d[2]), "+f"(d[3])
                 : "r"(a[0]), "r"(a[1]), "r"(a[2]), "r"(a[3]), "r"(b0), "r"(b1));
}
__device__ __forceinline__ uint32_t pack_bf16x2(float e0, float e1) {
    uint32_t r; asm("cvt.rn.bf16x2.f32 %0, %1, %2;" : "=r"(r) : "f"(e1), "f"(e0)); return r;
}
__device__ __forceinline__ float lo_bf16_f(uint32_t u) { return __uint_as_float(u << 16); }
__device__ __forceinline__ float hi_bf16_f(uint32_t u) { return __uint_as_float(u & 0xffff0000u); }
__device__ __forceinline__ void bf16_split(float v, __nv_bfloat16& h, __nv_bfloat16& l) {
    h = __float2bfloat16(v);
    l = __float2bfloat16(v - __bfloat162float(h));
}

// ---------------- Q/K projection: fp32 compute -> bf16 hi/lo [B][N][32] -------
__global__ __launch_bounds__(256)
void proj_qk_kernel(const float* __restrict__ W, const float* __restrict__ bias,
                    const float* __restrict__ X,
                    __nv_bfloat16* __restrict__ Yh, __nv_bfloat16* __restrict__ Yl)
{
    constexpr int BM = 32, BK = 32, BN = 64, TM = 2;
    __shared__ float Ws[BK][BM + 4];
    __shared__ float Xs[BK][BN];

    const int b  = blockIdx.z;
    const int n0 = blockIdx.x * BN;
    const float* Xb = X + (size_t)b * C_ * N_;

    const int tid = threadIdx.x;
    const int tm  = (tid / 16) * TM;
    const int tn  = (tid % 16) * 4;

    u64_t acc2[TM][2];
#pragma unroll
    for (int i = 0; i < TM; i++) { acc2[i][0] = pack2(0.f,0.f); acc2[i][1] = pack2(0.f,0.f); }

    for (int k0 = 0; k0 < C_; k0 += BK) {
        for (int i = tid; i < BM * BK; i += 256) {
            int m = i / BK, k = i % BK;
            Ws[k][m] = W[(size_t)m * C_ + (k0 + k)];
        }
        for (int i = tid; i < BK * BN / 4; i += 256) {
            int k = i / (BN / 4), n4 = (i % (BN / 4)) * 4;
            *(float4*)&Xs[k][n4] = *(const float4*)&Xb[(size_t)(k0 + k) * N_ + (n0 + n4)];
        }
        __syncthreads();
#pragma unroll
        for (int k = 0; k < BK; k++) {
            float2 w2 = *(const float2*)&Ws[k][tm];
            float4 x4 = *(const float4*)&Xs[k][tn];
            u64_t xp0 = pack2(x4.x, x4.y), xp1 = pack2(x4.z, x4.w);
            u64_t wb0 = bcast2(w2.x), wb1 = bcast2(w2.y);
            acc2[0][0] = fma2(xp0, wb0, acc2[0][0]);
            acc2[0][1] = fma2(xp1, wb0, acc2[0][1]);
            acc2[1][0] = fma2(xp0, wb1, acc2[1][0]);
            acc2[1][1] = fma2(xp1, wb1, acc2[1][1]);
        }
        __syncthreads();
    }
#pragma unroll
    for (int i = 0; i < TM; i++) {
        int m = tm + i;
        float bb = bias[m];
        float2 a0 = unpack2(acc2[i][0]), a1 = unpack2(acc2[i][1]);
        float vals[4] = {a0.x + bb, a0.y + bb, a1.x + bb, a1.y + bb};
#pragma unroll
        for (int j = 0; j < 4; j++) {
            size_t o = ((size_t)b * N_ + n0 + tn + j) * CQK_ + m;
            __nv_bfloat16 h, l; bf16_split(vals[j], h, l);
            Yh[o] = h; Yl[o] = l;
        }
    }
}

// ---------------- V projection: fp32 compute -> bf16 (hi only) [B][C][N] ------
__global__ __launch_bounds__(256)
void proj_vh_kernel(const float* __restrict__ W, const float* __restrict__ bias,
                    const float* __restrict__ X, __nv_bfloat16* __restrict__ Yh)
{
    constexpr int BM = 64, BK = 32, BN = 64, TM = 4;
    __shared__ float Ws[BK][BM + 4];
    __shared__ float Xs[BK][BN];

    const int b  = blockIdx.z;
    const int m0 = blockIdx.y * BM;
    const int n0 = blockIdx.x * BN;
    const float* Xb = X + (size_t)b * C_ * N_;

    const int tid = threadIdx.x;
    const int tm  = (tid / 16) * TM;
    const int tn  = (tid % 16) * 4;

    u64_t acc2[TM][2];
#pragma unroll
    for (int i = 0; i < TM; i++) { acc2[i][0] = pack2(0.f,0.f); acc2[i][1] = pack2(0.f,0.f); }

    for (int k0 = 0; k0 < C_; k0 += BK) {
        for (int i = tid; i < BM * BK; i += 256) {
            int m = i / BK, k = i % BK;
            Ws[k][m] = W[(size_t)(m0 + m) * C_ + (k0 + k)];
        }
        for (int i = tid; i < BK * BN / 4; i += 256) {
            int k = i / (BN / 4), n4 = (i % (BN / 4)) * 4;
            *(float4*)&Xs[k][n4] = *(const float4*)&Xb[(size_t)(k0 + k) * N_ + (n0 + n4)];
        }
        __syncthreads();
#pragma unroll
        for (int k = 0; k < BK; k++) {
            float4 w4 = *(const float4*)&Ws[k][tm];
            float wr[4] = {w4.x, w4.y, w4.z, w4.w};
            float4 x4 = *(const float4*)&Xs[k][tn];
            u64_t xp0 = pack2(x4.x, x4.y), xp1 = pack2(x4.z, x4.w);
#pragma unroll
            for (int i = 0; i < TM; i++) {
                u64_t wb = bcast2(wr[i]);
                acc2[i][0] = fma2(xp0, wb, acc2[i][0]);
                acc2[i][1] = fma2(xp1, wb, acc2[i][1]);
            }
        }
        __syncthreads();
    }
#pragma unroll
    for (int i = 0; i < TM; i++) {
        int m = m0 + tm + i;
        float bb = bias[m];
        float2 a0 = unpack2(acc2[i][0]), a1 = unpack2(acc2[i][1]);
        __nv_bfloat162 p01, p23;
        p01.x = __float2bfloat16(a0.x + bb); p01.y = __float2bfloat16(a0.y + bb);
        p23.x = __float2bfloat16(a1.x + bb); p23.y = __float2bfloat16(a1.y + bb);
        size_t base = ((size_t)b * C_ + m) * N_ + n0 + tn;
        *(__nv_bfloat162*)&Yh[base]     = p01;
        *(__nv_bfloat162*)&Yh[base + 2] = p23;
    }
}

// ---------------- final projection (fp32 in/out) ----------------
__global__ __launch_bounds__(256)
void proj_f_kernel(const float* __restrict__ W, const float* __restrict__ bias,
                   const float* __restrict__ X, float* __restrict__ Y)
{
    constexpr int BM = 64, BK = 32, BN = 64, TM = 4;
    __shared__ float Ws[BK][BM + 4];
    __shared__ float Xs[BK][BN];

    const int b  = blockIdx.z;
    const int m0 = blockIdx.y * BM;
    const int n0 = blockIdx.x * BN;
    const float* Xb = X + (size_t)b * C_ * N_;
    float*       Yb = Y + (size_t)b * C_ * N_;

    const int tid = threadIdx.x;
    const int tm  = (tid / 16) * TM;
    const int tn  = (tid % 16) * 4;

    u64_t acc2[TM][2];
#pragma unroll
    for (int i = 0; i < TM; i++) { acc2[i][0] = pack2(0.f,0.f); acc2[i][1] = pack2(0.f,0.f); }

    for (int k0 = 0; k0 < C_; k0 += BK) {
        for (int i = tid; i < BM * BK; i += 256) {
            int m = i / BK, k = i % BK;
            Ws[k][m] = W[(size_t)(m0 + m) * C_ + (k0 + k)];
        }
        for (int i = tid; i < BK * BN / 4; i += 256) {
            int k = i / (BN / 4), n4 = (i % (BN / 4)) * 4;
            *(float4*)&Xs[k][n4] = *(const float4*)&Xb[(size_t)(k0 + k) * N_ + (n0 + n4)];
        }
        __syncthreads();
#pragma unroll
        for (int k = 0; k < BK; k++) {
            float4 w4 = *(const float4*)&Ws[k][tm];
            float wr[4] = {w4.x, w4.y, w4.z, w4.w};
            float4 x4 = *(const float4*)&Xs[k][tn];
            u64_t xp0 = pack2(x4.x, x4.y), xp1 = pack2(x4.z, x4.w);
#pragma unroll
            for (int i = 0; i < TM; i++) {
                u64_t wb = bcast2(wr[i]);
                acc2[i][0] = fma2(xp0, wb, acc2[i][0]);
                acc2[i][1] = fma2(xp1, wb, acc2[i][1]);
            }
        }
        __syncthreads();
    }
#pragma unroll
    for (int i = 0; i < TM; i++) {
        float bb = bias[m0 + tm + i];
        float2 a0 = unpack2(acc2[i][0]), a1 = unpack2(acc2[i][1]);
        float4 o4 = make_float4(a0.x + bb, a0.y + bb, a1.x + bb, a1.y + bb);
        *(float4*)&Yb[(size_t)(m0 + tm + i) * N_ + (n0 + tn)] = o4;
    }
}

// ---------------- flash attention on mma.sync (symmetric warps) --------------
// 8 warps; warp w owns q-rows (w&3)*16 and channels (w>>2)*128.
// QK split by key-halves: group g = w>>2 computes S for keys g*32..g*32+31
// (24 MMAs, 3-term), exps its half (16 exps), exchanges half-P with partner
// warp w^4 (same rows, other key half) via lane-for-lane smem mirror.
// PV: 2-term (PhVh + PlVh), 128 MMAs, identical for all warps.
// smem layout (bytes):
//   [0,16384)      P exchange: hi @0, lo @8192.
//                  per region: [rowgrp 0-3]*2048 + [khalf]*1024 + [kj]*512
//                  + [lane]*16   (rowgrp region = 2 khalf x 2 kj x 32 lanes x 16B)
//                  (overlaid: Q tile [0,10240) until qa fragments loaded;
//                   overlaid after loop: 2x64 f32 row-sum arrays)
//   [16640,37120)  K bufs: 2 x (hi 5120 | lo 5120), rows 80 B
//   [37120,110848) V bufs: 2 x 36864 (hi only), rows 144 B
static constexpr int SP_HI = 0;
static constexpr int SP_LO = 8192;
static constexpr int SQH   = 0;
static constexpr int SQL   = 5120;
static constexpr int SKB   = 16640;
static constexpr int SVB   = 37120;
static constexpr int FL_SMEM = 110848;

__global__ __launch_bounds__(256, 2)
void flash_mma_kernel(const __nv_bfloat16* __restrict__ Qh, const __nv_bfloat16* __restrict__ Ql,
                      const __nv_bfloat16* __restrict__ Kh, const __nv_bfloat16* __restrict__ Kl,
                      const __nv_bfloat16* __restrict__ Vh, float* __restrict__ O)
{
    extern __shared__ char smem[];
    const uint32_t sb = smem_u32(smem);
    const int tid = threadIdx.x, lane = tid & 31, w = tid >> 5;
    const int qw = (w & 3) * 16;          // warp's first query row
    const int khalf = w >> 2;             // key half this warp computes S for
    const int cbase = (w >> 2) * 128;     // warp's channel half for PV
    const int b = blockIdx.y, q0 = blockIdx.x * 64;

    auto load_kv = [&](int kt, int bi) {
        const int j0 = kt * 64;
        for (int i = tid; i < 512; i += 256) {
            int half = i >> 8, r = (i >> 2) & 63, ch = i & 3;
            const __nv_bfloat16* src = (half ? Kl : Kh) + ((size_t)b * N_ + j0 + r) * CQK_ + ch * 8;
            cpa16(sb + SKB + bi * 10240 + half * 5120 + r * 80 + ch * 16, src);
        }
        for (int i = tid; i < 2048; i += 256) {
            int r = i >> 3, ch = i & 7;
            const __nv_bfloat16* src = Vh + ((size_t)b * C_ + r) * N_ + j0 + ch * 8;
            cpa16(sb + SVB + bi * 36864 + r * 144 + ch * 16, src);
        }
    };

    // prologue: Q + tiles 0,1
    for (int i = tid; i < 512; i += 256) {
        int half = i >> 8, r = (i >> 2) & 63, ch = i & 3;
        const __nv_bfloat16* src = (half ? Ql : Qh) + ((size_t)b * N_ + q0 + r) * CQK_ + ch * 8;
        cpa16(sb + (half ? SQL : SQH) + r * 80 + ch * 16, src);
    }
    load_kv(0, 0); CPA_COMMIT();
    load_kv(1, 1); CPA_COMMIT();
    CPA_WAIT(1);
    __syncthreads();

    // Q A-fragments (all warps: rows qw..qw+15)
    uint32_t qa[2][2][4];
#pragma unroll
    for (int hl = 0; hl < 2; hl++)
#pragma unroll
        for (int kc = 0; kc < 2; kc++) {
            uint32_t addr = sb + (hl ? SQL : SQH)
                          + (uint32_t)(qw + (lane & 15)) * 80
                          + (uint32_t)(kc * 16 + (lane >> 4) * 8) * 2;
            ldsm4(addr, qa[hl][kc]);
        }
    __syncthreads();   // Q region is dead; P exchange may now overwrite it

    float oacc[16][4];
#pragma unroll
    for (int i = 0; i < 16; i++)
#pragma unroll
        for (int j = 0; j < 4; j++) oacc[i][j] = 0.f;
    float rsum0 = 0.f, rsum1 = 0.f;

    // exchange addresses (lane-for-lane mirror with partner warp w^4)
    // per rowgroup: 2048 B = 2 khalf x (2 kj x 512 B)
    const uint32_t ex_wr = (uint32_t)((w & 3) * 2048 + khalf * 1024 + lane * 16);
    const uint32_t ex_rd = (uint32_t)((w & 3) * 2048 + (khalf ^ 1) * 1024 + lane * 16);

    for (int kt = 0; kt < 64; kt++) {
        const int bi = kt & 1;
        const uint32_t kh_b = sb + SKB + bi * 10240, kl_b = kh_b + 5120;
        const uint32_t vh_b = sb + SVB + bi * 36864;

        // --- S for this warp's key half (3-term bf16 split, 24 MMAs) ---
        float sacc[4][4];
#pragma unroll
        for (int i = 0; i < 4; i++)
#pragma unroll
            for (int j = 0; j < 4; j++) sacc[i][j] = 0.f;
#pragma unroll
        for (int kc = 0; kc < 2; kc++)
#pragma unroll
            for (int nbl = 0; nbl < 2; nbl++) {
                int nbp = khalf * 2 + nbl;
                uint32_t off = (uint32_t)((nbp * 2 + ((lane >> 4) & 1)) * 8 + (lane & 7)) * 80
                             + (uint32_t)(kc * 16 + ((lane >> 3) & 1) * 8) * 2;
                uint32_t bh[4], bl[4];
                ldsm4(kh_b + off, bh);
                ldsm4(kl_b + off, bl);
                mma16816(sacc[2*nbl],   qa[0][kc], bh[0], bh[1]);
                mma16816(sacc[2*nbl+1], qa[0][kc], bh[2], bh[3]);
                mma16816(sacc[2*nbl],   qa[1][kc], bh[0], bh[1]);
                mma16816(sacc[2*nbl+1], qa[1][kc], bh[2], bh[3]);
                mma16816(sacc[2*nbl],   qa[0][kc], bl[0], bl[1]);
                mma16816(sacc[2*nbl+1], qa[0][kc], bl[2], bl[3]);
            }

        // --- P = exp(S) for this half; pack bf16 hi/lo (16 exps) ---
        uint32_t pmh[2][4], pml[2][4];
#pragma unroll
        for (int nb = 0; nb < 4; nb++) {
            float e0 = __expf(sacc[nb][0]);
            float e1 = __expf(sacc[nb][1]);
            float e2 = __expf(sacc[nb][2]);
            float e3 = __expf(sacc[nb][3]);
            rsum0 += e0 + e1;
            rsum1 += e2 + e3;
            int kj = nb >> 1, o = (nb & 1) * 2;
            uint32_t h01 = pack_bf16x2(e0, e1);
            uint32_t h23 = pack_bf16x2(e2, e3);
            pmh[kj][o]     = h01;
            pmh[kj][o + 1] = h23;
            pml[kj][o]     = pack_bf16x2(e0 - lo_bf16_f(h01), e1 - hi_bf16_f(h01));
            pml[kj][o + 1] = pack_bf16x2(e2 - lo_bf16_f(h23), e3 - hi_bf16_f(h23));
        }

        // --- mirror half-P to smem for partner warp (lane-for-lane) ---
#pragma unroll
        for (int kj = 0; kj < 2; kj++) {
            *(uint4*)(smem + SP_HI + ex_wr + kj * 512) =
                make_uint4(pmh[kj][0], pmh[kj][1], pmh[kj][2], pmh[kj][3]);
            *(uint4*)(smem + SP_LO + ex_wr + kj * 512) =
                make_uint4(pml[kj][0], pml[kj][1], pml[kj][2], pml[kj][3]);
        }
        __syncthreads();   // both halves of P visible

        // --- assemble full P fragments (own half + partner half) ---
        uint32_t pah[4][4], pal[4][4];
#pragma unroll
        for (int kj = 0; kj < 2; kj++) {
            int own = khalf * 2 + kj, oth = (khalf ^ 1) * 2 + kj;
            pah[own][0] = pmh[kj][0]; pah[own][1] = pmh[kj][1];
            pah[own][2] = pmh[kj][2]; pah[own][3] = pmh[kj][3];
            pal[own][0] = pml[kj][0]; pal[own][1] = pml[kj][1];
            pal[own][2] = pml[kj][2]; pal[own][3] = pml[kj][3];
            uint4 h4 = *(const uint4*)(smem + SP_HI + ex_rd + kj * 512);
            uint4 l4 = *(const uint4*)(smem + SP_LO + ex_rd + kj * 512);
            pah[oth][0] = h4.x; pah[oth][1] = h4.y; pah[oth][2] = h4.z; pah[oth][3] = h4.w;
            pal[oth][0] = l4.x; pal[oth][1] = l4.y; pal[oth][2] = l4.z; pal[oth][3] = l4.w;
        }

        // --- O += P V^T (2-term) over this warp's 128 channels (128 MMAs) ---
#pragma unroll
        for (int cb = 0; cb < 16; cb++) {
            uint32_t rowoff = (uint32_t)(cbase + cb * 8 + (lane & 7)) * 144;
            uint32_t vfh[8];
#pragma unroll
            for (int kjp = 0; kjp < 2; kjp++) {
                uint32_t off = rowoff + (uint32_t)(kjp * 32 + (lane >> 3) * 8) * 2;
                ldsm4(vh_b + off, &vfh[4 * kjp]);
            }
#pragma unroll
            for (int kj = 0; kj < 4; kj++) {
                int ix = (kj >> 1) * 4 + (kj & 1) * 2;
                mma16816(oacc[cb], pah[kj], vfh[ix], vfh[ix + 1]);
                mma16816(oacc[cb], pal[kj], vfh[ix], vfh[ix + 1]);
            }
        }

        // --- pipeline: refill this buffer with tile kt+2 ---
        __syncthreads();                 // all reads of K/V(bi) and P done
        if (kt + 2 < 64) load_kv(kt + 2, bi);
        CPA_COMMIT();
        CPA_WAIT(1);                     // tile kt+1 resident
        __syncthreads();
    }

    // --- row sums: each group holds partial sums over its key half ---
    float* sA = (float*)(smem + 0);      // P exchange region is dead now
    float* sB = (float*)(smem + 256);
    rsum0 += __shfl_xor_sync(0xffffffffu, rsum0, 1);
    rsum0 += __shfl_xor_sync(0xffffffffu, rsum0, 2);
    rsum1 += __shfl_xor_sync(0xffffffffu, rsum1, 1);
    rsum1 += __shfl_xor_sync(0xffffffffu, rsum1, 2);
    __syncthreads();                     // ensure exchange reads finished
    if ((lane & 3) == 0) {
        float* s = (khalf == 0) ? sA : sB;
        s[qw + (lane >> 2)]     = rsum0;
        s[qw + 8 + (lane >> 2)] = rsum1;
    }
    __syncthreads();
    const float inv0 = 1.f / (sA[qw + (lane >> 2)]     + sB[qw + (lane >> 2)]);
    const float inv1 = 1.f / (sA[qw + 8 + (lane >> 2)] + sB[qw + 8 + (lane >> 2)]);

    const int qg = q0 + qw + (lane >> 2);
    float* Ob = O + (size_t)b * C_ * N_;
#pragma unroll
    for (int cb = 0; cb < 16; cb++) {
        int c = cbase + cb * 8 + (lane & 3) * 2;
        Ob[(size_t)c * N_ + qg]           = oacc[cb][0] * inv0;
        Ob[(size_t)(c + 1) * N_ + qg]     = oacc[cb][1] * inv0;
        Ob[(size_t)c * N_ + qg + 8]       = oacc[cb][2] * inv1;
        Ob[(size_t)(c + 1) * N_ + qg + 8] = oacc[cb][3] * inv1;
    }
}

// ---------------- kernel_launch ----------------
extern "C" void kernel_launch(void* const* d_in, const int* in_sizes, int n_in,
                              void* d_out, int out_size)
{
    (void)in_sizes; (void)n_in; (void)out_size;
    const float* x  = (const float*)d_in[0];
    const float* Wq = (const float*)d_in[1];
    const float* bq = (const float*)d_in[2];
    const float* Wk = (const float*)d_in[3];
    const float* bk = (const float*)d_in[4];
    const float* Wv = (const float*)d_in[5];
    const float* bv = (const float*)d_in[6];
    const float* Wf = (const float*)d_in[7];
    const float* bf = (const float*)d_in[8];
    float* out = (float*)d_out;

    float* go;
    __nv_bfloat16 *qh, *ql, *kh, *kl, *vh;
    cudaGetSymbolAddress((void**)&go, g_o);
    cudaGetSymbolAddress((void**)&qh, g_qh);
    cudaGetSymbolAddress((void**)&ql, g_ql);
    cudaGetSymbolAddress((void**)&kh, g_kh);
    cudaGetSymbolAddress((void**)&kl, g_kl);
    cudaGetSymbolAddress((void**)&vh, g_vh);

    cudaFuncSetAttribute(flash_mma_kernel,
                         cudaFuncAttributeMaxDynamicSharedMemorySize, FL_SMEM);

    // projections with fused bf16 hi/lo emission
    proj_qk_kernel<<<dim3(N_ / 64, 1, B_), 256>>>(Wq, bq, x, qh, ql);
    proj_qk_kernel<<<dim3(N_ / 64, 1, B_), 256>>>(Wk, bk, x, kh, kl);
    proj_vh_kernel<<<dim3(N_ / 64, C_ / 64, B_), 256>>>(Wv, bv, x, vh);

    // attention on tensor cores
    flash_mma_kernel<<<dim3(N_ / 64, B_), 256, FL_SMEM>>>(qh, ql, kh, kl, vh, go);

    // final projection
    proj_f_kernel<<<dim3(N_ / 64, C_ / 64, B_), 256>>>(Wf, bf, go, out);
}

// round 9
// speedup vs baseline: 1.3697x; 1.3697x over previous
#include <cuda_runtime.h>
#include <cuda_bf16.h>
#include <cstdint>

static constexpr int B_   = 8;
static constexpr int C_   = 256;
static constexpr int CQK_ = 32;
static constexpr int N_   = 4096;

// Scratch
__device__ __align__(256) __nv_bfloat16 g_qh[(size_t)B_ * N_ * CQK_];
__device__ __align__(256) __nv_bfloat16 g_ql[(size_t)B_ * N_ * CQK_];
__device__ __align__(256) __nv_bfloat16 g_kh[(size_t)B_ * N_ * CQK_];
__device__ __align__(256) __nv_bfloat16 g_kl[(size_t)B_ * N_ * CQK_];
__device__ __align__(256) __nv_bfloat16 g_vh[(size_t)B_ * C_ * N_];
__device__ __align__(256) __nv_bfloat16 g_xth[(size_t)B_ * N_ * C_];  // x^T hi [b][n][c]
__device__ __align__(256) __nv_bfloat16 g_xtl[(size_t)B_ * N_ * C_];
__device__ __align__(256) __nv_bfloat16 g_oth[(size_t)B_ * N_ * C_];  // O^T hi [b][n][c]
__device__ __align__(256) __nv_bfloat16 g_otl[(size_t)B_ * N_ * C_];
__device__ __align__(256) __nv_bfloat16 g_wvh[C_ * C_], g_wvl[C_ * C_];
__device__ __align__(256) __nv_bfloat16 g_wfh[C_ * C_], g_wfl[C_ * C_];

// ---------------- packed f32x2 ----------------
using u64_t = unsigned long long;
__device__ __forceinline__ u64_t pack2(float lo, float hi) {
    u64_t r; asm("mov.b64 %0, {%1, %2};" : "=l"(r) : "f"(lo), "f"(hi)); return r;
}
__device__ __forceinline__ u64_t bcast2(float x) { return pack2(x, x); }
__device__ __forceinline__ u64_t fma2(u64_t a, u64_t b, u64_t c) {
    u64_t d; asm("fma.rn.f32x2 %0, %1, %2, %3;" : "=l"(d) : "l"(a), "l"(b), "l"(c)); return d;
}
__device__ __forceinline__ float2 unpack2(u64_t a) {
    float2 f; asm("mov.b64 {%0, %1}, %2;" : "=f"(f.x), "=f"(f.y) : "l"(a)); return f;
}

// ---------------- mma / ldmatrix / cp.async ----------------
__device__ __forceinline__ uint32_t smem_u32(const void* p) {
    uint32_t a;
    asm("{ .reg .u64 t; cvta.to.shared.u64 t, %1; cvt.u32.u64 %0, t; }" : "=r"(a) : "l"(p));
    return a;
}
__device__ __forceinline__ void cpa16(uint32_t dst, const void* src) {
    asm volatile("cp.async.cg.shared.global [%0], [%1], 16;" :: "r"(dst), "l"(src) : "memory");
}
#define CPA_COMMIT() asm volatile("cp.async.commit_group;" ::: "memory")
#define CPA_WAIT(n)  asm volatile("cp.async.wait_group %0;" :: "n"(n) : "memory")

__device__ __forceinline__ void ldsm4(uint32_t addr, uint32_t* r) {
    asm volatile("ldmatrix.sync.aligned.m8n8.x4.shared.b16 {%0,%1,%2,%3}, [%4];"
                 : "=r"(r[0]), "=r"(r[1]), "=r"(r[2]), "=r"(r[3]) : "r"(addr));
}
__device__ __forceinline__ void mma16816(float* d, const uint32_t* a, uint32_t b0, uint32_t b1) {
    asm volatile("mma.sync.aligned.m16n8k16.row.col.f32.bf16.bf16.f32 "
                 "{%0,%1,%2,%3}, {%4,%5,%6,%7}, {%8,%9}, {%0,%1,%2,%3};"
                 : "+f"(d[0]), "+f"(d[1]), "+f"(d[2]), "+f"(d[3])
                 : "r"(a[0]), "r"(a[1]), "r"(a[2]), "r"(a[3]), "r"(b0), "r"(b1));
}
__device__ __forceinline__ uint32_t pack_bf16x2(float e0, float e1) {
    uint32_t r; asm("cvt.rn.bf16x2.f32 %0, %1, %2;" : "=r"(r) : "f"(e1), "f"(e0)); return r;
}
__device__ __forceinline__ float lo_bf16_f(uint32_t u) { return __uint_as_float(u << 16); }
__device__ __forceinline__ float hi_bf16_f(uint32_t u) { return __uint_as_float(u & 0xffff0000u); }
__device__ __forceinline__ void bf16_split(float v, __nv_bfloat16& h, __nv_bfloat16& l) {
    h = __float2bfloat16(v);
    l = __float2bfloat16(v - __bfloat162float(h));
}

// ---------------- W split: fp32 [256][256] -> bf16 hi/lo ----------------
__global__ __launch_bounds__(256)
void wsplit_kernel(const float* __restrict__ W,
                   __nv_bfloat16* __restrict__ Wh, __nv_bfloat16* __restrict__ Wl)
{
    int i = blockIdx.x * 256 + threadIdx.x;
    float v = W[i];
    __nv_bfloat16 h, l; bf16_split(v, h, l);
    Wh[i] = h; Wl[i] = l;
}

// ---------------- x split-transpose: fp32 [b][C][N] -> bf16 hi/lo [b][N][C] ---
__global__ __launch_bounds__(256)
void xsplit_kernel(const float* __restrict__ X,
                   __nv_bfloat16* __restrict__ Yh, __nv_bfloat16* __restrict__ Yl)
{
    __shared__ float t[64][65];
    const int b  = blockIdx.z;
    const int c0 = blockIdx.y * 64;
    const int n0 = blockIdx.x * 64;
    const int tid = threadIdx.x;
    for (int i = tid; i < 4096; i += 256) {
        int c = i >> 6, n = i & 63;
        t[c][n] = X[(size_t)b * C_ * N_ + (size_t)(c0 + c) * N_ + n0 + n];
    }
    __syncthreads();
    for (int i = tid; i < 4096; i += 256) {
        int n = i >> 6, c = i & 63;
        float v = t[c][n];
        __nv_bfloat16 h, l; bf16_split(v, h, l);
        size_t o = ((size_t)b * N_ + n0 + n) * C_ + c0 + c;
        Yh[o] = h; Yl[o] = l;
    }
}

// ---------------- Q/K projection: fp32 compute -> bf16 hi/lo [B][N][32] -------
__global__ __launch_bounds__(256)
void proj_qk_kernel(const float* __restrict__ W, const float* __restrict__ bias,
                    const float* __restrict__ X,
                    __nv_bfloat16* __restrict__ Yh, __nv_bfloat16* __restrict__ Yl)
{
    constexpr int BM = 32, BK = 32, BN = 64, TM = 2;
    __shared__ float Ws[BK][BM + 4];
    __shared__ float Xs[BK][BN];

    const int b  = blockIdx.z;
    const int n0 = blockIdx.x * BN;
    const float* Xb = X + (size_t)b * C_ * N_;

    const int tid = threadIdx.x;
    const int tm  = (tid / 16) * TM;
    const int tn  = (tid % 16) * 4;

    u64_t acc2[TM][2];
#pragma unroll
    for (int i = 0; i < TM; i++) { acc2[i][0] = pack2(0.f,0.f); acc2[i][1] = pack2(0.f,0.f); }

    for (int k0 = 0; k0 < C_; k0 += BK) {
        for (int i = tid; i < BM * BK; i += 256) {
            int m = i / BK, k = i % BK;
            Ws[k][m] = W[(size_t)m * C_ + (k0 + k)];
        }
        for (int i = tid; i < BK * BN / 4; i += 256) {
            int k = i / (BN / 4), n4 = (i % (BN / 4)) * 4;
            *(float4*)&Xs[k][n4] = *(const float4*)&Xb[(size_t)(k0 + k) * N_ + (n0 + n4)];
        }
        __syncthreads();
#pragma unroll
        for (int k = 0; k < BK; k++) {
            float2 w2 = *(const float2*)&Ws[k][tm];
            float4 x4 = *(const float4*)&Xs[k][tn];
            u64_t xp0 = pack2(x4.x, x4.y), xp1 = pack2(x4.z, x4.w);
            u64_t wb0 = bcast2(w2.x), wb1 = bcast2(w2.y);
            acc2[0][0] = fma2(xp0, wb0, acc2[0][0]);
            acc2[0][1] = fma2(xp1, wb0, acc2[0][1]);
            acc2[1][0] = fma2(xp0, wb1, acc2[1][0]);
            acc2[1][1] = fma2(xp1, wb1, acc2[1][1]);
        }
        __syncthreads();
    }
#pragma unroll
    for (int i = 0; i < TM; i++) {
        int m = tm + i;
        float bb = bias[m];
        float2 a0 = unpack2(acc2[i][0]), a1 = unpack2(acc2[i][1]);
        float vals[4] = {a0.x + bb, a0.y + bb, a1.x + bb, a1.y + bb};
#pragma unroll
        for (int j = 0; j < 4; j++) {
            size_t o = ((size_t)b * N_ + n0 + tn + j) * CQK_ + m;
            __nv_bfloat16 h, l; bf16_split(vals[j], h, l);
            Yh[o] = h; Yl[o] = l;
        }
    }
}

// ---------------- tensor-core projection GEMM (3-term bf16 split) -------------
// out[m][n] = bias[m] + sum_k W[m][k] * X[k][n]
// W: bf16 hi/lo [256][256] row-major. X: bf16 hi/lo [b][n][k=256] (n-major).
// CTA: 128 m x 64 n, K streamed in 4 steps of 64, double-buffered.
// Warp w: m-rows w*16..w*16+15, all 64 n.
// OUT_FP32=0: bf16 out at [b][m][n] (V for flash); =1: fp32 out at [b][m][n].
static constexpr int PM_SW   = 0;        // W bufs: + bi*36864, lo at +18432; rows 144 B
static constexpr int PM_SX   = 73728;    // X bufs: + bi*18432, lo at +9216;  rows 144 B
static constexpr int PM_SMEM = 110592;

template <int OUT_FP32>
__global__ __launch_bounds__(256, 2)
void proj_mma_kernel(const __nv_bfloat16* __restrict__ Wh, const __nv_bfloat16* __restrict__ Wl,
                     const __nv_bfloat16* __restrict__ Xh, const __nv_bfloat16* __restrict__ Xl,
                     const float* __restrict__ bias, void* __restrict__ Yout)
{
    extern __shared__ char smem[];
    const uint32_t sb = smem_u32(smem);
    const int tid = threadIdx.x, lane = tid & 31, w = tid >> 5;
    const int b  = blockIdx.z;
    const int m0 = blockIdx.y * 128;
    const int n0 = blockIdx.x * 64;
    const int mw = w * 16;

    auto load_wx = [&](int ks, int bi) {
        const int k0 = ks * 64;
        for (int i = tid; i < 2048; i += 256) {
            int half = i >> 10, r = (i >> 3) & 127, ch = i & 7;
            const __nv_bfloat16* src = (half ? Wl : Wh) + (size_t)(m0 + r) * 256 + k0 + ch * 8;
            cpa16(sb + PM_SW + bi * 36864 + half * 18432 + r * 144 + ch * 16, src);
        }
        for (int i = tid; i < 1024; i += 256) {
            int half = i >> 9, r = (i >> 3) & 63, ch = i & 7;
            const __nv_bfloat16* src = (half ? Xl : Xh) + ((size_t)b * N_ + n0 + r) * 256 + k0 + ch * 8;
            cpa16(sb + PM_SX + bi * 18432 + half * 9216 + r * 144 + ch * 16, src);
        }
    };

    load_wx(0, 0); CPA_COMMIT();
    load_wx(1, 1); CPA_COMMIT();

    float oacc[8][4];
#pragma unroll
    for (int i = 0; i < 8; i++)
#pragma unroll
        for (int j = 0; j < 4; j++) oacc[i][j] = 0.f;

#pragma unroll
    for (int ks = 0; ks < 4; ks++) {
        const int bi = ks & 1;
        if (ks < 2) { CPA_WAIT(1); } else { CPA_WAIT(0); }
        __syncthreads();

        const uint32_t wb_hi = sb + PM_SW + bi * 36864;
        const uint32_t xb_hi = sb + PM_SX + bi * 18432;

        // A fragments (W rows mw..mw+15, this 64-k chunk)
        uint32_t ah[4][4], al[4][4];
#pragma unroll
        for (int kc = 0; kc < 4; kc++) {
            uint32_t addr = wb_hi + (uint32_t)(mw + (lane & 15)) * 144
                          + (uint32_t)(kc * 16 + (lane >> 4) * 8) * 2;
            ldsm4(addr, ah[kc]);
            ldsm4(addr + 18432, al[kc]);
        }

#pragma unroll
        for (int nb = 0; nb < 8; nb++) {
            uint32_t rowoff = xb_hi + (uint32_t)(nb * 8 + (lane & 7)) * 144;
            uint32_t bh[8], bl[8];
#pragma unroll
            for (int kk = 0; kk < 2; kk++) {
                uint32_t off = (uint32_t)(kk * 32 + (lane >> 3) * 8) * 2;
                ldsm4(rowoff + off, &bh[4 * kk]);
                ldsm4(rowoff + off + 9216, &bl[4 * kk]);
            }
#pragma unroll
            for (int kc = 0; kc < 4; kc++) {
                int ix = (kc >> 1) * 4 + (kc & 1) * 2;
                mma16816(oacc[nb], ah[kc], bh[ix], bh[ix + 1]);   // Wh*Xh
                mma16816(oacc[nb], al[kc], bh[ix], bh[ix + 1]);   // Wl*Xh
                mma16816(oacc[nb], ah[kc], bl[ix], bl[ix + 1]);   // Wh*Xl
            }
        }

        __syncthreads();
        if (ks + 2 < 4) { load_wx(ks + 2, bi); CPA_COMMIT(); }
    }

    // epilogue
    const int r0 = m0 + mw + (lane >> 2);
    const float b0f = bias[r0], b1f = bias[r0 + 8];
#pragma unroll
    for (int nb = 0; nb < 8; nb++) {
        int col = n0 + nb * 8 + (lane & 3) * 2;
        float v0 = oacc[nb][0] + b0f, v1 = oacc[nb][1] + b0f;
        float v2 = oacc[nb][2] + b1f, v3 = oacc[nb][3] + b1f;
        if (OUT_FP32) {
            float* Yf = (float*)Yout + (size_t)b * C_ * N_;
            *(float2*)&Yf[(size_t)r0 * N_ + col]       = make_float2(v0, v1);
            *(float2*)&Yf[(size_t)(r0 + 8) * N_ + col] = make_float2(v2, v3);
        } else {
            __nv_bfloat16* Yb = (__nv_bfloat16*)Yout + (size_t)b * C_ * N_;
            *(uint32_t*)&Yb[(size_t)r0 * N_ + col]       = pack_bf16x2(v0, v1);
            *(uint32_t*)&Yb[(size_t)(r0 + 8) * N_ + col] = pack_bf16x2(v2, v3);
        }
    }
}

// ---------------- flash attention on mma.sync (R6 structure) -----------------
// 8 warps: warps 0-3 = producers (S/exp/P for rows (w&3)*16, share P via smem
// lane-mirror); warps 4-7 = consumers (same rows, other channel half).
// PV 2-term (PhVh + PlVh). QK 3-term, computed once.
// Epilogue writes O as bf16 hi/lo in [b][n][c] (feeds proj_mma directly).
static constexpr int SP_HI = 0;
static constexpr int SP_LO = 8192;
static constexpr int S_INV = 16384;
static constexpr int SQH   = 0;
static constexpr int SQL   = 5120;
static constexpr int SKB   = 16640;
static constexpr int SVB   = 37120;
static constexpr int FL_SMEM = 110848;

__global__ __launch_bounds__(256, 2)
void flash_mma_kernel(const __nv_bfloat16* __restrict__ Qh, const __nv_bfloat16* __restrict__ Ql,
                      const __nv_bfloat16* __restrict__ Kh, const __nv_bfloat16* __restrict__ Kl,
                      const __nv_bfloat16* __restrict__ Vh,
                      __nv_bfloat16* __restrict__ Oh, __nv_bfloat16* __restrict__ Ol)
{
    extern __shared__ char smem[];
    const uint32_t sb = smem_u32(smem);
    const int tid = threadIdx.x, lane = tid & 31, w = tid >> 5;
    const int qw = (w & 3) * 16;
    const int cbase = (w >> 2) * 128;
    const bool producer = (w < 4);
    const int b = blockIdx.y, q0 = blockIdx.x * 64;

    auto load_kv = [&](int kt, int bi) {
        const int j0 = kt * 64;
        for (int i = tid; i < 512; i += 256) {
            int half = i >> 8, r = (i >> 2) & 63, ch = i & 3;
            const __nv_bfloat16* src = (half ? Kl : Kh) + ((size_t)b * N_ + j0 + r) * CQK_ + ch * 8;
            cpa16(sb + SKB + bi * 10240 + half * 5120 + r * 80 + ch * 16, src);
        }
        for (int i = tid; i < 2048; i += 256) {
            int r = i >> 3, ch = i & 7;
            const __nv_bfloat16* src = Vh + ((size_t)b * C_ + r) * N_ + j0 + ch * 8;
            cpa16(sb + SVB + bi * 36864 + r * 144 + ch * 16, src);
        }
    };

    // prologue: Q + tiles 0,1
    for (int i = tid; i < 512; i += 256) {
        int half = i >> 8, r = (i >> 2) & 63, ch = i & 3;
        const __nv_bfloat16* src = (half ? Ql : Qh) + ((size_t)b * N_ + q0 + r) * CQK_ + ch * 8;
        cpa16(sb + (half ? SQL : SQH) + r * 80 + ch * 16, src);
    }
    load_kv(0, 0); CPA_COMMIT();
    load_kv(1, 1); CPA_COMMIT();
    CPA_WAIT(1);
    __syncthreads();

    // Q A-fragments (producers only)
    uint32_t qa[2][2][4];
    if (producer) {
#pragma unroll
        for (int hl = 0; hl < 2; hl++)
#pragma unroll
            for (int kc = 0; kc < 2; kc++) {
                uint32_t addr = sb + (hl ? SQL : SQH)
                              + (uint32_t)(qw + (lane & 15)) * 80
                              + (uint32_t)(kc * 16 + (lane >> 4) * 8) * 2;
                ldsm4(addr, qa[hl][kc]);
            }
    }
    __syncthreads();   // Q region is dead; P exchange may now overwrite it

    float oacc[16][4];
#pragma unroll
    for (int i = 0; i < 16; i++)
#pragma unroll
        for (int j = 0; j < 4; j++) oacc[i][j] = 0.f;
    float rsum0 = 0.f, rsum1 = 0.f;

    for (int kt = 0; kt < 64; kt++) {
        const int bi = kt & 1;
        const uint32_t vh_b = sb + SVB + bi * 36864;

        uint32_t pah[4][4], pal[4][4];

        if (producer) {
            const uint32_t kh_b = sb + SKB + bi * 10240, kl_b = kh_b + 5120;
            // --- S = QK^T (3-term bf16 split) ---
            float sacc[8][4];
#pragma unroll
            for (int i = 0; i < 8; i++)
#pragma unroll
                for (int j = 0; j < 4; j++) sacc[i][j] = 0.f;
#pragma unroll
            for (int kc = 0; kc < 2; kc++)
#pragma unroll
                for (int nbp = 0; nbp < 4; nbp++) {
                    uint32_t off = (uint32_t)((nbp * 2 + ((lane >> 4) & 1)) * 8 + (lane & 7)) * 80
                                 + (uint32_t)(kc * 16 + ((lane >> 3) & 1) * 8) * 2;
                    uint32_t bh[4], bl[4];
                    ldsm4(kh_b + off, bh);
                    ldsm4(kl_b + off, bl);
                    mma16816(sacc[2*nbp],   qa[0][kc], bh[0], bh[1]);
                    mma16816(sacc[2*nbp+1], qa[0][kc], bh[2], bh[3]);
                    mma16816(sacc[2*nbp],   qa[1][kc], bh[0], bh[1]);
                    mma16816(sacc[2*nbp+1], qa[1][kc], bh[2], bh[3]);
                    mma16816(sacc[2*nbp],   qa[0][kc], bl[0], bl[1]);
                    mma16816(sacc[2*nbp+1], qa[0][kc], bl[2], bl[3]);
                }
            // --- P = exp(S); pack bf16 hi/lo ---
#pragma unroll
            for (int nb = 0; nb < 8; nb++) {
                float e0 = __expf(sacc[nb][0]);
                float e1 = __expf(sacc[nb][1]);
                float e2 = __expf(sacc[nb][2]);
                float e3 = __expf(sacc[nb][3]);
                rsum0 += e0 + e1;
                rsum1 += e2 + e3;
                int kj = nb >> 1, o = (nb & 1) * 2;
                uint32_t h01 = pack_bf16x2(e0, e1);
                uint32_t h23 = pack_bf16x2(e2, e3);
                pah[kj][o]     = h01;
                pah[kj][o + 1] = h23;
                pal[kj][o]     = pack_bf16x2(e0 - lo_bf16_f(h01), e1 - hi_bf16_f(h01));
                pal[kj][o + 1] = pack_bf16x2(e2 - lo_bf16_f(h23), e3 - hi_bf16_f(h23));
            }
            // --- mirror P fragments to smem for partner warp (lane-for-lane) ---
            char* ph_dst = smem + SP_HI + (w & 3) * 2048 + lane * 16;
            char* pl_dst = smem + SP_LO + (w & 3) * 2048 + lane * 16;
#pragma unroll
            for (int kj = 0; kj < 4; kj++) {
                *(uint4*)(ph_dst + kj * 512) = make_uint4(pah[kj][0], pah[kj][1], pah[kj][2], pah[kj][3]);
                *(uint4*)(pl_dst + kj * 512) = make_uint4(pal[kj][0], pal[kj][1], pal[kj][2], pal[kj][3]);
            }
        }
        __syncthreads();   // P visible to consumers

        if (!producer) {
            const char* ph_src = smem + SP_HI + (w & 3) * 2048 + lane * 16;
            const char* pl_src = smem + SP_LO + (w & 3) * 2048 + lane * 16;
#pragma unroll
            for (int kj = 0; kj < 4; kj++) {
                uint4 h4 = *(const uint4*)(ph_src + kj * 512);
                uint4 l4 = *(const uint4*)(pl_src + kj * 512);
                pah[kj][0] = h4.x; pah[kj][1] = h4.y; pah[kj][2] = h4.z; pah[kj][3] = h4.w;
                pal[kj][0] = l4.x; pal[kj][1] = l4.y; pal[kj][2] = l4.z; pal[kj][3] = l4.w;
            }
        }

        // --- O += P V^T (2-term: PhVh + PlVh) over this warp's 128 channels ---
#pragma unroll
        for (int cb = 0; cb < 16; cb++) {
            uint32_t rowoff = (uint32_t)(cbase + cb * 8 + (lane & 7)) * 144;
            uint32_t vfh[8];
#pragma unroll
            for (int kjp = 0; kjp < 2; kjp++) {
                uint32_t off = rowoff + (uint32_t)(kjp * 32 + (lane >> 3) * 8) * 2;
                ldsm4(vh_b + off, &vfh[4 * kjp]);
            }
#pragma unroll
            for (int kj = 0; kj < 4; kj++) {
                int ix = (kj >> 1) * 4 + (kj & 1) * 2;
                mma16816(oacc[cb], pah[kj], vfh[ix], vfh[ix + 1]);
                mma16816(oacc[cb], pal[kj], vfh[ix], vfh[ix + 1]);
            }
        }

        // --- pipeline (merged barriers): wait kt+1, one sync, refill bi ---
        CPA_WAIT(0);                     // tile kt+1 landed (issued one tile ago)
        __syncthreads();                 // visible to all; buffer bi reads done
        if (kt + 2 < 64) load_kv(kt + 2, bi);
        CPA_COMMIT();
    }

    // row sums -> smem (producers own them)
    float* sinv = (float*)(smem + S_INV);
    if (producer) {
        rsum0 += __shfl_xor_sync(0xffffffffu, rsum0, 1);
        rsum0 += __shfl_xor_sync(0xffffffffu, rsum0, 2);
        rsum1 += __shfl_xor_sync(0xffffffffu, rsum1, 1);
        rsum1 += __shfl_xor_sync(0xffffffffu, rsum1, 2);
        if ((lane & 3) == 0) {
            sinv[qw + (lane >> 2)]     = rsum0;
            sinv[qw + 8 + (lane >> 2)] = rsum1;
        }
    }
    __syncthreads();
    const float inv0 = 1.f / sinv[qw + (lane >> 2)];
    const float inv1 = 1.f / sinv[qw + 8 + (lane >> 2)];

    // epilogue: write O bf16 hi/lo at [b][n][c]
    const int qg = q0 + qw + (lane >> 2);
    const size_t rbase0 = ((size_t)b * N_ + qg) * C_;
    const size_t rbase1 = ((size_t)b * N_ + qg + 8) * C_;
#pragma unroll
    for (int cb = 0; cb < 16; cb++) {
        int c = cbase + cb * 8 + (lane & 3) * 2;
        float v0 = oacc[cb][0] * inv0, v1 = oacc[cb][1] * inv0;
        float v2 = oacc[cb][2] * inv1, v3 = oacc[cb][3] * inv1;
        uint32_t h01 = pack_bf16x2(v0, v1);
        uint32_t l01 = pack_bf16x2(v0 - lo_bf16_f(h01), v1 - hi_bf16_f(h01));
        uint32_t h23 = pack_bf16x2(v2, v3);
        uint32_t l23 = pack_bf16x2(v2 - lo_bf16_f(h23), v3 - hi_bf16_f(h23));
        *(uint32_t*)&Oh[rbase0 + c] = h01;
        *(uint32_t*)&Ol[rbase0 + c] = l01;
        *(uint32_t*)&Oh[rbase1 + c] = h23;
        *(uint32_t*)&Ol[rbase1 + c] = l23;
    }
}

// ---------------- kernel_launch ----------------
extern "C" void kernel_launch(void* const* d_in, const int* in_sizes, int n_in,
                              void* d_out, int out_size)
{
    (void)in_sizes; (void)n_in; (void)out_size;
    const float* x  = (const float*)d_in[0];
    const float* Wq = (const float*)d_in[1];
    const float* bq = (const float*)d_in[2];
    const float* Wk = (const float*)d_in[3];
    const float* bk = (const float*)d_in[4];
    const float* Wv = (const float*)d_in[5];
    const float* bv = (const float*)d_in[6];
    const float* Wf = (const float*)d_in[7];
    const float* bf = (const float*)d_in[8];
    float* out = (float*)d_out;

    __nv_bfloat16 *qh, *ql, *kh, *kl, *vh, *xth, *xtl, *oth, *otl;
    __nv_bfloat16 *wvh, *wvl, *wfh, *wfl;
    cudaGetSymbolAddress((void**)&qh,  g_qh);
    cudaGetSymbolAddress((void**)&ql,  g_ql);
    cudaGetSymbolAddress((void**)&kh,  g_kh);
    cudaGetSymbolAddress((void**)&kl,  g_kl);
    cudaGetSymbolAddress((void**)&vh,  g_vh);
    cudaGetSymbolAddress((void**)&xth, g_xth);
    cudaGetSymbolAddress((void**)&xtl, g_xtl);
    cudaGetSymbolAddress((void**)&oth, g_oth);
    cudaGetSymbolAddress((void**)&otl, g_otl);
    cudaGetSymbolAddress((void**)&wvh, g_wvh);
    cudaGetSymbolAddress((void**)&wvl, g_wvl);
    cudaGetSymbolAddress((void**)&wfh, g_wfh);
    cudaGetSymbolAddress((void**)&wfl, g_wfl);

    cudaFuncSetAttribute(flash_mma_kernel,
                         cudaFuncAttributeMaxDynamicSharedMemorySize, FL_SMEM);
    cudaFuncSetAttribute(proj_mma_kernel<0>,
                         cudaFuncAttributeMaxDynamicSharedMemorySize, PM_SMEM);
    cudaFuncSetAttribute(proj_mma_kernel<1>,
                         cudaFuncAttributeMaxDynamicSharedMemorySize, PM_SMEM);

    // operand prep
    wsplit_kernel<<<C_ * C_ / 256, 256>>>(Wv, wvh, wvl);
    wsplit_kernel<<<C_ * C_ / 256, 256>>>(Wf, wfh, wfl);
    xsplit_kernel<<<dim3(N_ / 64, C_ / 64, B_), 256>>>(x, xth, xtl);

    // Q/K projections (fp32, fused bf16 hi/lo emission)
    proj_qk_kernel<<<dim3(N_ / 64, 1, B_), 256>>>(Wq, bq, x, qh, ql);
    proj_qk_kernel<<<dim3(N_ / 64, 1, B_), 256>>>(Wk, bk, x, kh, kl);

    // V projection on tensor cores -> bf16 [b][C][N]
    proj_mma_kernel<0><<<dim3(N_ / 64, 2, B_), 256, PM_SMEM>>>(wvh, wvl, xth, xtl, bv, vh);

    // attention on tensor cores -> O bf16 hi/lo [b][N][C]
    flash_mma_kernel<<<dim3(N_ / 64, B_), 256, FL_SMEM>>>(qh, ql, kh, kl, vh, oth, otl);

    // final projection on tensor cores -> fp32 out
    proj_mma_kernel<1><<<dim3(N_ / 64, 2, B_), 256, PM_SMEM>>>(wfh, wfl, oth, otl, bf, out);
}

// round 10
// speedup vs baseline: 1.5113x; 1.1034x over previous
#include <cuda_runtime.h>
#include <cuda_bf16.h>
#include <cstdint>

static constexpr int B_   = 8;
static constexpr int C_   = 256;
static constexpr int CQK_ = 32;
static constexpr int N_   = 4096;

// Scratch
__device__ __align__(256) __nv_bfloat16 g_qh[(size_t)B_ * N_ * CQK_];
__device__ __align__(256) __nv_bfloat16 g_ql[(size_t)B_ * N_ * CQK_];
__device__ __align__(256) __nv_bfloat16 g_kh[(size_t)B_ * N_ * CQK_];
__device__ __align__(256) __nv_bfloat16 g_kl[(size_t)B_ * N_ * CQK_];
__device__ __align__(256) __nv_bfloat16 g_vh[(size_t)B_ * C_ * N_];
__device__ __align__(256) __nv_bfloat16 g_xth[(size_t)B_ * N_ * C_];  // x^T hi [b][n][c]
__device__ __align__(256) __nv_bfloat16 g_xtl[(size_t)B_ * N_ * C_];
__device__ __align__(256) __nv_bfloat16 g_oth[(size_t)B_ * N_ * C_];  // O^T hi [b][n][c]
__device__ __align__(256) __nv_bfloat16 g_otl[(size_t)B_ * N_ * C_];
__device__ __align__(256) __nv_bfloat16 g_wvh[C_ * C_], g_wvl[C_ * C_];
__device__ __align__(256) __nv_bfloat16 g_wfh[C_ * C_], g_wfl[C_ * C_];
__device__ __align__(256) __nv_bfloat16 g_wqkh[64 * C_], g_wqkl[64 * C_];  // Wq||Wk stacked

// ---------------- mma / ldmatrix / cp.async ----------------
__device__ __forceinline__ uint32_t smem_u32(const void* p) {
    uint32_t a;
    asm("{ .reg .u64 t; cvta.to.shared.u64 t, %1; cvt.u32.u64 %0, t; }" : "=r"(a) : "l"(p));
    return a;
}
__device__ __forceinline__ void cpa16(uint32_t dst, const void* src) {
    asm volatile("cp.async.cg.shared.global [%0], [%1], 16;" :: "r"(dst), "l"(src) : "memory");
}
#define CPA_COMMIT() asm volatile("cp.async.commit_group;" ::: "memory")
#define CPA_WAIT(n)  asm volatile("cp.async.wait_group %0;" :: "n"(n) : "memory")

__device__ __forceinline__ void ldsm4(uint32_t addr, uint32_t* r) {
    asm volatile("ldmatrix.sync.aligned.m8n8.x4.shared.b16 {%0,%1,%2,%3}, [%4];"
                 : "=r"(r[0]), "=r"(r[1]), "=r"(r[2]), "=r"(r[3]) : "r"(addr));
}
__device__ __forceinline__ void mma16816(float* d, const uint32_t* a, uint32_t b0, uint32_t b1) {
    asm volatile("mma.sync.aligned.m16n8k16.row.col.f32.bf16.bf16.f32 "
                 "{%0,%1,%2,%3}, {%4,%5,%6,%7}, {%8,%9}, {%0,%1,%2,%3};"
                 : "+f"(d[0]), "+f"(d[1]), "+f"(d[2]), "+f"(d[3])
                 : "r"(a[0]), "r"(a[1]), "r"(a[2]), "r"(a[3]), "r"(b0), "r"(b1));
}
__device__ __forceinline__ uint32_t pack_bf16x2(float e0, float e1) {
    uint32_t r; asm("cvt.rn.bf16x2.f32 %0, %1, %2;" : "=r"(r) : "f"(e1), "f"(e0)); return r;
}
__device__ __forceinline__ float lo_bf16_f(uint32_t u) { return __uint_as_float(u << 16); }
__device__ __forceinline__ float hi_bf16_f(uint32_t u) { return __uint_as_float(u & 0xffff0000u); }
__device__ __forceinline__ void bf16_split(float v, __nv_bfloat16& h, __nv_bfloat16& l) {
    h = __float2bfloat16(v);
    l = __float2bfloat16(v - __bfloat162float(h));
}

// ---------------- W split: fp32 [256][256] -> bf16 hi/lo ----------------
__global__ __launch_bounds__(256)
void wsplit_kernel(const float* __restrict__ W,
                   __nv_bfloat16* __restrict__ Wh, __nv_bfloat16* __restrict__ Wl)
{
    int i = blockIdx.x * 256 + threadIdx.x;
    float v = W[i];
    __nv_bfloat16 h, l; bf16_split(v, h, l);
    Wh[i] = h; Wl[i] = l;
}

// ---------------- Wq||Wk stack + split: -> bf16 hi/lo [64][256] ----------------
__global__ __launch_bounds__(256)
void wqksplit_kernel(const float* __restrict__ Wq, const float* __restrict__ Wk,
                     __nv_bfloat16* __restrict__ Wh, __nv_bfloat16* __restrict__ Wl)
{
    int i = blockIdx.x * 256 + threadIdx.x;   // 64*256 = 16384
    int row = i >> 8, col = i & 255;
    float v = (row < 32) ? Wq[(size_t)row * 256 + col] : Wk[(size_t)(row - 32) * 256 + col];
    __nv_bfloat16 h, l; bf16_split(v, h, l);
    Wh[i] = h; Wl[i] = l;
}

// ---------------- x split-transpose: fp32 [b][C][N] -> bf16 hi/lo [b][N][C] ---
__global__ __launch_bounds__(256)
void xsplit_kernel(const float* __restrict__ X,
                   __nv_bfloat16* __restrict__ Yh, __nv_bfloat16* __restrict__ Yl)
{
    __shared__ float t[64][65];
    const int b  = blockIdx.z;
    const int c0 = blockIdx.y * 64;
    const int n0 = blockIdx.x * 64;
    const int tid = threadIdx.x;
    for (int i = tid; i < 4096; i += 256) {
        int c = i >> 6, n = i & 63;
        t[c][n] = X[(size_t)b * C_ * N_ + (size_t)(c0 + c) * N_ + n0 + n];
    }
    __syncthreads();
    for (int i = tid; i < 4096; i += 256) {
        int n = i >> 6, c = i & 63;
        float v = t[c][n];
        __nv_bfloat16 h, l; bf16_split(v, h, l);
        size_t o = ((size_t)b * N_ + n0 + n) * C_ + c0 + c;
        Yh[o] = h; Yl[o] = l;
    }
}

// ---------------- tensor-core projection GEMM (3-term bf16 split) -------------
// out[m][n] = bias[m] + sum_k W[m][k] * X[k][n]
// W: bf16 hi/lo [256][256] row-major. X: bf16 hi/lo [b][n][k=256] (n-major).
// CTA: 128 m x 64 n, K streamed in 4 steps of 64, double-buffered.
// OUT_FP32=0: bf16 out at [b][m][n] (V for flash); =1: fp32 out at [b][m][n].
static constexpr int PM_SW   = 0;        // A bufs: + bi*36864, lo at +18432; rows 144 B
static constexpr int PM_SX   = 73728;    // B bufs: + bi*18432, lo at +9216;  rows 144 B
static constexpr int PM_SMEM = 110592;

template <int OUT_FP32>
__global__ __launch_bounds__(256, 2)
void proj_mma_kernel(const __nv_bfloat16* __restrict__ Wh, const __nv_bfloat16* __restrict__ Wl,
                     const __nv_bfloat16* __restrict__ Xh, const __nv_bfloat16* __restrict__ Xl,
                     const float* __restrict__ bias, void* __restrict__ Yout)
{
    extern __shared__ char smem[];
    const uint32_t sb = smem_u32(smem);
    const int tid = threadIdx.x, lane = tid & 31, w = tid >> 5;
    const int b  = blockIdx.z;
    const int m0 = blockIdx.y * 128;
    const int n0 = blockIdx.x * 64;
    const int mw = w * 16;

    auto load_wx = [&](int ks, int bi) {
        const int k0 = ks * 64;
        for (int i = tid; i < 2048; i += 256) {
            int half = i >> 10, r = (i >> 3) & 127, ch = i & 7;
            const __nv_bfloat16* src = (half ? Wl : Wh) + (size_t)(m0 + r) * 256 + k0 + ch * 8;
            cpa16(sb + PM_SW + bi * 36864 + half * 18432 + r * 144 + ch * 16, src);
        }
        for (int i = tid; i < 1024; i += 256) {
            int half = i >> 9, r = (i >> 3) & 63, ch = i & 7;
            const __nv_bfloat16* src = (half ? Xl : Xh) + ((size_t)b * N_ + n0 + r) * 256 + k0 + ch * 8;
            cpa16(sb + PM_SX + bi * 18432 + half * 9216 + r * 144 + ch * 16, src);
        }
    };

    load_wx(0, 0); CPA_COMMIT();
    load_wx(1, 1); CPA_COMMIT();

    float oacc[8][4];
#pragma unroll
    for (int i = 0; i < 8; i++)
#pragma unroll
        for (int j = 0; j < 4; j++) oacc[i][j] = 0.f;

#pragma unroll
    for (int ks = 0; ks < 4; ks++) {
        const int bi = ks & 1;
        if (ks < 2) { CPA_WAIT(1); } else { CPA_WAIT(0); }
        __syncthreads();

        const uint32_t wb_hi = sb + PM_SW + bi * 36864;
        const uint32_t xb_hi = sb + PM_SX + bi * 18432;

        uint32_t ah[4][4], al[4][4];
#pragma unroll
        for (int kc = 0; kc < 4; kc++) {
            uint32_t addr = wb_hi + (uint32_t)(mw + (lane & 15)) * 144
                          + (uint32_t)(kc * 16 + (lane >> 4) * 8) * 2;
            ldsm4(addr, ah[kc]);
            ldsm4(addr + 18432, al[kc]);
        }

#pragma unroll
        for (int nb = 0; nb < 8; nb++) {
            uint32_t rowoff = xb_hi + (uint32_t)(nb * 8 + (lane & 7)) * 144;
            uint32_t bh[8], bl[8];
#pragma unroll
            for (int kk = 0; kk < 2; kk++) {
                uint32_t off = (uint32_t)(kk * 32 + (lane >> 3) * 8) * 2;
                ldsm4(rowoff + off, &bh[4 * kk]);
                ldsm4(rowoff + off + 9216, &bl[4 * kk]);
            }
#pragma unroll
            for (int kc = 0; kc < 4; kc++) {
                int ix = (kc >> 1) * 4 + (kc & 1) * 2;
                mma16816(oacc[nb], ah[kc], bh[ix], bh[ix + 1]);
                mma16816(oacc[nb], al[kc], bh[ix], bh[ix + 1]);
                mma16816(oacc[nb], ah[kc], bl[ix], bl[ix + 1]);
            }
        }

        __syncthreads();
        if (ks + 2 < 4) { load_wx(ks + 2, bi); CPA_COMMIT(); }
    }

    const int r0 = m0 + mw + (lane >> 2);
    const float b0f = bias[r0], b1f = bias[r0 + 8];
#pragma unroll
    for (int nb = 0; nb < 8; nb++) {
        int col = n0 + nb * 8 + (lane & 3) * 2;
        float v0 = oacc[nb][0] + b0f, v1 = oacc[nb][1] + b0f;
        float v2 = oacc[nb][2] + b1f, v3 = oacc[nb][3] + b1f;
        if (OUT_FP32) {
            float* Yf = (float*)Yout + (size_t)b * C_ * N_;
            *(float2*)&Yf[(size_t)r0 * N_ + col]       = make_float2(v0, v1);
            *(float2*)&Yf[(size_t)(r0 + 8) * N_ + col] = make_float2(v2, v3);
        } else {
            __nv_bfloat16* Yb = (__nv_bfloat16*)Yout + (size_t)b * C_ * N_;
            *(uint32_t*)&Yb[(size_t)r0 * N_ + col]       = pack_bf16x2(v0, v1);
            *(uint32_t*)&Yb[(size_t)(r0 + 8) * N_ + col] = pack_bf16x2(v2, v3);
        }
    }
}

// ---------------- Q/K projection on tensor cores ------------------------------
// Y[token][ch] = sum_k X[token][k] * Wqk[ch][k] + bias[ch]
// A = x tokens (128 rows, from xth/xtl), B = Wq||Wk stacked (64 rows).
// Fragment output is token-major -> Q/K land directly at [b][n][32] hi/lo.
__global__ __launch_bounds__(256, 2)
void proj_qk_mma_kernel(const __nv_bfloat16* __restrict__ Xh, const __nv_bfloat16* __restrict__ Xl,
                        const __nv_bfloat16* __restrict__ Wh, const __nv_bfloat16* __restrict__ Wl,
                        const float* __restrict__ bq, const float* __restrict__ bk,
                        __nv_bfloat16* __restrict__ Qh, __nv_bfloat16* __restrict__ Ql,
                        __nv_bfloat16* __restrict__ Kh, __nv_bfloat16* __restrict__ Kl)
{
    extern __shared__ char smem[];
    const uint32_t sb = smem_u32(smem);
    const int tid = threadIdx.x, lane = tid & 31, w = tid >> 5;
    const int b  = blockIdx.z;
    const int m0 = blockIdx.y * 128;   // token tile
    const int mw = w * 16;

    auto load_ab = [&](int ks, int bi) {
        const int k0 = ks * 64;
        for (int i = tid; i < 2048; i += 256) {   // A = X tokens, 128 rows hi+lo
            int half = i >> 10, r = (i >> 3) & 127, ch = i & 7;
            const __nv_bfloat16* src = (half ? Xl : Xh) + ((size_t)b * N_ + m0 + r) * 256 + k0 + ch * 8;
            cpa16(sb + PM_SW + bi * 36864 + half * 18432 + r * 144 + ch * 16, src);
        }
        for (int i = tid; i < 1024; i += 256) {   // B = Wqk, 64 rows hi+lo
            int half = i >> 9, r = (i >> 3) & 63, ch = i & 7;
            const __nv_bfloat16* src = (half ? Wl : Wh) + (size_t)r * 256 + k0 + ch * 8;
            cpa16(sb + PM_SX + bi * 18432 + half * 9216 + r * 144 + ch * 16, src);
        }
    };

    load_ab(0, 0); CPA_COMMIT();
    load_ab(1, 1); CPA_COMMIT();

    float oacc[8][4];
#pragma unroll
    for (int i = 0; i < 8; i++)
#pragma unroll
        for (int j = 0; j < 4; j++) oacc[i][j] = 0.f;

#pragma unroll
    for (int ks = 0; ks < 4; ks++) {
        const int bi = ks & 1;
        if (ks < 2) { CPA_WAIT(1); } else { CPA_WAIT(0); }
        __syncthreads();

        const uint32_t ab_hi = sb + PM_SW + bi * 36864;
        const uint32_t bb_hi = sb + PM_SX + bi * 18432;

        uint32_t ah[4][4], al[4][4];
#pragma unroll
        for (int kc = 0; kc < 4; kc++) {
            uint32_t addr = ab_hi + (uint32_t)(mw + (lane & 15)) * 144
                          + (uint32_t)(kc * 16 + (lane >> 4) * 8) * 2;
            ldsm4(addr, ah[kc]);
            ldsm4(addr + 18432, al[kc]);
        }

#pragma unroll
        for (int nb = 0; nb < 8; nb++) {
            uint32_t rowoff = bb_hi + (uint32_t)(nb * 8 + (lane & 7)) * 144;
            uint32_t bh[8], bl[8];
#pragma unroll
            for (int kk = 0; kk < 2; kk++) {
                uint32_t off = (uint32_t)(kk * 32 + (lane >> 3) * 8) * 2;
                ldsm4(rowoff + off, &bh[4 * kk]);
                ldsm4(rowoff + off + 9216, &bl[4 * kk]);
            }
#pragma unroll
            for (int kc = 0; kc < 4; kc++) {
                int ix = (kc >> 1) * 4 + (kc & 1) * 2;
                mma16816(oacc[nb], ah[kc], bh[ix], bh[ix + 1]);   // Xh*Wh
                mma16816(oacc[nb], al[kc], bh[ix], bh[ix + 1]);   // Xl*Wh
                mma16816(oacc[nb], ah[kc], bl[ix], bl[ix + 1]);   // Xh*Wl
            }
        }

        __syncthreads();
        if (ks + 2 < 4) { load_ab(ks + 2, bi); CPA_COMMIT(); }
    }

    // epilogue: rows = tokens r0, r0+8; cols = stacked channel 0..63
    const int r0 = m0 + mw + (lane >> 2);
#pragma unroll
    for (int nb = 0; nb < 8; nb++) {
        int c = nb * 8 + (lane & 3) * 2;
        const bool isQ = (c < 32);
        const int cc = isQ ? c : c - 32;
        const float bb0 = isQ ? bq[cc] : bk[cc];
        const float bb1 = isQ ? bq[cc + 1] : bk[cc + 1];
        float v0 = oacc[nb][0] + bb0, v1 = oacc[nb][1] + bb1;   // token r0
        float v2 = oacc[nb][2] + bb0, v3 = oacc[nb][3] + bb1;   // token r0+8
        uint32_t h01 = pack_bf16x2(v0, v1);
        uint32_t l01 = pack_bf16x2(v0 - lo_bf16_f(h01), v1 - hi_bf16_f(h01));
        uint32_t h23 = pack_bf16x2(v2, v3);
        uint32_t l23 = pack_bf16x2(v2 - lo_bf16_f(h23), v3 - hi_bf16_f(h23));
        __nv_bfloat16* dh = isQ ? Qh : Kh;
        __nv_bfloat16* dl = isQ ? Ql : Kl;
        size_t o0 = ((size_t)b * N_ + r0) * CQK_ + cc;
        size_t o1 = ((size_t)b * N_ + r0 + 8) * CQK_ + cc;
        *(uint32_t*)&dh[o0] = h01;
        *(uint32_t*)&dl[o0] = l01;
        *(uint32_t*)&dh[o1] = h23;
        *(uint32_t*)&dl[o1] = l23;
    }
}

// ---------------- flash attention on mma.sync (R6 structure + merged barriers)
static constexpr int SP_HI = 0;
static constexpr int SP_LO = 8192;
static constexpr int S_INV = 16384;
static constexpr int SQH   = 0;
static constexpr int SQL   = 5120;
static constexpr int SKB   = 16640;
static constexpr int SVB   = 37120;
static constexpr int FL_SMEM = 110848;

__global__ __launch_bounds__(256, 2)
void flash_mma_kernel(const __nv_bfloat16* __restrict__ Qh, const __nv_bfloat16* __restrict__ Ql,
                      const __nv_bfloat16* __restrict__ Kh, const __nv_bfloat16* __restrict__ Kl,
                      const __nv_bfloat16* __restrict__ Vh,
                      __nv_bfloat16* __restrict__ Oh, __nv_bfloat16* __restrict__ Ol)
{
    extern __shared__ char smem[];
    const uint32_t sb = smem_u32(smem);
    const int tid = threadIdx.x, lane = tid & 31, w = tid >> 5;
    const int qw = (w & 3) * 16;
    const int cbase = (w >> 2) * 128;
    const bool producer = (w < 4);
    const int b = blockIdx.y, q0 = blockIdx.x * 64;

    auto load_kv = [&](int kt, int bi) {
        const int j0 = kt * 64;
        for (int i = tid; i < 512; i += 256) {
            int half = i >> 8, r = (i >> 2) & 63, ch = i & 3;
            const __nv_bfloat16* src = (half ? Kl : Kh) + ((size_t)b * N_ + j0 + r) * CQK_ + ch * 8;
            cpa16(sb + SKB + bi * 10240 + half * 5120 + r * 80 + ch * 16, src);
        }
        for (int i = tid; i < 2048; i += 256) {
            int r = i >> 3, ch = i & 7;
            const __nv_bfloat16* src = Vh + ((size_t)b * C_ + r) * N_ + j0 + ch * 8;
            cpa16(sb + SVB + bi * 36864 + r * 144 + ch * 16, src);
        }
    };

    for (int i = tid; i < 512; i += 256) {
        int half = i >> 8, r = (i >> 2) & 63, ch = i & 3;
        const __nv_bfloat16* src = (half ? Ql : Qh) + ((size_t)b * N_ + q0 + r) * CQK_ + ch * 8;
        cpa16(sb + (half ? SQL : SQH) + r * 80 + ch * 16, src);
    }
    load_kv(0, 0); CPA_COMMIT();
    load_kv(1, 1); CPA_COMMIT();
    CPA_WAIT(1);
    __syncthreads();

    uint32_t qa[2][2][4];
    if (producer) {
#pragma unroll
        for (int hl = 0; hl < 2; hl++)
#pragma unroll
            for (int kc = 0; kc < 2; kc++) {
                uint32_t addr = sb + (hl ? SQL : SQH)
                              + (uint32_t)(qw + (lane & 15)) * 80
                              + (uint32_t)(kc * 16 + (lane >> 4) * 8) * 2;
                ldsm4(addr, qa[hl][kc]);
            }
    }
    __syncthreads();

    float oacc[16][4];
#pragma unroll
    for (int i = 0; i < 16; i++)
#pragma unroll
        for (int j = 0; j < 4; j++) oacc[i][j] = 0.f;
    float rsum0 = 0.f, rsum1 = 0.f;

    for (int kt = 0; kt < 64; kt++) {
        const int bi = kt & 1;
        const uint32_t vh_b = sb + SVB + bi * 36864;

        uint32_t pah[4][4], pal[4][4];

        if (producer) {
            const uint32_t kh_b = sb + SKB + bi * 10240, kl_b = kh_b + 5120;
            float sacc[8][4];
#pragma unroll
            for (int i = 0; i < 8; i++)
#pragma unroll
                for (int j = 0; j < 4; j++) sacc[i][j] = 0.f;
#pragma unroll
            for (int kc = 0; kc < 2; kc++)
#pragma unroll
                for (int nbp = 0; nbp < 4; nbp++) {
                    uint32_t off = (uint32_t)((nbp * 2 + ((lane >> 4) & 1)) * 8 + (lane & 7)) * 80
                                 + (uint32_t)(kc * 16 + ((lane >> 3) & 1) * 8) * 2;
                    uint32_t bh[4], bl[4];
                    ldsm4(kh_b + off, bh);
                    ldsm4(kl_b + off, bl);
                    mma16816(sacc[2*nbp],   qa[0][kc], bh[0], bh[1]);
                    mma16816(sacc[2*nbp+1], qa[0][kc], bh[2], bh[3]);
                    mma16816(sacc[2*nbp],   qa[1][kc], bh[0], bh[1]);
                    mma16816(sacc[2*nbp+1], qa[1][kc], bh[2], bh[3]);
                    mma16816(sacc[2*nbp],   qa[0][kc], bl[0], bl[1]);
                    mma16816(sacc[2*nbp+1], qa[0][kc], bl[2], bl[3]);
                }
#pragma unroll
            for (int nb = 0; nb < 8; nb++) {
                float e0 = __expf(sacc[nb][0]);
                float e1 = __expf(sacc[nb][1]);
                float e2 = __expf(sacc[nb][2]);
                float e3 = __expf(sacc[nb][3]);
                rsum0 += e0 + e1;
                rsum1 += e2 + e3;
                int kj = nb >> 1, o = (nb & 1) * 2;
                uint32_t h01 = pack_bf16x2(e0, e1);
                uint32_t h23 = pack_bf16x2(e2, e3);
                pah[kj][o]     = h01;
                pah[kj][o + 1] = h23;
                pal[kj][o]     = pack_bf16x2(e0 - lo_bf16_f(h01), e1 - hi_bf16_f(h01));
                pal[kj][o + 1] = pack_bf16x2(e2 - lo_bf16_f(h23), e3 - hi_bf16_f(h23));
            }
            char* ph_dst = smem + SP_HI + (w & 3) * 2048 + lane * 16;
            char* pl_dst = smem + SP_LO + (w & 3) * 2048 + lane * 16;
#pragma unroll
            for (int kj = 0; kj < 4; kj++) {
                *(uint4*)(ph_dst + kj * 512) = make_uint4(pah[kj][0], pah[kj][1], pah[kj][2], pah[kj][3]);
                *(uint4*)(pl_dst + kj * 512) = make_uint4(pal[kj][0], pal[kj][1], pal[kj][2], pal[kj][3]);
            }
        }
        __syncthreads();

        if (!producer) {
            const char* ph_src = smem + SP_HI + (w & 3) * 2048 + lane * 16;
            const char* pl_src = smem + SP_LO + (w & 3) * 2048 + lane * 16;
#pragma unroll
            for (int kj = 0; kj < 4; kj++) {
                uint4 h4 = *(const uint4*)(ph_src + kj * 512);
                uint4 l4 = *(const uint4*)(pl_src + kj * 512);
                pah[kj][0] = h4.x; pah[kj][1] = h4.y; pah[kj][2] = h4.z; pah[kj][3] = h4.w;
                pal[kj][0] = l4.x; pal[kj][1] = l4.y; pal[kj][2] = l4.z; pal[kj][3] = l4.w;
            }
        }

#pragma unroll
        for (int cb = 0; cb < 16; cb++) {
            uint32_t rowoff = (uint32_t)(cbase + cb * 8 + (lane & 7)) * 144;
            uint32_t vfh[8];
#pragma unroll
            for (int kjp = 0; kjp < 2; kjp++) {
                uint32_t off = rowoff + (uint32_t)(kjp * 32 + (lane >> 3) * 8) * 2;
                ldsm4(vh_b + off, &vfh[4 * kjp]);
            }
#pragma unroll
            for (int kj = 0; kj < 4; kj++) {
                int ix = (kj >> 1) * 4 + (kj & 1) * 2;
                mma16816(oacc[cb], pah[kj], vfh[ix], vfh[ix + 1]);
                mma16816(oacc[cb], pal[kj], vfh[ix], vfh[ix + 1]);
            }
        }

        CPA_WAIT(0);
        __syncthreads();
        if (kt + 2 < 64) load_kv(kt + 2, bi);
        CPA_COMMIT();
    }

    float* sinv = (float*)(smem + S_INV);
    if (producer) {
        rsum0 += __shfl_xor_sync(0xffffffffu, rsum0, 1);
        rsum0 += __shfl_xor_sync(0xffffffffu, rsum0, 2);
        rsum1 += __shfl_xor_sync(0xffffffffu, rsum1, 1);
        rsum1 += __shfl_xor_sync(0xffffffffu, rsum1, 2);
        if ((lane & 3) == 0) {
            sinv[qw + (lane >> 2)]     = rsum0;
            sinv[qw + 8 + (lane >> 2)] = rsum1;
        }
    }
    __syncthreads();
    const float inv0 = 1.f / sinv[qw + (lane >> 2)];
    const float inv1 = 1.f / sinv[qw + 8 + (lane >> 2)];

    const int qg = q0 + qw + (lane >> 2);
    const size_t rbase0 = ((size_t)b * N_ + qg) * C_;
    const size_t rbase1 = ((size_t)b * N_ + qg + 8) * C_;
#pragma unroll
    for (int cb = 0; cb < 16; cb++) {
        int c = cbase + cb * 8 + (lane & 3) * 2;
        float v0 = oacc[cb][0] * inv0, v1 = oacc[cb][1] * inv0;
        float v2 = oacc[cb][2] * inv1, v3 = oacc[cb][3] * inv1;
        uint32_t h01 = pack_bf16x2(v0, v1);
        uint32_t l01 = pack_bf16x2(v0 - lo_bf16_f(h01), v1 - hi_bf16_f(h01));
        uint32_t h23 = pack_bf16x2(v2, v3);
        uint32_t l23 = pack_bf16x2(v2 - lo_bf16_f(h23), v3 - hi_bf16_f(h23));
        *(uint32_t*)&Oh[rbase0 + c] = h01;
        *(uint32_t*)&Ol[rbase0 + c] = l01;
        *(uint32_t*)&Oh[rbase1 + c] = h23;
        *(uint32_t*)&Ol[rbase1 + c] = l23;
    }
}

// ---------------- kernel_launch ----------------
extern "C" void kernel_launch(void* const* d_in, const int* in_sizes, int n_in,
                              void* d_out, int out_size)
{
    (void)in_sizes; (void)n_in; (void)out_size;
    const float* x  = (const float*)d_in[0];
    const float* Wq = (const float*)d_in[1];
    const float* bq = (const float*)d_in[2];
    const float* Wk = (const float*)d_in[3];
    const float* bk = (const float*)d_in[4];
    const float* Wv = (const float*)d_in[5];
    const float* bv = (const float*)d_in[6];
    const float* Wf = (const float*)d_in[7];
    const float* bf = (const float*)d_in[8];
    float* out = (float*)d_out;

    __nv_bfloat16 *qh, *ql, *kh, *kl, *vh, *xth, *xtl, *oth, *otl;
    __nv_bfloat16 *wvh, *wvl, *wfh, *wfl, *wqkh, *wqkl;
    cudaGetSymbolAddress((void**)&qh,   g_qh);
    cudaGetSymbolAddress((void**)&ql,   g_ql);
    cudaGetSymbolAddress((void**)&kh,   g_kh);
    cudaGetSymbolAddress((void**)&kl,   g_kl);
    cudaGetSymbolAddress((void**)&vh,   g_vh);
    cudaGetSymbolAddress((void**)&xth,  g_xth);
    cudaGetSymbolAddress((void**)&xtl,  g_xtl);
    cudaGetSymbolAddress((void**)&oth,  g_oth);
    cudaGetSymbolAddress((void**)&otl,  g_otl);
    cudaGetSymbolAddress((void**)&wvh,  g_wvh);
    cudaGetSymbolAddress((void**)&wvl,  g_wvl);
    cudaGetSymbolAddress((void**)&wfh,  g_wfh);
    cudaGetSymbolAddress((void**)&wfl,  g_wfl);
    cudaGetSymbolAddress((void**)&wqkh, g_wqkh);
    cudaGetSymbolAddress((void**)&wqkl, g_wqkl);

    cudaFuncSetAttribute(flash_mma_kernel,
                         cudaFuncAttributeMaxDynamicSharedMemorySize, FL_SMEM);
    cudaFuncSetAttribute(proj_mma_kernel<0>,
                         cudaFuncAttributeMaxDynamicSharedMemorySize, PM_SMEM);
    cudaFuncSetAttribute(proj_mma_kernel<1>,
                         cudaFuncAttributeMaxDynamicSharedMemorySize, PM_SMEM);
    cudaFuncSetAttribute(proj_qk_mma_kernel,
                         cudaFuncAttributeMaxDynamicSharedMemorySize, PM_SMEM);

    // operand prep
    wsplit_kernel<<<C_ * C_ / 256, 256>>>(Wv, wvh, wvl);
    wsplit_kernel<<<C_ * C_ / 256, 256>>>(Wf, wfh, wfl);
    wqksplit_kernel<<<64 * C_ / 256, 256>>>(Wq, Wk, wqkh, wqkl);
    xsplit_kernel<<<dim3(N_ / 64, C_ / 64, B_), 256>>>(x, xth, xtl);

    // Q+K projection on tensor cores -> bf16 hi/lo [b][N][32]
    proj_qk_mma_kernel<<<dim3(1, N_ / 128, B_), 256, PM_SMEM>>>(
        xth, xtl, wqkh, wqkl, bq, bk, qh, ql, kh, kl);

    // V projection on tensor cores -> bf16 [b][C][N]
    proj_mma_kernel<0><<<dim3(N_ / 64, 2, B_), 256, PM_SMEM>>>(wvh, wvl, xth, xtl, bv, vh);

    // attention on tensor cores -> O bf16 hi/lo [b][N][C]
    flash_mma_kernel<<<dim3(N_ / 64, B_), 256, FL_SMEM>>>(qh, ql, kh, kl, vh, oth, otl);

    // final projection on tensor cores -> fp32 out
    proj_mma_kernel<1><<<dim3(N_ / 64, 2, B_), 256, PM_SMEM>>>(wfh, wfl, oth, otl, bf, out);
}

// round 11
// speedup vs baseline: 1.5161x; 1.0032x over previous
#include <cuda_runtime.h>
#include <cuda_bf16.h>
#include <cstdint>

static constexpr int B_   = 8;
static constexpr int C_   = 256;
static constexpr int CQK_ = 32;
static constexpr int N_   = 4096;

// Scratch
__device__ __align__(256) __nv_bfloat16 g_qh[(size_t)B_ * N_ * CQK_];
__device__ __align__(256) __nv_bfloat16 g_ql[(size_t)B_ * N_ * CQK_];
__device__ __align__(256) __nv_bfloat16 g_kh[(size_t)B_ * N_ * CQK_];
__device__ __align__(256) __nv_bfloat16 g_kl[(size_t)B_ * N_ * CQK_];
__device__ __align__(256) __nv_bfloat16 g_vh[(size_t)B_ * C_ * N_];
__device__ __align__(256) __nv_bfloat16 g_xth[(size_t)B_ * N_ * C_];  // x^T hi [b][n][c]
__device__ __align__(256) __nv_bfloat16 g_xtl[(size_t)B_ * N_ * C_];
__device__ __align__(256) __nv_bfloat16 g_oth[(size_t)B_ * N_ * C_];  // O^T hi [b][n][c]
__device__ __align__(256) __nv_bfloat16 g_otl[(size_t)B_ * N_ * C_];
__device__ __align__(256) __nv_bfloat16 g_wvh[C_ * C_], g_wvl[C_ * C_];
__device__ __align__(256) __nv_bfloat16 g_wfh[C_ * C_], g_wfl[C_ * C_];
__device__ __align__(256) __nv_bfloat16 g_wqkh[64 * C_], g_wqkl[64 * C_];  // Wq||Wk stacked

// ---------------- mma / ldmatrix / cp.async ----------------
__device__ __forceinline__ uint32_t smem_u32(const void* p) {
    uint32_t a;
    asm("{ .reg .u64 t; cvta.to.shared.u64 t, %1; cvt.u32.u64 %0, t; }" : "=r"(a) : "l"(p));
    return a;
}
__device__ __forceinline__ void cpa16(uint32_t dst, const void* src) {
    asm volatile("cp.async.cg.shared.global [%0], [%1], 16;" :: "r"(dst), "l"(src) : "memory");
}
#define CPA_COMMIT() asm volatile("cp.async.commit_group;" ::: "memory")
#define CPA_WAIT(n)  asm volatile("cp.async.wait_group %0;" :: "n"(n) : "memory")

__device__ __forceinline__ void ldsm4(uint32_t addr, uint32_t* r) {
    asm volatile("ldmatrix.sync.aligned.m8n8.x4.shared.b16 {%0,%1,%2,%3}, [%4];"
                 : "=r"(r[0]), "=r"(r[1]), "=r"(r[2]), "=r"(r[3]) : "r"(addr));
}
__device__ __forceinline__ void mma16816(float* d, const uint32_t* a, uint32_t b0, uint32_t b1) {
    asm volatile("mma.sync.aligned.m16n8k16.row.col.f32.bf16.bf16.f32 "
                 "{%0,%1,%2,%3}, {%4,%5,%6,%7}, {%8,%9}, {%0,%1,%2,%3};"
                 : "+f"(d[0]), "+f"(d[1]), "+f"(d[2]), "+f"(d[3])
                 : "r"(a[0]), "r"(a[1]), "r"(a[2]), "r"(a[3]), "r"(b0), "r"(b1));
}
__device__ __forceinline__ uint32_t pack_bf16x2(float e0, float e1) {
    uint32_t r; asm("cvt.rn.bf16x2.f32 %0, %1, %2;" : "=r"(r) : "f"(e1), "f"(e0)); return r;
}
__device__ __forceinline__ float lo_bf16_f(uint32_t u) { return __uint_as_float(u << 16); }
__device__ __forceinline__ float hi_bf16_f(uint32_t u) { return __uint_as_float(u & 0xffff0000u); }
__device__ __forceinline__ void bf16_split(float v, __nv_bfloat16& h, __nv_bfloat16& l) {
    h = __float2bfloat16(v);
    l = __float2bfloat16(v - __bfloat162float(h));
}

// ---------------- W split: fp32 [256][256] -> bf16 hi/lo ----------------
__global__ __launch_bounds__(256)
void wsplit_kernel(const float* __restrict__ W,
                   __nv_bfloat16* __restrict__ Wh, __nv_bfloat16* __restrict__ Wl)
{
    int i = blockIdx.x * 256 + threadIdx.x;
    float v = W[i];
    __nv_bfloat16 h, l; bf16_split(v, h, l);
    Wh[i] = h; Wl[i] = l;
}

// ---------------- Wq||Wk stack + split: -> bf16 hi/lo [64][256] ----------------
__global__ __launch_bounds__(256)
void wqksplit_kernel(const float* __restrict__ Wq, const float* __restrict__ Wk,
                     __nv_bfloat16* __restrict__ Wh, __nv_bfloat16* __restrict__ Wl)
{
    int i = blockIdx.x * 256 + threadIdx.x;   // 64*256 = 16384
    int row = i >> 8, col = i & 255;
    float v = (row < 32) ? Wq[(size_t)row * 256 + col] : Wk[(size_t)(row - 32) * 256 + col];
    __nv_bfloat16 h, l; bf16_split(v, h, l);
    Wh[i] = h; Wl[i] = l;
}

// ---------------- x split-transpose: fp32 [b][C][N] -> bf16 hi/lo [b][N][C] ---
__global__ __launch_bounds__(256)
void xsplit_kernel(const float* __restrict__ X,
                   __nv_bfloat16* __restrict__ Yh, __nv_bfloat16* __restrict__ Yl)
{
    __shared__ float t[64][65];
    const int b  = blockIdx.z;
    const int c0 = blockIdx.y * 64;
    const int n0 = blockIdx.x * 64;
    const int tid = threadIdx.x;
    for (int i = tid; i < 4096; i += 256) {
        int c = i >> 6, n = i & 63;
        t[c][n] = X[(size_t)b * C_ * N_ + (size_t)(c0 + c) * N_ + n0 + n];
    }
    __syncthreads();
    for (int i = tid; i < 4096; i += 256) {
        int n = i >> 6, c = i & 63;
        float v = t[c][n];
        __nv_bfloat16 h, l; bf16_split(v, h, l);
        size_t o = ((size_t)b * N_ + n0 + n) * C_ + c0 + c;
        Yh[o] = h; Yl[o] = l;
    }
}

// ---------------- tensor-core projection GEMM (3-term bf16 split) -------------
static constexpr int PM_SW   = 0;        // A bufs: + bi*36864, lo at +18432; rows 144 B
static constexpr int PM_SX   = 73728;    // B bufs: + bi*18432, lo at +9216;  rows 144 B
static constexpr int PM_SMEM = 110592;

template <int OUT_FP32>
__global__ __launch_bounds__(256, 2)
void proj_mma_kernel(const __nv_bfloat16* __restrict__ Wh, const __nv_bfloat16* __restrict__ Wl,
                     const __nv_bfloat16* __restrict__ Xh, const __nv_bfloat16* __restrict__ Xl,
                     const float* __restrict__ bias, void* __restrict__ Yout)
{
    extern __shared__ char smem[];
    const uint32_t sb = smem_u32(smem);
    const int tid = threadIdx.x, lane = tid & 31, w = tid >> 5;
    const int b  = blockIdx.z;
    const int m0 = blockIdx.y * 128;
    const int n0 = blockIdx.x * 64;
    const int mw = w * 16;

    auto load_wx = [&](int ks, int bi) {
        const int k0 = ks * 64;
        for (int i = tid; i < 2048; i += 256) {
            int half = i >> 10, r = (i >> 3) & 127, ch = i & 7;
            const __nv_bfloat16* src = (half ? Wl : Wh) + (size_t)(m0 + r) * 256 + k0 + ch * 8;
            cpa16(sb + PM_SW + bi * 36864 + half * 18432 + r * 144 + ch * 16, src);
        }
        for (int i = tid; i < 1024; i += 256) {
            int half = i >> 9, r = (i >> 3) & 63, ch = i & 7;
            const __nv_bfloat16* src = (half ? Xl : Xh) + ((size_t)b * N_ + n0 + r) * 256 + k0 + ch * 8;
            cpa16(sb + PM_SX + bi * 18432 + half * 9216 + r * 144 + ch * 16, src);
        }
    };

    load_wx(0, 0); CPA_COMMIT();
    load_wx(1, 1); CPA_COMMIT();

    float oacc[8][4];
#pragma unroll
    for (int i = 0; i < 8; i++)
#pragma unroll
        for (int j = 0; j < 4; j++) oacc[i][j] = 0.f;

#pragma unroll
    for (int ks = 0; ks < 4; ks++) {
        const int bi = ks & 1;
        if (ks < 2) { CPA_WAIT(1); } else { CPA_WAIT(0); }
        __syncthreads();

        const uint32_t wb_hi = sb + PM_SW + bi * 36864;
        const uint32_t xb_hi = sb + PM_SX + bi * 18432;

        uint32_t ah[4][4], al[4][4];
#pragma unroll
        for (int kc = 0; kc < 4; kc++) {
            uint32_t addr = wb_hi + (uint32_t)(mw + (lane & 15)) * 144
                          + (uint32_t)(kc * 16 + (lane >> 4) * 8) * 2;
            ldsm4(addr, ah[kc]);
            ldsm4(addr + 18432, al[kc]);
        }

#pragma unroll
        for (int nb = 0; nb < 8; nb++) {
            uint32_t rowoff = xb_hi + (uint32_t)(nb * 8 + (lane & 7)) * 144;
            uint32_t bh[8], bl[8];
#pragma unroll
            for (int kk = 0; kk < 2; kk++) {
                uint32_t off = (uint32_t)(kk * 32 + (lane >> 3) * 8) * 2;
                ldsm4(rowoff + off, &bh[4 * kk]);
                ldsm4(rowoff + off + 9216, &bl[4 * kk]);
            }
#pragma unroll
            for (int kc = 0; kc < 4; kc++) {
                int ix = (kc >> 1) * 4 + (kc & 1) * 2;
                mma16816(oacc[nb], ah[kc], bh[ix], bh[ix + 1]);
                mma16816(oacc[nb], al[kc], bh[ix], bh[ix + 1]);
                mma16816(oacc[nb], ah[kc], bl[ix], bl[ix + 1]);
            }
        }

        __syncthreads();
        if (ks + 2 < 4) { load_wx(ks + 2, bi); CPA_COMMIT(); }
    }

    const int r0 = m0 + mw + (lane >> 2);
    const float b0f = bias[r0], b1f = bias[r0 + 8];
#pragma unroll
    for (int nb = 0; nb < 8; nb++) {
        int col = n0 + nb * 8 + (lane & 3) * 2;
        float v0 = oacc[nb][0] + b0f, v1 = oacc[nb][1] + b0f;
        float v2 = oacc[nb][2] + b1f, v3 = oacc[nb][3] + b1f;
        if (OUT_FP32) {
            float* Yf = (float*)Yout + (size_t)b * C_ * N_;
            *(float2*)&Yf[(size_t)r0 * N_ + col]       = make_float2(v0, v1);
            *(float2*)&Yf[(size_t)(r0 + 8) * N_ + col] = make_float2(v2, v3);
        } else {
            __nv_bfloat16* Yb = (__nv_bfloat16*)Yout + (size_t)b * C_ * N_;
            *(uint32_t*)&Yb[(size_t)r0 * N_ + col]       = pack_bf16x2(v0, v1);
            *(uint32_t*)&Yb[(size_t)(r0 + 8) * N_ + col] = pack_bf16x2(v2, v3);
        }
    }
}

// ---------------- Q/K projection on tensor cores ------------------------------
__global__ __launch_bounds__(256, 2)
void proj_qk_mma_kernel(const __nv_bfloat16* __restrict__ Xh, const __nv_bfloat16* __restrict__ Xl,
                        const __nv_bfloat16* __restrict__ Wh, const __nv_bfloat16* __restrict__ Wl,
                        const float* __restrict__ bq, const float* __restrict__ bk,
                        __nv_bfloat16* __restrict__ Qh, __nv_bfloat16* __restrict__ Ql,
                        __nv_bfloat16* __restrict__ Kh, __nv_bfloat16* __restrict__ Kl)
{
    extern __shared__ char smem[];
    const uint32_t sb = smem_u32(smem);
    const int tid = threadIdx.x, lane = tid & 31, w = tid >> 5;
    const int b  = blockIdx.z;
    const int m0 = blockIdx.y * 128;   // token tile
    const int mw = w * 16;

    auto load_ab = [&](int ks, int bi) {
        const int k0 = ks * 64;
        for (int i = tid; i < 2048; i += 256) {
            int half = i >> 10, r = (i >> 3) & 127, ch = i & 7;
            const __nv_bfloat16* src = (half ? Xl : Xh) + ((size_t)b * N_ + m0 + r) * 256 + k0 + ch * 8;
            cpa16(sb + PM_SW + bi * 36864 + half * 18432 + r * 144 + ch * 16, src);
        }
        for (int i = tid; i < 1024; i += 256) {
            int half = i >> 9, r = (i >> 3) & 63, ch = i & 7;
            const __nv_bfloat16* src = (half ? Wl : Wh) + (size_t)r * 256 + k0 + ch * 8;
            cpa16(sb + PM_SX + bi * 18432 + half * 9216 + r * 144 + ch * 16, src);
        }
    };

    load_ab(0, 0); CPA_COMMIT();
    load_ab(1, 1); CPA_COMMIT();

    float oacc[8][4];
#pragma unroll
    for (int i = 0; i < 8; i++)
#pragma unroll
        for (int j = 0; j < 4; j++) oacc[i][j] = 0.f;

#pragma unroll
    for (int ks = 0; ks < 4; ks++) {
        const int bi = ks & 1;
        if (ks < 2) { CPA_WAIT(1); } else { CPA_WAIT(0); }
        __syncthreads();

        const uint32_t ab_hi = sb + PM_SW + bi * 36864;
        const uint32_t bb_hi = sb + PM_SX + bi * 18432;

        uint32_t ah[4][4], al[4][4];
#pragma unroll
        for (int kc = 0; kc < 4; kc++) {
            uint32_t addr = ab_hi + (uint32_t)(mw + (lane & 15)) * 144
                          + (uint32_t)(kc * 16 + (lane >> 4) * 8) * 2;
            ldsm4(addr, ah[kc]);
            ldsm4(addr + 18432, al[kc]);
        }

#pragma unroll
        for (int nb = 0; nb < 8; nb++) {
            uint32_t rowoff = bb_hi + (uint32_t)(nb * 8 + (lane & 7)) * 144;
            uint32_t bh[8], bl[8];
#pragma unroll
            for (int kk = 0; kk < 2; kk++) {
                uint32_t off = (uint32_t)(kk * 32 + (lane >> 3) * 8) * 2;
                ldsm4(rowoff + off, &bh[4 * kk]);
                ldsm4(rowoff + off + 9216, &bl[4 * kk]);
            }
#pragma unroll
            for (int kc = 0; kc < 4; kc++) {
                int ix = (kc >> 1) * 4 + (kc & 1) * 2;
                mma16816(oacc[nb], ah[kc], bh[ix], bh[ix + 1]);
                mma16816(oacc[nb], al[kc], bh[ix], bh[ix + 1]);
                mma16816(oacc[nb], ah[kc], bl[ix], bl[ix + 1]);
            }
        }

        __syncthreads();
        if (ks + 2 < 4) { load_ab(ks + 2, bi); CPA_COMMIT(); }
    }

    const int r0 = m0 + mw + (lane >> 2);
#pragma unroll
    for (int nb = 0; nb < 8; nb++) {
        int c = nb * 8 + (lane & 3) * 2;
        const bool isQ = (c < 32);
        const int cc = isQ ? c : c - 32;
        const float bb0 = isQ ? bq[cc] : bk[cc];
        const float bb1 = isQ ? bq[cc + 1] : bk[cc + 1];
        float v0 = oacc[nb][0] + bb0, v1 = oacc[nb][1] + bb1;
        float v2 = oacc[nb][2] + bb0, v3 = oacc[nb][3] + bb1;
        uint32_t h01 = pack_bf16x2(v0, v1);
        uint32_t l01 = pack_bf16x2(v0 - lo_bf16_f(h01), v1 - hi_bf16_f(h01));
        uint32_t h23 = pack_bf16x2(v2, v3);
        uint32_t l23 = pack_bf16x2(v2 - lo_bf16_f(h23), v3 - hi_bf16_f(h23));
        __nv_bfloat16* dh = isQ ? Qh : Kh;
        __nv_bfloat16* dl = isQ ? Ql : Kl;
        size_t o0 = ((size_t)b * N_ + r0) * CQK_ + cc;
        size_t o1 = ((size_t)b * N_ + r0 + 8) * CQK_ + cc;
        *(uint32_t*)&dh[o0] = h01;
        *(uint32_t*)&dl[o0] = l01;
        *(uint32_t*)&dh[o1] = h23;
        *(uint32_t*)&dl[o1] = l23;
    }
}

// ---------------- flash attention: asymmetric producer/consumer ---------------
// Producers (w 0-3): S (48 MMAs) + exp + P exchange + PV over channels 0-103
// (13 cbs, 104 MMAs). Consumers (w 4-7): PV over channels 104-255 (19 cbs,
// 152 MMAs). Balanced critical paths; divergent role loops with matched
// bar.sync counts (2/tile each).
static constexpr int SP_HI = 0;
static constexpr int SP_LO = 8192;
static constexpr int S_INV = 16384;
static constexpr int SQH   = 0;
static constexpr int SQL   = 5120;
static constexpr int SKB   = 16640;
static constexpr int SVB   = 37120;
static constexpr int FL_SMEM = 110848;

__global__ __launch_bounds__(256, 2)
void flash_mma_kernel(const __nv_bfloat16* __restrict__ Qh, const __nv_bfloat16* __restrict__ Ql,
                      const __nv_bfloat16* __restrict__ Kh, const __nv_bfloat16* __restrict__ Kl,
                      const __nv_bfloat16* __restrict__ Vh,
                      __nv_bfloat16* __restrict__ Oh, __nv_bfloat16* __restrict__ Ol)
{
    extern __shared__ char smem[];
    const uint32_t sb = smem_u32(smem);
    const int tid = threadIdx.x, lane = tid & 31, w = tid >> 5;
    const int qw = (w & 3) * 16;
    const int b = blockIdx.y, q0 = blockIdx.x * 64;

    auto load_kv = [&](int kt, int bi) {
        const int j0 = kt * 64;
        for (int i = tid; i < 512; i += 256) {
            int half = i >> 8, r = (i >> 2) & 63, ch = i & 3;
            const __nv_bfloat16* src = (half ? Kl : Kh) + ((size_t)b * N_ + j0 + r) * CQK_ + ch * 8;
            cpa16(sb + SKB + bi * 10240 + half * 5120 + r * 80 + ch * 16, src);
        }
        for (int i = tid; i < 2048; i += 256) {
            int r = i >> 3, ch = i & 7;
            const __nv_bfloat16* src = Vh + ((size_t)b * C_ + r) * N_ + j0 + ch * 8;
            cpa16(sb + SVB + bi * 36864 + r * 144 + ch * 16, src);
        }
    };

    for (int i = tid; i < 512; i += 256) {
        int half = i >> 8, r = (i >> 2) & 63, ch = i & 3;
        const __nv_bfloat16* src = (half ? Ql : Qh) + ((size_t)b * N_ + q0 + r) * CQK_ + ch * 8;
        cpa16(sb + (half ? SQL : SQH) + r * 80 + ch * 16, src);
    }
    load_kv(0, 0); CPA_COMMIT();
    load_kv(1, 1); CPA_COMMIT();
    CPA_WAIT(1);
    __syncthreads();

    float* sinv = (float*)(smem + S_INV);
    const int qg = q0 + qw + (lane >> 2);
    const size_t rbase0 = ((size_t)b * N_ + qg) * C_;
    const size_t rbase1 = ((size_t)b * N_ + qg + 8) * C_;

    if (w < 4) {
        // ================= PRODUCER =================
        uint32_t qa[2][2][4];
#pragma unroll
        for (int hl = 0; hl < 2; hl++)
#pragma unroll
            for (int kc = 0; kc < 2; kc++) {
                uint32_t addr = sb + (hl ? SQL : SQH)
                              + (uint32_t)(qw + (lane & 15)) * 80
                              + (uint32_t)(kc * 16 + (lane >> 4) * 8) * 2;
                ldsm4(addr, qa[hl][kc]);
            }
        __syncthreads();   // sync #0 (Q region dead)

        float oacc[13][4];
#pragma unroll
        for (int i = 0; i < 13; i++)
#pragma unroll
            for (int j = 0; j < 4; j++) oacc[i][j] = 0.f;
        float rsum0 = 0.f, rsum1 = 0.f;

        for (int kt = 0; kt < 64; kt++) {
            const int bi = kt & 1;
            const uint32_t kh_b = sb + SKB + bi * 10240, kl_b = kh_b + 5120;
            const uint32_t vh_b = sb + SVB + bi * 36864;

            // S = QK^T (3-term)
            float sacc[8][4];
#pragma unroll
            for (int i = 0; i < 8; i++)
#pragma unroll
                for (int j = 0; j < 4; j++) sacc[i][j] = 0.f;
#pragma unroll
            for (int kc = 0; kc < 2; kc++)
#pragma unroll
                for (int nbp = 0; nbp < 4; nbp++) {
                    uint32_t off = (uint32_t)((nbp * 2 + ((lane >> 4) & 1)) * 8 + (lane & 7)) * 80
                                 + (uint32_t)(kc * 16 + ((lane >> 3) & 1) * 8) * 2;
                    uint32_t bh[4], bl[4];
                    ldsm4(kh_b + off, bh);
                    ldsm4(kl_b + off, bl);
                    mma16816(sacc[2*nbp],   qa[0][kc], bh[0], bh[1]);
                    mma16816(sacc[2*nbp+1], qa[0][kc], bh[2], bh[3]);
                    mma16816(sacc[2*nbp],   qa[1][kc], bh[0], bh[1]);
                    mma16816(sacc[2*nbp+1], qa[1][kc], bh[2], bh[3]);
                    mma16816(sacc[2*nbp],   qa[0][kc], bl[0], bl[1]);
                    mma16816(sacc[2*nbp+1], qa[0][kc], bl[2], bl[3]);
                }

            // P = exp(S); pack hi/lo
            uint32_t pah[4][4], pal[4][4];
#pragma unroll
            for (int nb = 0; nb < 8; nb++) {
                float e0 = __expf(sacc[nb][0]);
                float e1 = __expf(sacc[nb][1]);
                float e2 = __expf(sacc[nb][2]);
                float e3 = __expf(sacc[nb][3]);
                rsum0 += e0 + e1;
                rsum1 += e2 + e3;
                int kj = nb >> 1, o = (nb & 1) * 2;
                uint32_t h01 = pack_bf16x2(e0, e1);
                uint32_t h23 = pack_bf16x2(e2, e3);
                pah[kj][o]     = h01;
                pah[kj][o + 1] = h23;
                pal[kj][o]     = pack_bf16x2(e0 - lo_bf16_f(h01), e1 - hi_bf16_f(h01));
                pal[kj][o + 1] = pack_bf16x2(e2 - lo_bf16_f(h23), e3 - hi_bf16_f(h23));
            }
            // mirror P for partner warp
            char* ph_dst = smem + SP_HI + (w & 3) * 2048 + lane * 16;
            char* pl_dst = smem + SP_LO + (w & 3) * 2048 + lane * 16;
#pragma unroll
            for (int kj = 0; kj < 4; kj++) {
                *(uint4*)(ph_dst + kj * 512) = make_uint4(pah[kj][0], pah[kj][1], pah[kj][2], pah[kj][3]);
                *(uint4*)(pl_dst + kj * 512) = make_uint4(pal[kj][0], pal[kj][1], pal[kj][2], pal[kj][3]);
            }
            __syncthreads();   // sync #1: P visible

            // PV over channels 0..103 (13 cbs)
#pragma unroll
            for (int cb = 0; cb < 13; cb++) {
                uint32_t rowoff = (uint32_t)(cb * 8 + (lane & 7)) * 144;
                uint32_t vfh[8];
#pragma unroll
                for (int kjp = 0; kjp < 2; kjp++) {
                    uint32_t off = rowoff + (uint32_t)(kjp * 32 + (lane >> 3) * 8) * 2;
                    ldsm4(vh_b + off, &vfh[4 * kjp]);
                }
#pragma unroll
                for (int kj = 0; kj < 4; kj++) {
                    int ix = (kj >> 1) * 4 + (kj & 1) * 2;
                    mma16816(oacc[cb], pah[kj], vfh[ix], vfh[ix + 1]);
                    mma16816(oacc[cb], pal[kj], vfh[ix], vfh[ix + 1]);
                }
            }

            CPA_WAIT(0);
            __syncthreads();   // sync #2: buffer reads done
            if (kt + 2 < 64) load_kv(kt + 2, bi);
            CPA_COMMIT();
        }

        // row sums
        rsum0 += __shfl_xor_sync(0xffffffffu, rsum0, 1);
        rsum0 += __shfl_xor_sync(0xffffffffu, rsum0, 2);
        rsum1 += __shfl_xor_sync(0xffffffffu, rsum1, 1);
        rsum1 += __shfl_xor_sync(0xffffffffu, rsum1, 2);
        if ((lane & 3) == 0) {
            sinv[qw + (lane >> 2)]     = rsum0;
            sinv[qw + 8 + (lane >> 2)] = rsum1;
        }
        __syncthreads();   // sync #3
        const float inv0 = 1.f / sinv[qw + (lane >> 2)];
        const float inv1 = 1.f / sinv[qw + 8 + (lane >> 2)];

#pragma unroll
        for (int cb = 0; cb < 13; cb++) {
            int c = cb * 8 + (lane & 3) * 2;
            float v0 = oacc[cb][0] * inv0, v1 = oacc[cb][1] * inv0;
            float v2 = oacc[cb][2] * inv1, v3 = oacc[cb][3] * inv1;
            uint32_t h01 = pack_bf16x2(v0, v1);
            uint32_t l01 = pack_bf16x2(v0 - lo_bf16_f(h01), v1 - hi_bf16_f(h01));
            uint32_t h23 = pack_bf16x2(v2, v3);
            uint32_t l23 = pack_bf16x2(v2 - lo_bf16_f(h23), v3 - hi_bf16_f(h23));
            *(uint32_t*)&Oh[rbase0 + c] = h01;
            *(uint32_t*)&Ol[rbase0 + c] = l01;
            *(uint32_t*)&Oh[rbase1 + c] = h23;
            *(uint32_t*)&Ol[rbase1 + c] = l23;
        }
    } else {
        // ================= CONSUMER =================
        __syncthreads();   // sync #0 (match producer)

        float oacc[19][4];
#pragma unroll
        for (int i = 0; i < 19; i++)
#pragma unroll
            for (int j = 0; j < 4; j++) oacc[i][j] = 0.f;

        const char* ph_src = smem + SP_HI + (w & 3) * 2048 + lane * 16;
        const char* pl_src = smem + SP_LO + (w & 3) * 2048 + lane * 16;

        for (int kt = 0; kt < 64; kt++) {
            const int bi = kt & 1;
            const uint32_t vh_b = sb + SVB + bi * 36864;

            __syncthreads();   // sync #1: P visible

            uint32_t pah[4][4], pal[4][4];
#pragma unroll
            for (int kj = 0; kj < 4; kj++) {
                uint4 h4 = *(const uint4*)(ph_src + kj * 512);
                uint4 l4 = *(const uint4*)(pl_src + kj * 512);
                pah[kj][0] = h4.x; pah[kj][1] = h4.y; pah[kj][2] = h4.z; pah[kj][3] = h4.w;
                pal[kj][0] = l4.x; pal[kj][1] = l4.y; pal[kj][2] = l4.z; pal[kj][3] = l4.w;
            }

            // PV over channels 104..255 (19 cbs)
#pragma unroll
            for (int cb = 0; cb < 19; cb++) {
                uint32_t rowoff = (uint32_t)(104 + cb * 8 + (lane & 7)) * 144;
                uint32_t vfh[8];
#pragma unroll
                for (int kjp = 0; kjp < 2; kjp++) {
                    uint32_t off = rowoff + (uint32_t)(kjp * 32 + (lane >> 3) * 8) * 2;
                    ldsm4(vh_b + off, &vfh[4 * kjp]);
                }
#pragma unroll
                for (int kj = 0; kj < 4; kj++) {
                    int ix = (kj >> 1) * 4 + (kj & 1) * 2;
                    mma16816(oacc[cb], pah[kj], vfh[ix], vfh[ix + 1]);
                    mma16816(oacc[cb], pal[kj], vfh[ix], vfh[ix + 1]);
                }
            }

            CPA_WAIT(0);
            __syncthreads();   // sync #2
            if (kt + 2 < 64) load_kv(kt + 2, bi);
            CPA_COMMIT();
        }

        __syncthreads();   // sync #3 (sinv ready)
        const float inv0 = 1.f / sinv[qw + (lane >> 2)];
        const float inv1 = 1.f / sinv[qw + 8 + (lane >> 2)];

#pragma unroll
        for (int cb = 0; cb < 19; cb++) {
            int c = 104 + cb * 8 + (lane & 3) * 2;
            float v0 = oacc[cb][0] * inv0, v1 = oacc[cb][1] * inv0;
            float v2 = oacc[cb][2] * inv1, v3 = oacc[cb][3] * inv1;
            uint32_t h01 = pack_bf16x2(v0, v1);
            uint32_t l01 = pack_bf16x2(v0 - lo_bf16_f(h01), v1 - hi_bf16_f(h01));
            uint32_t h23 = pack_bf16x2(v2, v3);
            uint32_t l23 = pack_bf16x2(v2 - lo_bf16_f(h23), v3 - hi_bf16_f(h23));
            *(uint32_t*)&Oh[rbase0 + c] = h01;
            *(uint32_t*)&Ol[rbase0 + c] = l01;
            *(uint32_t*)&Oh[rbase1 + c] = h23;
            *(uint32_t*)&Ol[rbase1 + c] = l23;
        }
    }
}

// ---------------- kernel_launch ----------------
extern "C" void kernel_launch(void* const* d_in, const int* in_sizes, int n_in,
                              void* d_out, int out_size)
{
    (void)in_sizes; (void)n_in; (void)out_size;
    const float* x  = (const float*)d_in[0];
    const float* Wq = (const float*)d_in[1];
    const float* bq = (const float*)d_in[2];
    const float* Wk = (const float*)d_in[3];
    const float* bk = (const float*)d_in[4];
    const float* Wv = (const float*)d_in[5];
    const float* bv = (const float*)d_in[6];
    const float* Wf = (const float*)d_in[7];
    const float* bf = (const float*)d_in[8];
    float* out = (float*)d_out;

    __nv_bfloat16 *qh, *ql, *kh, *kl, *vh, *xth, *xtl, *oth, *otl;
    __nv_bfloat16 *wvh, *wvl, *wfh, *wfl, *wqkh, *wqkl;
    cudaGetSymbolAddress((void**)&qh,   g_qh);
    cudaGetSymbolAddress((void**)&ql,   g_ql);
    cudaGetSymbolAddress((void**)&kh,   g_kh);
    cudaGetSymbolAddress((void**)&kl,   g_kl);
    cudaGetSymbolAddress((void**)&vh,   g_vh);
    cudaGetSymbolAddress((void**)&xth,  g_xth);
    cudaGetSymbolAddress((void**)&xtl,  g_xtl);
    cudaGetSymbolAddress((void**)&oth,  g_oth);
    cudaGetSymbolAddress((void**)&otl,  g_otl);
    cudaGetSymbolAddress((void**)&wvh,  g_wvh);
    cudaGetSymbolAddress((void**)&wvl,  g_wvl);
    cudaGetSymbolAddress((void**)&wfh,  g_wfh);
    cudaGetSymbolAddress((void**)&wfl,  g_wfl);
    cudaGetSymbolAddress((void**)&wqkh, g_wqkh);
    cudaGetSymbolAddress((void**)&wqkl, g_wqkl);

    cudaFuncSetAttribute(flash_mma_kernel,
                         cudaFuncAttributeMaxDynamicSharedMemorySize, FL_SMEM);
    cudaFuncSetAttribute(proj_mma_kernel<0>,
                         cudaFuncAttributeMaxDynamicSharedMemorySize, PM_SMEM);
    cudaFuncSetAttribute(proj_mma_kernel<1>,
                         cudaFuncAttributeMaxDynamicSharedMemorySize, PM_SMEM);
    cudaFuncSetAttribute(proj_qk_mma_kernel,
                         cudaFuncAttributeMaxDynamicSharedMemorySize, PM_SMEM);

    // operand prep
    wsplit_kernel<<<C_ * C_ / 256, 256>>>(Wv, wvh, wvl);
    wsplit_kernel<<<C_ * C_ / 256, 256>>>(Wf, wfh, wfl);
    wqksplit_kernel<<<64 * C_ / 256, 256>>>(Wq, Wk, wqkh, wqkl);
    xsplit_kernel<<<dim3(N_ / 64, C_ / 64, B_), 256>>>(x, xth, xtl);

    // Q+K projection on tensor cores -> bf16 hi/lo [b][N][32]
    proj_qk_mma_kernel<<<dim3(1, N_ / 128, B_), 256, PM_SMEM>>>(
        xth, xtl, wqkh, wqkl, bq, bk, qh, ql, kh, kl);

    // V projection on tensor cores -> bf16 [b][C][N]
    proj_mma_kernel<0><<<dim3(N_ / 64, 2, B_), 256, PM_SMEM>>>(wvh, wvl, xth, xtl, bv, vh);

    // attention on tensor cores -> O bf16 hi/lo [b][N][C]
    flash_mma_kernel<<<dim3(N_ / 64, B_), 256, FL_SMEM>>>(qh, ql, kh, kl, vh, oth, otl);

    // final projection on tensor cores -> fp32 out
    proj_mma_kernel<1><<<dim3(N_ / 64, 2, B_), 256, PM_SMEM>>>(wfh, wfl, oth, otl, bf, out);
}

// round 12
// speedup vs baseline: 1.5167x; 1.0004x over previous
#include <cuda_runtime.h>
#include <cuda_bf16.h>
#include <cstdint>

static constexpr int B_   = 8;
static constexpr int C_   = 256;
static constexpr int CQK_ = 32;
static constexpr int N_   = 4096;

// Scratch
__device__ __align__(256) __nv_bfloat16 g_qh[(size_t)B_ * N_ * CQK_];
__device__ __align__(256) __nv_bfloat16 g_ql[(size_t)B_ * N_ * CQK_];
__device__ __align__(256) __nv_bfloat16 g_kh[(size_t)B_ * N_ * CQK_];
__device__ __align__(256) __nv_bfloat16 g_kl[(size_t)B_ * N_ * CQK_];
__device__ __align__(256) __nv_bfloat16 g_vh[(size_t)B_ * C_ * N_];
__device__ __align__(256) __nv_bfloat16 g_xth[(size_t)B_ * N_ * C_];
__device__ __align__(256) __nv_bfloat16 g_xtl[(size_t)B_ * N_ * C_];
__device__ __align__(256) __nv_bfloat16 g_oth[(size_t)B_ * N_ * C_];
__device__ __align__(256) __nv_bfloat16 g_otl[(size_t)B_ * N_ * C_];
__device__ __align__(256) __nv_bfloat16 g_wvh[C_ * C_], g_wvl[C_ * C_];
__device__ __align__(256) __nv_bfloat16 g_wfh[C_ * C_], g_wfl[C_ * C_];
__device__ __align__(256) __nv_bfloat16 g_wqkh[64 * C_], g_wqkl[64 * C_];

// ---------------- helpers ----------------
__device__ __forceinline__ uint32_t smem_u32(const void* p) {
    uint32_t a;
    asm("{ .reg .u64 t; cvta.to.shared.u64 t, %1; cvt.u32.u64 %0, t; }" : "=r"(a) : "l"(p));
    return a;
}
__device__ __forceinline__ void cpa16(uint32_t dst, const void* src) {
    asm volatile("cp.async.cg.shared.global [%0], [%1], 16;" :: "r"(dst), "l"(src) : "memory");
}
#define CPA_COMMIT() asm volatile("cp.async.commit_group;" ::: "memory")
#define CPA_WAIT(n)  asm volatile("cp.async.wait_group %0;" :: "n"(n) : "memory")
#define BAR_SYNC(id, cnt)   asm volatile("bar.sync %0, %1;"   :: "r"(id), "r"(cnt) : "memory")
#define BAR_ARRIVE(id, cnt) asm volatile("bar.arrive %0, %1;" :: "r"(id), "r"(cnt) : "memory")

__device__ __forceinline__ void ldsm4(uint32_t addr, uint32_t* r) {
    asm volatile("ldmatrix.sync.aligned.m8n8.x4.shared.b16 {%0,%1,%2,%3}, [%4];"
                 : "=r"(r[0]), "=r"(r[1]), "=r"(r[2]), "=r"(r[3]) : "r"(addr));
}
__device__ __forceinline__ void mma16816(float* d, const uint32_t* a, uint32_t b0, uint32_t b1) {
    asm volatile("mma.sync.aligned.m16n8k16.row.col.f32.bf16.bf16.f32 "
                 "{%0,%1,%2,%3}, {%4,%5,%6,%7}, {%8,%9}, {%0,%1,%2,%3};"
                 : "+f"(d[0]), "+f"(d[1]), "+f"(d[2]), "+f"(d[3])
                 : "r"(a[0]), "r"(a[1]), "r"(a[2]), "r"(a[3]), "r"(b0), "r"(b1));
}
__device__ __forceinline__ uint32_t pack_bf16x2(float e0, float e1) {
    uint32_t r; asm("cvt.rn.bf16x2.f32 %0, %1, %2;" : "=r"(r) : "f"(e1), "f"(e0)); return r;
}
__device__ __forceinline__ float lo_bf16_f(uint32_t u) { return __uint_as_float(u << 16); }
__device__ __forceinline__ float hi_bf16_f(uint32_t u) { return __uint_as_float(u & 0xffff0000u); }
__device__ __forceinline__ void bf16_split(float v, __nv_bfloat16& h, __nv_bfloat16& l) {
    h = __float2bfloat16(v);
    l = __float2bfloat16(v - __bfloat162float(h));
}

// ---------------- W split ----------------
__global__ __launch_bounds__(256)
void wsplit_kernel(const float* __restrict__ W,
                   __nv_bfloat16* __restrict__ Wh, __nv_bfloat16* __restrict__ Wl)
{
    int i = blockIdx.x * 256 + threadIdx.x;
    float v = W[i];
    __nv_bfloat16 h, l; bf16_split(v, h, l);
    Wh[i] = h; Wl[i] = l;
}

// ---------------- Wq||Wk stack + split ----------------
__global__ __launch_bounds__(256)
void wqksplit_kernel(const float* __restrict__ Wq, const float* __restrict__ Wk,
                     __nv_bfloat16* __restrict__ Wh, __nv_bfloat16* __restrict__ Wl)
{
    int i = blockIdx.x * 256 + threadIdx.x;
    int row = i >> 8, col = i & 255;
    float v = (row < 32) ? Wq[(size_t)row * 256 + col] : Wk[(size_t)(row - 32) * 256 + col];
    __nv_bfloat16 h, l; bf16_split(v, h, l);
    Wh[i] = h; Wl[i] = l;
}

// ---------------- x split-transpose (vectorized bf162 stores) ----------------
__global__ __launch_bounds__(256)
void xsplit_kernel(const float* __restrict__ X,
                   __nv_bfloat16* __restrict__ Yh, __nv_bfloat16* __restrict__ Yl)
{
    __shared__ float t[64][65];
    const int b  = blockIdx.z;
    const int c0 = blockIdx.y * 64;
    const int n0 = blockIdx.x * 64;
    const int tid = threadIdx.x;
    for (int i = tid; i < 4096; i += 256) {
        int c = i >> 6, n = i & 63;
        t[c][n] = X[(size_t)b * C_ * N_ + (size_t)(c0 + c) * N_ + n0 + n];
    }
    __syncthreads();
    for (int i = tid; i < 2048; i += 256) {
        int n = i >> 5, c2 = (i & 31) * 2;
        float v0 = t[c2][n], v1 = t[c2 + 1][n];
        __nv_bfloat16 h0, l0, h1, l1;
        bf16_split(v0, h0, l0);
        bf16_split(v1, h1, l1);
        __nv_bfloat162 hh, ll;
        hh.x = h0; hh.y = h1; ll.x = l0; ll.y = l1;
        size_t o = ((size_t)b * N_ + n0 + n) * C_ + c0 + c2;
        *(__nv_bfloat162*)&Yh[o] = hh;
        *(__nv_bfloat162*)&Yl[o] = ll;
    }
}

// ---------------- tensor-core projection GEMM (3-term bf16 split) -------------
static constexpr int PM_SW   = 0;
static constexpr int PM_SX   = 73728;
static constexpr int PM_SMEM = 110592;

template <int OUT_FP32>
__global__ __launch_bounds__(256, 2)
void proj_mma_kernel(const __nv_bfloat16* __restrict__ Wh, const __nv_bfloat16* __restrict__ Wl,
                     const __nv_bfloat16* __restrict__ Xh, const __nv_bfloat16* __restrict__ Xl,
                     const float* __restrict__ bias, void* __restrict__ Yout)
{
    extern __shared__ char smem[];
    const uint32_t sb = smem_u32(smem);
    const int tid = threadIdx.x, lane = tid & 31, w = tid >> 5;
    const int b  = blockIdx.z;
    const int m0 = blockIdx.y * 128;
    const int n0 = blockIdx.x * 64;
    const int mw = w * 16;

    auto load_wx = [&](int ks, int bi) {
        const int k0 = ks * 64;
        for (int i = tid; i < 2048; i += 256) {
            int half = i >> 10, r = (i >> 3) & 127, ch = i & 7;
            const __nv_bfloat16* src = (half ? Wl : Wh) + (size_t)(m0 + r) * 256 + k0 + ch * 8;
            cpa16(sb + PM_SW + bi * 36864 + half * 18432 + r * 144 + ch * 16, src);
        }
        for (int i = tid; i < 1024; i += 256) {
            int half = i >> 9, r = (i >> 3) & 63, ch = i & 7;
            const __nv_bfloat16* src = (half ? Xl : Xh) + ((size_t)b * N_ + n0 + r) * 256 + k0 + ch * 8;
            cpa16(sb + PM_SX + bi * 18432 + half * 9216 + r * 144 + ch * 16, src);
        }
    };

    load_wx(0, 0); CPA_COMMIT();
    load_wx(1, 1); CPA_COMMIT();

    float oacc[8][4];
#pragma unroll
    for (int i = 0; i < 8; i++)
#pragma unroll
        for (int j = 0; j < 4; j++) oacc[i][j] = 0.f;

#pragma unroll
    for (int ks = 0; ks < 4; ks++) {
        const int bi = ks & 1;
        if (ks < 2) { CPA_WAIT(1); } else { CPA_WAIT(0); }
        __syncthreads();

        const uint32_t wb_hi = sb + PM_SW + bi * 36864;
        const uint32_t xb_hi = sb + PM_SX + bi * 18432;

        uint32_t ah[4][4], al[4][4];
#pragma unroll
        for (int kc = 0; kc < 4; kc++) {
            uint32_t addr = wb_hi + (uint32_t)(mw + (lane & 15)) * 144
                          + (uint32_t)(kc * 16 + (lane >> 4) * 8) * 2;
            ldsm4(addr, ah[kc]);
            ldsm4(addr + 18432, al[kc]);
        }

#pragma unroll
        for (int nb = 0; nb < 8; nb++) {
            uint32_t rowoff = xb_hi + (uint32_t)(nb * 8 + (lane & 7)) * 144;
            uint32_t bh[8], bl[8];
#pragma unroll
            for (int kk = 0; kk < 2; kk++) {
                uint32_t off = (uint32_t)(kk * 32 + (lane >> 3) * 8) * 2;
                ldsm4(rowoff + off, &bh[4 * kk]);
                ldsm4(rowoff + off + 9216, &bl[4 * kk]);
            }
#pragma unroll
            for (int kc = 0; kc < 4; kc++) {
                int ix = (kc >> 1) * 4 + (kc & 1) * 2;
                mma16816(oacc[nb], ah[kc], bh[ix], bh[ix + 1]);
                mma16816(oacc[nb], al[kc], bh[ix], bh[ix + 1]);
                mma16816(oacc[nb], ah[kc], bl[ix], bl[ix + 1]);
            }
        }

        __syncthreads();
        if (ks + 2 < 4) { load_wx(ks + 2, bi); CPA_COMMIT(); }
    }

    const int r0 = m0 + mw + (lane >> 2);
    const float b0f = bias[r0], b1f = bias[r0 + 8];
#pragma unroll
    for (int nb = 0; nb < 8; nb++) {
        int col = n0 + nb * 8 + (lane & 3) * 2;
        float v0 = oacc[nb][0] + b0f, v1 = oacc[nb][1] + b0f;
        float v2 = oacc[nb][2] + b1f, v3 = oacc[nb][3] + b1f;
        if (OUT_FP32) {
            float* Yf = (float*)Yout + (size_t)b * C_ * N_;
            *(float2*)&Yf[(size_t)r0 * N_ + col]       = make_float2(v0, v1);
            *(float2*)&Yf[(size_t)(r0 + 8) * N_ + col] = make_float2(v2, v3);
        } else {
            __nv_bfloat16* Yb = (__nv_bfloat16*)Yout + (size_t)b * C_ * N_;
            *(uint32_t*)&Yb[(size_t)r0 * N_ + col]       = pack_bf16x2(v0, v1);
            *(uint32_t*)&Yb[(size_t)(r0 + 8) * N_ + col] = pack_bf16x2(v2, v3);
        }
    }
}

// ---------------- Q/K projection on tensor cores ------------------------------
__global__ __launch_bounds__(256, 2)
void proj_qk_mma_kernel(const __nv_bfloat16* __restrict__ Xh, const __nv_bfloat16* __restrict__ Xl,
                        const __nv_bfloat16* __restrict__ Wh, const __nv_bfloat16* __restrict__ Wl,
                        const float* __restrict__ bq, const float* __restrict__ bk,
                        __nv_bfloat16* __restrict__ Qh, __nv_bfloat16* __restrict__ Ql,
                        __nv_bfloat16* __restrict__ Kh, __nv_bfloat16* __restrict__ Kl)
{
    extern __shared__ char smem[];
    const uint32_t sb = smem_u32(smem);
    const int tid = threadIdx.x, lane = tid & 31, w = tid >> 5;
    const int b  = blockIdx.z;
    const int m0 = blockIdx.y * 128;
    const int mw = w * 16;

    auto load_ab = [&](int ks, int bi) {
        const int k0 = ks * 64;
        for (int i = tid; i < 2048; i += 256) {
            int half = i >> 10, r = (i >> 3) & 127, ch = i & 7;
            const __nv_bfloat16* src = (half ? Xl : Xh) + ((size_t)b * N_ + m0 + r) * 256 + k0 + ch * 8;
            cpa16(sb + PM_SW + bi * 36864 + half * 18432 + r * 144 + ch * 16, src);
        }
        for (int i = tid; i < 1024; i += 256) {
            int half = i >> 9, r = (i >> 3) & 63, ch = i & 7;
            const __nv_bfloat16* src = (half ? Wl : Wh) + (size_t)r * 256 + k0 + ch * 8;
            cpa16(sb + PM_SX + bi * 18432 + half * 9216 + r * 144 + ch * 16, src);
        }
    };

    load_ab(0, 0); CPA_COMMIT();
    load_ab(1, 1); CPA_COMMIT();

    float oacc[8][4];
#pragma unroll
    for (int i = 0; i < 8; i++)
#pragma unroll
        for (int j = 0; j < 4; j++) oacc[i][j] = 0.f;

#pragma unroll
    for (int ks = 0; ks < 4; ks++) {
        const int bi = ks & 1;
        if (ks < 2) { CPA_WAIT(1); } else { CPA_WAIT(0); }
        __syncthreads();

        const uint32_t ab_hi = sb + PM_SW + bi * 36864;
        const uint32_t bb_hi = sb + PM_SX + bi * 18432;

        uint32_t ah[4][4], al[4][4];
#pragma unroll
        for (int kc = 0; kc < 4; kc++) {
            uint32_t addr = ab_hi + (uint32_t)(mw + (lane & 15)) * 144
                          + (uint32_t)(kc * 16 + (lane >> 4) * 8) * 2;
            ldsm4(addr, ah[kc]);
            ldsm4(addr + 18432, al[kc]);
        }

#pragma unroll
        for (int nb = 0; nb < 8; nb++) {
            uint32_t rowoff = bb_hi + (uint32_t)(nb * 8 + (lane & 7)) * 144;
            uint32_t bh[8], bl[8];
#pragma unroll
            for (int kk = 0; kk < 2; kk++) {
                uint32_t off = (uint32_t)(kk * 32 + (lane >> 3) * 8) * 2;
                ldsm4(rowoff + off, &bh[4 * kk]);
                ldsm4(rowoff + off + 9216, &bl[4 * kk]);
            }
#pragma unroll
            for (int kc = 0; kc < 4; kc++) {
                int ix = (kc >> 1) * 4 + (kc & 1) * 2;
                mma16816(oacc[nb], ah[kc], bh[ix], bh[ix + 1]);
                mma16816(oacc[nb], al[kc], bh[ix], bh[ix + 1]);
                mma16816(oacc[nb], ah[kc], bl[ix], bl[ix + 1]);
            }
        }

        __syncthreads();
        if (ks + 2 < 4) { load_ab(ks + 2, bi); CPA_COMMIT(); }
    }

    const int r0 = m0 + mw + (lane >> 2);
#pragma unroll
    for (int nb = 0; nb < 8; nb++) {
        int c = nb * 8 + (lane & 3) * 2;
        const bool isQ = (c < 32);
        const int cc = isQ ? c : c - 32;
        const float bb0 = isQ ? bq[cc] : bk[cc];
        const float bb1 = isQ ? bq[cc + 1] : bk[cc + 1];
        float v0 = oacc[nb][0] + bb0, v1 = oacc[nb][1] + bb1;
        float v2 = oacc[nb][2] + bb0, v3 = oacc[nb][3] + bb1;
        uint32_t h01 = pack_bf16x2(v0, v1);
        uint32_t l01 = pack_bf16x2(v0 - lo_bf16_f(h01), v1 - hi_bf16_f(h01));
        uint32_t h23 = pack_bf16x2(v2, v3);
        uint32_t l23 = pack_bf16x2(v2 - lo_bf16_f(h23), v3 - hi_bf16_f(h23));
        __nv_bfloat16* dh = isQ ? Qh : Kh;
        __nv_bfloat16* dl = isQ ? Ql : Kl;
        size_t o0 = ((size_t)b * N_ + r0) * CQK_ + cc;
        size_t o1 = ((size_t)b * N_ + r0 + 8) * CQK_ + cc;
        *(uint32_t*)&dh[o0] = h01;
        *(uint32_t*)&dl[o0] = l01;
        *(uint32_t*)&dh[o1] = h23;
        *(uint32_t*)&dl[o1] = l23;
    }
}

// ---------------- flash attention: pipelined producer/consumer ----------------
// Producers (w 0-3): load K, compute S/exp/P, PV channels 0-103.
// Consumers (w 4-7): load V, PV channels 104-255.
// Named barriers (arrive/sync counts verified per tile):
//  1: P ready       (P arrive, C sync)        x64/x64
//  2: P buffer free (C arrive kt<63, P sync kt>0)  x63/x63
//  3: V(kt+1) ready (C arrive kt<63, P sync kt>0)  x63/x63
//  4: V(kt) free    (P arrive, C sync)        x64/x64
//  5: producer-group K visibility (128)       pre-loop + per tile
//  6: consumer-group V visibility (128)       per tile
//  7: sinv handoff  (P arrive, C sync)        x1/x1
static constexpr int SP_HI = 0;
static constexpr int SP_LO = 8192;
static constexpr int S_INV = 16384;
static constexpr int SQH   = 0;
static constexpr int SQL   = 5120;
static constexpr int SKB   = 16640;
static constexpr int SVB   = 37120;
static constexpr int FL_SMEM = 110848;

__global__ __launch_bounds__(256, 2)
void flash_mma_kernel(const __nv_bfloat16* __restrict__ Qh, const __nv_bfloat16* __restrict__ Ql,
                      const __nv_bfloat16* __restrict__ Kh, const __nv_bfloat16* __restrict__ Kl,
                      const __nv_bfloat16* __restrict__ Vh,
                      __nv_bfloat16* __restrict__ Oh, __nv_bfloat16* __restrict__ Ol)
{
    extern __shared__ char smem[];
    const uint32_t sb = smem_u32(smem);
    const int tid = threadIdx.x, lane = tid & 31, w = tid >> 5;
    const int qw = (w & 3) * 16;
    const int b = blockIdx.y, q0 = blockIdx.x * 64;

    // ---- prologue (all 256 threads): Q, K0, V0 | K1, V1 ----
    for (int i = tid; i < 512; i += 256) {
        int half = i >> 8, r = (i >> 2) & 63, ch = i & 3;
        const __nv_bfloat16* src = (half ? Ql : Qh) + ((size_t)b * N_ + q0 + r) * CQK_ + ch * 8;
        cpa16(sb + (half ? SQL : SQH) + r * 80 + ch * 16, src);
    }
    for (int t = 0; t < 2; t++) {
        const int j0 = t * 64;
        for (int i = tid; i < 512; i += 256) {
            int half = i >> 8, r = (i >> 2) & 63, ch = i & 3;
            const __nv_bfloat16* src = (half ? Kl : Kh) + ((size_t)b * N_ + j0 + r) * CQK_ + ch * 8;
            cpa16(sb + SKB + t * 10240 + half * 5120 + r * 80 + ch * 16, src);
        }
        for (int i = tid; i < 2048; i += 256) {
            int r = i >> 3, ch = i & 7;
            const __nv_bfloat16* src = Vh + ((size_t)b * C_ + r) * N_ + j0 + ch * 8;
            cpa16(sb + SVB + t * 36864 + r * 144 + ch * 16, src);
        }
        CPA_COMMIT();
    }
    CPA_WAIT(0);
    __syncthreads();   // last common barrier; roles diverge below

    float* sinv = (float*)(smem + S_INV);
    const int qg = q0 + qw + (lane >> 2);
    const size_t rbase0 = ((size_t)b * N_ + qg) * C_;
    const size_t rbase1 = ((size_t)b * N_ + qg + 8) * C_;

    if (w < 4) {
        // ========================= PRODUCER =========================
        uint32_t qa[2][2][4];
#pragma unroll
        for (int hl = 0; hl < 2; hl++)
#pragma unroll
            for (int kc = 0; kc < 2; kc++) {
                uint32_t addr = sb + (hl ? SQL : SQH)
                              + (uint32_t)(qw + (lane & 15)) * 80
                              + (uint32_t)(kc * 16 + (lane >> 4) * 8) * 2;
                ldsm4(addr, qa[hl][kc]);
            }
        BAR_SYNC(5, 128);   // all producers done reading Q region before P writes

        float oacc[13][4];
#pragma unroll
        for (int i = 0; i < 13; i++)
#pragma unroll
            for (int j = 0; j < 4; j++) oacc[i][j] = 0.f;
        float rsum0 = 0.f, rsum1 = 0.f;

        char* ph_dst = smem + SP_HI + (w & 3) * 2048 + lane * 16;
        char* pl_dst = smem + SP_LO + (w & 3) * 2048 + lane * 16;

        for (int kt = 0; kt < 64; kt++) {
            const int bi = kt & 1;
            const uint32_t kh_b = sb + SKB + bi * 10240, kl_b = kh_b + 5120;
            const uint32_t vh_b = sb + SVB + bi * 36864;

            // S = QK^T (3-term)
            float sacc[8][4];
#pragma unroll
            for (int i = 0; i < 8; i++)
#pragma unroll
                for (int j = 0; j < 4; j++) sacc[i][j] = 0.f;
#pragma unroll
            for (int kc = 0; kc < 2; kc++)
#pragma unroll
                for (int nbp = 0; nbp < 4; nbp++) {
                    uint32_t off = (uint32_t)((nbp * 2 + ((lane >> 4) & 1)) * 8 + (lane & 7)) * 80
                                 + (uint32_t)(kc * 16 + ((lane >> 3) & 1) * 8) * 2;
                    uint32_t bh[4], bl[4];
                    ldsm4(kh_b + off, bh);
                    ldsm4(kl_b + off, bl);
                    mma16816(sacc[2*nbp],   qa[0][kc], bh[0], bh[1]);
                    mma16816(sacc[2*nbp+1], qa[0][kc], bh[2], bh[3]);
                    mma16816(sacc[2*nbp],   qa[1][kc], bh[0], bh[1]);
                    mma16816(sacc[2*nbp+1], qa[1][kc], bh[2], bh[3]);
                    mma16816(sacc[2*nbp],   qa[0][kc], bl[0], bl[1]);
                    mma16816(sacc[2*nbp+1], qa[0][kc], bl[2], bl[3]);
                }

            // P = exp(S)
            uint32_t pah[4][4], pal[4][4];
#pragma unroll
            for (int nb = 0; nb < 8; nb++) {
                float e0 = __expf(sacc[nb][0]);
                float e1 = __expf(sacc[nb][1]);
                float e2 = __expf(sacc[nb][2]);
                float e3 = __expf(sacc[nb][3]);
                rsum0 += e0 + e1;
                rsum1 += e2 + e3;
                int kj = nb >> 1, o = (nb & 1) * 2;
                uint32_t h01 = pack_bf16x2(e0, e1);
                uint32_t h23 = pack_bf16x2(e2, e3);
                pah[kj][o]     = h01;
                pah[kj][o + 1] = h23;
                pal[kj][o]     = pack_bf16x2(e0 - lo_bf16_f(h01), e1 - hi_bf16_f(h01));
                pal[kj][o + 1] = pack_bf16x2(e2 - lo_bf16_f(h23), e3 - hi_bf16_f(h23));
            }

            if (kt > 0) BAR_SYNC(2, 256);   // P buffer free
#pragma unroll
            for (int kj = 0; kj < 4; kj++) {
                *(uint4*)(ph_dst + kj * 512) = make_uint4(pah[kj][0], pah[kj][1], pah[kj][2], pah[kj][3]);
                *(uint4*)(pl_dst + kj * 512) = make_uint4(pal[kj][0], pal[kj][1], pal[kj][2], pal[kj][3]);
            }
            BAR_ARRIVE(1, 256);             // P(kt) ready

            if (kt > 0) BAR_SYNC(3, 256);   // V(kt) ready (kt=0 from prologue)

            // PV channels 0..103
#pragma unroll
            for (int cb = 0; cb < 13; cb++) {
                uint32_t rowoff = (uint32_t)(cb * 8 + (lane & 7)) * 144;
                uint32_t vfh[8];
#pragma unroll
                for (int kjp = 0; kjp < 2; kjp++) {
                    uint32_t off = rowoff + (uint32_t)(kjp * 32 + (lane >> 3) * 8) * 2;
                    ldsm4(vh_b + off, &vfh[4 * kjp]);
                }
#pragma unroll
                for (int kj = 0; kj < 4; kj++) {
                    int ix = (kj >> 1) * 4 + (kj & 1) * 2;
                    mma16816(oacc[cb], pah[kj], vfh[ix], vfh[ix + 1]);
                    mma16816(oacc[cb], pal[kj], vfh[ix], vfh[ix + 1]);
                }
            }
            BAR_ARRIVE(4, 256);             // done with V(kt)

            // refill K(kt+2)
            if (kt + 2 < 64) {
                const int j0 = (kt + 2) * 64;
                const uint32_t kd = sb + SKB + bi * 10240;
                for (int i = tid; i < 512; i += 128) {
                    int half = i >> 8, r = (i >> 2) & 63, ch = i & 3;
                    const __nv_bfloat16* src = (half ? Kl : Kh) + ((size_t)b * N_ + j0 + r) * CQK_ + ch * 8;
                    cpa16(kd + half * 5120 + r * 80 + ch * 16, src);
                }
            }
            CPA_COMMIT();
            CPA_WAIT(1);                    // K(kt+1) landed
            BAR_SYNC(5, 128);               // producer-group visibility
        }

        // row sums
        rsum0 += __shfl_xor_sync(0xffffffffu, rsum0, 1);
        rsum0 += __shfl_xor_sync(0xffffffffu, rsum0, 2);
        rsum1 += __shfl_xor_sync(0xffffffffu, rsum1, 1);
        rsum1 += __shfl_xor_sync(0xffffffffu, rsum1, 2);
        if ((lane & 3) == 0) {
            sinv[qw + (lane >> 2)]     = rsum0;
            sinv[qw + 8 + (lane >> 2)] = rsum1;
        }
        __syncwarp();
        BAR_ARRIVE(7, 256);                 // sinv ready for consumers

        const float inv0 = 1.f / sinv[qw + (lane >> 2)];
        const float inv1 = 1.f / sinv[qw + 8 + (lane >> 2)];
#pragma unroll
        for (int cb = 0; cb < 13; cb++) {
            int c = cb * 8 + (lane & 3) * 2;
            float v0 = oacc[cb][0] * inv0, v1 = oacc[cb][1] * inv0;
            float v2 = oacc[cb][2] * inv1, v3 = oacc[cb][3] * inv1;
            uint32_t h01 = pack_bf16x2(v0, v1);
            uint32_t l01 = pack_bf16x2(v0 - lo_bf16_f(h01), v1 - hi_bf16_f(h01));
            uint32_t h23 = pack_bf16x2(v2, v3);
            uint32_t l23 = pack_bf16x2(v2 - lo_bf16_f(h23), v3 - hi_bf16_f(h23));
            *(uint32_t*)&Oh[rbase0 + c] = h01;
            *(uint32_t*)&Ol[rbase0 + c] = l01;
            *(uint32_t*)&Oh[rbase1 + c] = h23;
            *(uint32_t*)&Ol[rbase1 + c] = l23;
        }
    } else {
        // ========================= CONSUMER =========================
        float oacc[19][4];
#pragma unroll
        for (int i = 0; i < 19; i++)
#pragma unroll
            for (int j = 0; j < 4; j++) oacc[i][j] = 0.f;

        const char* ph_src = smem + SP_HI + (w & 3) * 2048 + lane * 16;
        const char* pl_src = smem + SP_LO + (w & 3) * 2048 + lane * 16;
        const int ctid = tid - 128;   // 0..127

        for (int kt = 0; kt < 64; kt++) {
            const int bi = kt & 1;
            const uint32_t vh_b = sb + SVB + bi * 36864;

            BAR_SYNC(1, 256);               // P(kt) ready
            uint32_t pah[4][4], pal[4][4];
#pragma unroll
            for (int kj = 0; kj < 4; kj++) {
                uint4 h4 = *(const uint4*)(ph_src + kj * 512);
                uint4 l4 = *(const uint4*)(pl_src + kj * 512);
                pah[kj][0] = h4.x; pah[kj][1] = h4.y; pah[kj][2] = h4.z; pah[kj][3] = h4.w;
                pal[kj][0] = l4.x; pal[kj][1] = l4.y; pal[kj][2] = l4.z; pal[kj][3] = l4.w;
            }
            if (kt + 1 < 64) BAR_ARRIVE(2, 256);   // P buffer free

            // PV channels 104..255
#pragma unroll
            for (int cb = 0; cb < 19; cb++) {
                uint32_t rowoff = (uint32_t)(104 + cb * 8 + (lane & 7)) * 144;
                uint32_t vfh[8];
#pragma unroll
                for (int kjp = 0; kjp < 2; kjp++) {
                    uint32_t off = rowoff + (uint32_t)(kjp * 32 + (lane >> 3) * 8) * 2;
                    ldsm4(vh_b + off, &vfh[4 * kjp]);
                }
#pragma unroll
                for (int kj = 0; kj < 4; kj++) {
                    int ix = (kj >> 1) * 4 + (kj & 1) * 2;
                    mma16816(oacc[cb], pah[kj], vfh[ix], vfh[ix + 1]);
                    mma16816(oacc[cb], pal[kj], vfh[ix], vfh[ix + 1]);
                }
            }

            BAR_SYNC(4, 256);               // producers done with V(kt)
            if (kt + 2 < 64) {
                const int j0 = (kt + 2) * 64;
                const uint32_t vd = sb + SVB + bi * 36864;
                for (int i = ctid; i < 2048; i += 128) {
                    int r = i >> 3, ch = i & 7;
                    const __nv_bfloat16* src = Vh + ((size_t)b * C_ + r) * N_ + j0 + ch * 8;
                    cpa16(vd + r * 144 + ch * 16, src);
                }
            }
            CPA_COMMIT();
            CPA_WAIT(1);                    // V(kt+1) landed
            BAR_SYNC(6, 128);               // consumer-group visibility
            if (kt + 1 < 64) BAR_ARRIVE(3, 256);   // V(kt+1) ready for producers
        }

        BAR_SYNC(7, 256);                   // sinv ready
        const float inv0 = 1.f / sinv[qw + (lane >> 2)];
        const float inv1 = 1.f / sinv[qw + 8 + (lane >> 2)];
#pragma unroll
        for (int cb = 0; cb < 19; cb++) {
            int c = 104 + cb * 8 + (lane & 3) * 2;
            float v0 = oacc[cb][0] * inv0, v1 = oacc[cb][1] * inv0;
            float v2 = oacc[cb][2] * inv1, v3 = oacc[cb][3] * inv1;
            uint32_t h01 = pack_bf16x2(v0, v1);
            uint32_t l01 = pack_bf16x2(v0 - lo_bf16_f(h01), v1 - hi_bf16_f(h01));
            uint32_t h23 = pack_bf16x2(v2, v3);
            uint32_t l23 = pack_bf16x2(v2 - lo_bf16_f(h23), v3 - hi_bf16_f(h23));
            *(uint32_t*)&Oh[rbase0 + c] = h01;
            *(uint32_t*)&Ol[rbase0 + c] = l01;
            *(uint32_t*)&Oh[rbase1 + c] = h23;
            *(uint32_t*)&Ol[rbase1 + c] = l23;
        }
    }
}

// ---------------- kernel_launch ----------------
extern "C" void kernel_launch(void* const* d_in, const int* in_sizes, int n_in,
                              void* d_out, int out_size)
{
    (void)in_sizes; (void)n_in; (void)out_size;
    const float* x  = (const float*)d_in[0];
    const float* Wq = (const float*)d_in[1];
    const float* bq = (const float*)d_in[2];
    const float* Wk = (const float*)d_in[3];
    const float* bk = (const float*)d_in[4];
    const float* Wv = (const float*)d_in[5];
    const float* bv = (const float*)d_in[6];
    const float* Wf = (const float*)d_in[7];
    const float* bf = (const float*)d_in[8];
    float* out = (float*)d_out;

    __nv_bfloat16 *qh, *ql, *kh, *kl, *vh, *xth, *xtl, *oth, *otl;
    __nv_bfloat16 *wvh, *wvl, *wfh, *wfl, *wqkh, *wqkl;
    cudaGetSymbolAddress((void**)&qh,   g_qh);
    cudaGetSymbolAddress((void**)&ql,   g_ql);
    cudaGetSymbolAddress((void**)&kh,   g_kh);
    cudaGetSymbolAddress((void**)&kl,   g_kl);
    cudaGetSymbolAddress((void**)&vh,   g_vh);
    cudaGetSymbolAddress((void**)&xth,  g_xth);
    cudaGetSymbolAddress((void**)&xtl,  g_xtl);
    cudaGetSymbolAddress((void**)&oth,  g_oth);
    cudaGetSymbolAddress((void**)&otl,  g_otl);
    cudaGetSymbolAddress((void**)&wvh,  g_wvh);
    cudaGetSymbolAddress((void**)&wvl,  g_wvl);
    cudaGetSymbolAddress((void**)&wfh,  g_wfh);
    cudaGetSymbolAddress((void**)&wfl,  g_wfl);
    cudaGetSymbolAddress((void**)&wqkh, g_wqkh);
    cudaGetSymbolAddress((void**)&wqkl, g_wqkl);

    cudaFuncSetAttribute(flash_mma_kernel,
                         cudaFuncAttributeMaxDynamicSharedMemorySize, FL_SMEM);
    cudaFuncSetAttribute(proj_mma_kernel<0>,
                         cudaFuncAttributeMaxDynamicSharedMemorySize, PM_SMEM);
    cudaFuncSetAttribute(proj_mma_kernel<1>,
                         cudaFuncAttributeMaxDynamicSharedMemorySize, PM_SMEM);
    cudaFuncSetAttribute(proj_qk_mma_kernel,
                         cudaFuncAttributeMaxDynamicSharedMemorySize, PM_SMEM);

    // operand prep
    wsplit_kernel<<<C_ * C_ / 256, 256>>>(Wv, wvh, wvl);
    wsplit_kernel<<<C_ * C_ / 256, 256>>>(Wf, wfh, wfl);
    wqksplit_kernel<<<64 * C_ / 256, 256>>>(Wq, Wk, wqkh, wqkl);
    xsplit_kernel<<<dim3(N_ / 64, C_ / 64, B_), 256>>>(x, xth, xtl);

    // Q+K projection on tensor cores -> bf16 hi/lo [b][N][32]
    proj_qk_mma_kernel<<<dim3(1, N_ / 128, B_), 256, PM_SMEM>>>(
        xth, xtl, wqkh, wqkl, bq, bk, qh, ql, kh, kl);

    // V projection on tensor cores -> bf16 [b][C][N]
    proj_mma_kernel<0><<<dim3(N_ / 64, 2, B_), 256, PM_SMEM>>>(wvh, wvl, xth, xtl, bv, vh);

    // attention (pipelined producer/consumer) -> O bf16 hi/lo [b][N][C]
    flash_mma_kernel<<<dim3(N_ / 64, B_), 256, FL_SMEM>>>(qh, ql, kh, kl, vh, oth, otl);

    // final projection on tensor cores -> fp32 out
    proj_mma_kernel<1><<<dim3(N_ / 64, 2, B_), 256, PM_SMEM>>>(wfh, wfl, oth, otl, bf, out);
}

// round 13
// speedup vs baseline: 1.5311x; 1.0095x over previous
#include <cuda_runtime.h>
#include <cuda_bf16.h>
#include <cstdint>

static constexpr int B_   = 8;
static constexpr int C_   = 256;
static constexpr int CQK_ = 32;
static constexpr int N_   = 4096;

// Scratch
__device__ __align__(256) __nv_bfloat16 g_qh[(size_t)B_ * N_ * CQK_];
__device__ __align__(256) __nv_bfloat16 g_ql[(size_t)B_ * N_ * CQK_];
__device__ __align__(256) __nv_bfloat16 g_kh[(size_t)B_ * N_ * CQK_];
__device__ __align__(256) __nv_bfloat16 g_kl[(size_t)B_ * N_ * CQK_];
__device__ __align__(256) __nv_bfloat16 g_vh[(size_t)B_ * C_ * N_];
__device__ __align__(256) __nv_bfloat16 g_xth[(size_t)B_ * N_ * C_];
__device__ __align__(256) __nv_bfloat16 g_xtl[(size_t)B_ * N_ * C_];
__device__ __align__(256) __nv_bfloat16 g_oth[(size_t)B_ * N_ * C_];
__device__ __align__(256) __nv_bfloat16 g_otl[(size_t)B_ * N_ * C_];
__device__ __align__(256) __nv_bfloat16 g_wvh[C_ * C_], g_wvl[C_ * C_];
__device__ __align__(256) __nv_bfloat16 g_wfh[C_ * C_], g_wfl[C_ * C_];
__device__ __align__(256) __nv_bfloat16 g_wqkh[64 * C_], g_wqkl[64 * C_];

// ---------------- helpers ----------------
__device__ __forceinline__ uint32_t smem_u32(const void* p) {
    uint32_t a;
    asm("{ .reg .u64 t; cvta.to.shared.u64 t, %1; cvt.u32.u64 %0, t; }" : "=r"(a) : "l"(p));
    return a;
}
__device__ __forceinline__ void cpa16(uint32_t dst, const void* src) {
    asm volatile("cp.async.cg.shared.global [%0], [%1], 16;" :: "r"(dst), "l"(src) : "memory");
}
#define CPA_COMMIT() asm volatile("cp.async.commit_group;" ::: "memory")
#define CPA_WAIT(n)  asm volatile("cp.async.wait_group %0;" :: "n"(n) : "memory")
#define BAR_SYNC(id, cnt)   asm volatile("bar.sync %0, %1;"   :: "r"(id), "r"(cnt) : "memory")
#define BAR_ARRIVE(id, cnt) asm volatile("bar.arrive %0, %1;" :: "r"(id), "r"(cnt) : "memory")

__device__ __forceinline__ void ldsm4(uint32_t addr, uint32_t* r) {
    asm volatile("ldmatrix.sync.aligned.m8n8.x4.shared.b16 {%0,%1,%2,%3}, [%4];"
                 : "=r"(r[0]), "=r"(r[1]), "=r"(r[2]), "=r"(r[3]) : "r"(addr));
}
__device__ __forceinline__ void mma16816(float* d, const uint32_t* a, uint32_t b0, uint32_t b1) {
    asm volatile("mma.sync.aligned.m16n8k16.row.col.f32.bf16.bf16.f32 "
                 "{%0,%1,%2,%3}, {%4,%5,%6,%7}, {%8,%9}, {%0,%1,%2,%3};"
                 : "+f"(d[0]), "+f"(d[1]), "+f"(d[2]), "+f"(d[3])
                 : "r"(a[0]), "r"(a[1]), "r"(a[2]), "r"(a[3]), "r"(b0), "r"(b1));
}
__device__ __forceinline__ uint32_t pack_bf16x2(float e0, float e1) {
    uint32_t r; asm("cvt.rn.bf16x2.f32 %0, %1, %2;" : "=r"(r) : "f"(e1), "f"(e0)); return r;
}
__device__ __forceinline__ float lo_bf16_f(uint32_t u) { return __uint_as_float(u << 16); }
__device__ __forceinline__ float hi_bf16_f(uint32_t u) { return __uint_as_float(u & 0xffff0000u); }
__device__ __forceinline__ void bf16_split(float v, __nv_bfloat16& h, __nv_bfloat16& l) {
    h = __float2bfloat16(v);
    l = __float2bfloat16(v - __bfloat162float(h));
}

// ---------------- W split ----------------
__global__ __launch_bounds__(256)
void wsplit_kernel(const float* __restrict__ W,
                   __nv_bfloat16* __restrict__ Wh, __nv_bfloat16* __restrict__ Wl)
{
    int i = blockIdx.x * 256 + threadIdx.x;
    float v = W[i];
    __nv_bfloat16 h, l; bf16_split(v, h, l);
    Wh[i] = h; Wl[i] = l;
}

// ---------------- Wq||Wk stack + split ----------------
__global__ __launch_bounds__(256)
void wqksplit_kernel(const float* __restrict__ Wq, const float* __restrict__ Wk,
                     __nv_bfloat16* __restrict__ Wh, __nv_bfloat16* __restrict__ Wl)
{
    int i = blockIdx.x * 256 + threadIdx.x;
    int row = i >> 8, col = i & 255;
    float v = (row < 32) ? Wq[(size_t)row * 256 + col] : Wk[(size_t)(row - 32) * 256 + col];
    __nv_bfloat16 h, l; bf16_split(v, h, l);
    Wh[i] = h; Wl[i] = l;
}

// ---------------- x split-transpose ----------------
__global__ __launch_bounds__(256)
void xsplit_kernel(const float* __restrict__ X,
                   __nv_bfloat16* __restrict__ Yh, __nv_bfloat16* __restrict__ Yl)
{
    __shared__ float t[64][65];
    const int b  = blockIdx.z;
    const int c0 = blockIdx.y * 64;
    const int n0 = blockIdx.x * 64;
    const int tid = threadIdx.x;
    for (int i = tid; i < 4096; i += 256) {
        int c = i >> 6, n = i & 63;
        t[c][n] = X[(size_t)b * C_ * N_ + (size_t)(c0 + c) * N_ + n0 + n];
    }
    __syncthreads();
    for (int i = tid; i < 2048; i += 256) {
        int n = i >> 5, c2 = (i & 31) * 2;
        float v0 = t[c2][n], v1 = t[c2 + 1][n];
        __nv_bfloat16 h0, l0, h1, l1;
        bf16_split(v0, h0, l0);
        bf16_split(v1, h1, l1);
        __nv_bfloat162 hh, ll;
        hh.x = h0; hh.y = h1; ll.x = l0; ll.y = l1;
        size_t o = ((size_t)b * N_ + n0 + n) * C_ + c0 + c2;
        *(__nv_bfloat162*)&Yh[o] = hh;
        *(__nv_bfloat162*)&Yl[o] = ll;
    }
}

// ---------------- tensor-core projection GEMM (3-term bf16 split) -------------
static constexpr int PM_SW   = 0;
static constexpr int PM_SX   = 73728;
static constexpr int PM_SMEM = 110592;

template <int OUT_FP32>
__global__ __launch_bounds__(256, 2)
void proj_mma_kernel(const __nv_bfloat16* __restrict__ Wh, const __nv_bfloat16* __restrict__ Wl,
                     const __nv_bfloat16* __restrict__ Xh, const __nv_bfloat16* __restrict__ Xl,
                     const float* __restrict__ bias, void* __restrict__ Yout)
{
    extern __shared__ char smem[];
    const uint32_t sb = smem_u32(smem);
    const int tid = threadIdx.x, lane = tid & 31, w = tid >> 5;
    const int b  = blockIdx.z;
    const int m0 = blockIdx.y * 128;
    const int n0 = blockIdx.x * 64;
    const int mw = w * 16;

    auto load_wx = [&](int ks, int bi) {
        const int k0 = ks * 64;
        for (int i = tid; i < 2048; i += 256) {
            int half = i >> 10, r = (i >> 3) & 127, ch = i & 7;
            const __nv_bfloat16* src = (half ? Wl : Wh) + (size_t)(m0 + r) * 256 + k0 + ch * 8;
            cpa16(sb + PM_SW + bi * 36864 + half * 18432 + r * 144 + ch * 16, src);
        }
        for (int i = tid; i < 1024; i += 256) {
            int half = i >> 9, r = (i >> 3) & 63, ch = i & 7;
            const __nv_bfloat16* src = (half ? Xl : Xh) + ((size_t)b * N_ + n0 + r) * 256 + k0 + ch * 8;
            cpa16(sb + PM_SX + bi * 18432 + half * 9216 + r * 144 + ch * 16, src);
        }
    };

    load_wx(0, 0); CPA_COMMIT();
    load_wx(1, 1); CPA_COMMIT();

    float oacc[8][4];
#pragma unroll
    for (int i = 0; i < 8; i++)
#pragma unroll
        for (int j = 0; j < 4; j++) oacc[i][j] = 0.f;

#pragma unroll
    for (int ks = 0; ks < 4; ks++) {
        const int bi = ks & 1;
        if (ks < 2) { CPA_WAIT(1); } else { CPA_WAIT(0); }
        __syncthreads();

        const uint32_t wb_hi = sb + PM_SW + bi * 36864;
        const uint32_t xb_hi = sb + PM_SX + bi * 18432;

        uint32_t ah[4][4], al[4][4];
#pragma unroll
        for (int kc = 0; kc < 4; kc++) {
            uint32_t addr = wb_hi + (uint32_t)(mw + (lane & 15)) * 144
                          + (uint32_t)(kc * 16 + (lane >> 4) * 8) * 2;
            ldsm4(addr, ah[kc]);
            ldsm4(addr + 18432, al[kc]);
        }

#pragma unroll
        for (int nb = 0; nb < 8; nb++) {
            uint32_t rowoff = xb_hi + (uint32_t)(nb * 8 + (lane & 7)) * 144;
            uint32_t bh[8], bl[8];
#pragma unroll
            for (int kk = 0; kk < 2; kk++) {
                uint32_t off = (uint32_t)(kk * 32 + (lane >> 3) * 8) * 2;
                ldsm4(rowoff + off, &bh[4 * kk]);
                ldsm4(rowoff + off + 9216, &bl[4 * kk]);
            }
#pragma unroll
            for (int kc = 0; kc < 4; kc++) {
                int ix = (kc >> 1) * 4 + (kc & 1) * 2;
                mma16816(oacc[nb], ah[kc], bh[ix], bh[ix + 1]);
                mma16816(oacc[nb], al[kc], bh[ix], bh[ix + 1]);
                mma16816(oacc[nb], ah[kc], bl[ix], bl[ix + 1]);
            }
        }

        __syncthreads();
        if (ks + 2 < 4) { load_wx(ks + 2, bi); CPA_COMMIT(); }
    }

    const int r0 = m0 + mw + (lane >> 2);
    const float b0f = bias[r0], b1f = bias[r0 + 8];
#pragma unroll
    for (int nb = 0; nb < 8; nb++) {
        int col = n0 + nb * 8 + (lane & 3) * 2;
        float v0 = oacc[nb][0] + b0f, v1 = oacc[nb][1] + b0f;
        float v2 = oacc[nb][2] + b1f, v3 = oacc[nb][3] + b1f;
        if (OUT_FP32) {
            float* Yf = (float*)Yout + (size_t)b * C_ * N_;
            *(float2*)&Yf[(size_t)r0 * N_ + col]       = make_float2(v0, v1);
            *(float2*)&Yf[(size_t)(r0 + 8) * N_ + col] = make_float2(v2, v3);
        } else {
            __nv_bfloat16* Yb = (__nv_bfloat16*)Yout + (size_t)b * C_ * N_;
            *(uint32_t*)&Yb[(size_t)r0 * N_ + col]       = pack_bf16x2(v0, v1);
            *(uint32_t*)&Yb[(size_t)(r0 + 8) * N_ + col] = pack_bf16x2(v2, v3);
        }
    }
}

// ---------------- Q/K projection on tensor cores ------------------------------
__global__ __launch_bounds__(256, 2)
void proj_qk_mma_kernel(const __nv_bfloat16* __restrict__ Xh, const __nv_bfloat16* __restrict__ Xl,
                        const __nv_bfloat16* __restrict__ Wh, const __nv_bfloat16* __restrict__ Wl,
                        const float* __restrict__ bq, const float* __restrict__ bk,
                        __nv_bfloat16* __restrict__ Qh, __nv_bfloat16* __restrict__ Ql,
                        __nv_bfloat16* __restrict__ Kh, __nv_bfloat16* __restrict__ Kl)
{
    extern __shared__ char smem[];
    const uint32_t sb = smem_u32(smem);
    const int tid = threadIdx.x, lane = tid & 31, w = tid >> 5;
    const int b  = blockIdx.z;
    const int m0 = blockIdx.y * 128;
    const int mw = w * 16;

    auto load_ab = [&](int ks, int bi) {
        const int k0 = ks * 64;
        for (int i = tid; i < 2048; i += 256) {
            int half = i >> 10, r = (i >> 3) & 127, ch = i & 7;
            const __nv_bfloat16* src = (half ? Xl : Xh) + ((size_t)b * N_ + m0 + r) * 256 + k0 + ch * 8;
            cpa16(sb + PM_SW + bi * 36864 + half * 18432 + r * 144 + ch * 16, src);
        }
        for (int i = tid; i < 1024; i += 256) {
            int half = i >> 9, r = (i >> 3) & 63, ch = i & 7;
            const __nv_bfloat16* src = (half ? Wl : Wh) + (size_t)r * 256 + k0 + ch * 8;
            cpa16(sb + PM_SX + bi * 18432 + half * 9216 + r * 144 + ch * 16, src);
        }
    };

    load_ab(0, 0); CPA_COMMIT();
    load_ab(1, 1); CPA_COMMIT();

    float oacc[8][4];
#pragma unroll
    for (int i = 0; i < 8; i++)
#pragma unroll
        for (int j = 0; j < 4; j++) oacc[i][j] = 0.f;

#pragma unroll
    for (int ks = 0; ks < 4; ks++) {
        const int bi = ks & 1;
        if (ks < 2) { CPA_WAIT(1); } else { CPA_WAIT(0); }
        __syncthreads();

        const uint32_t ab_hi = sb + PM_SW + bi * 36864;
        const uint32_t bb_hi = sb + PM_SX + bi * 18432;

        uint32_t ah[4][4], al[4][4];
#pragma unroll
        for (int kc = 0; kc < 4; kc++) {
            uint32_t addr = ab_hi + (uint32_t)(mw + (lane & 15)) * 144
                          + (uint32_t)(kc * 16 + (lane >> 4) * 8) * 2;
            ldsm4(addr, ah[kc]);
            ldsm4(addr + 18432, al[kc]);
        }

#pragma unroll
        for (int nb = 0; nb < 8; nb++) {
            uint32_t rowoff = bb_hi + (uint32_t)(nb * 8 + (lane & 7)) * 144;
            uint32_t bh[8], bl[8];
#pragma unroll
            for (int kk = 0; kk < 2; kk++) {
                uint32_t off = (uint32_t)(kk * 32 + (lane >> 3) * 8) * 2;
                ldsm4(rowoff + off, &bh[4 * kk]);
                ldsm4(rowoff + off + 9216, &bl[4 * kk]);
            }
#pragma unroll
            for (int kc = 0; kc < 4; kc++) {
                int ix = (kc >> 1) * 4 + (kc & 1) * 2;
                mma16816(oacc[nb], ah[kc], bh[ix], bh[ix + 1]);
                mma16816(oacc[nb], al[kc], bh[ix], bh[ix + 1]);
                mma16816(oacc[nb], ah[kc], bl[ix], bl[ix + 1]);
            }
        }

        __syncthreads();
        if (ks + 2 < 4) { load_ab(ks + 2, bi); CPA_COMMIT(); }
    }

    const int r0 = m0 + mw + (lane >> 2);
#pragma unroll
    for (int nb = 0; nb < 8; nb++) {
        int c = nb * 8 + (lane & 3) * 2;
        const bool isQ = (c < 32);
        const int cc = isQ ? c : c - 32;
        const float bb0 = isQ ? bq[cc] : bk[cc];
        const float bb1 = isQ ? bq[cc + 1] : bk[cc + 1];
        float v0 = oacc[nb][0] + bb0, v1 = oacc[nb][1] + bb1;
        float v2 = oacc[nb][2] + bb0, v3 = oacc[nb][3] + bb1;
        uint32_t h01 = pack_bf16x2(v0, v1);
        uint32_t l01 = pack_bf16x2(v0 - lo_bf16_f(h01), v1 - hi_bf16_f(h01));
        uint32_t h23 = pack_bf16x2(v2, v3);
        uint32_t l23 = pack_bf16x2(v2 - lo_bf16_f(h23), v3 - hi_bf16_f(h23));
        __nv_bfloat16* dh = isQ ? Qh : Kh;
        __nv_bfloat16* dl = isQ ? Ql : Kl;
        size_t o0 = ((size_t)b * N_ + r0) * CQK_ + cc;
        size_t o1 = ((size_t)b * N_ + r0 + 8) * CQK_ + cc;
        *(uint32_t*)&dh[o0] = h01;
        *(uint32_t*)&dl[o0] = l01;
        *(uint32_t*)&dh[o1] = h23;
        *(uint32_t*)&dl[o1] = l23;
    }
}

// ---------------- flash attention: pipelined producer/consumer ----------------
// Same barrier structure as R12; PV loops restructured for ILP=2 (paired
// channel blocks, interleaved MMA chains; per-accumulator order unchanged).
static constexpr int SP_HI = 0;
static constexpr int SP_LO = 8192;
static constexpr int S_INV = 16384;
static constexpr int SQH   = 0;
static constexpr int SQL   = 5120;
static constexpr int SKB   = 16640;
static constexpr int SVB   = 37120;
static constexpr int FL_SMEM = 110848;

// paired PV: two independent accumulator chains in flight
__device__ __forceinline__ void pv_pair(float* oa, float* ob,
                                        const uint32_t pah[4][4], const uint32_t pal[4][4],
                                        uint32_t vh_b, int c0, int c1, int lane)
{
    uint32_t vfa[8], vfb[8];
    uint32_t ra = (uint32_t)(c0 + (lane & 7)) * 144;
    uint32_t rb = (uint32_t)(c1 + (lane & 7)) * 144;
#pragma unroll
    for (int kjp = 0; kjp < 2; kjp++) {
        uint32_t off = (uint32_t)(kjp * 32 + (lane >> 3) * 8) * 2;
        ldsm4(vh_b + ra + off, &vfa[4 * kjp]);
        ldsm4(vh_b + rb + off, &vfb[4 * kjp]);
    }
#pragma unroll
    for (int kj = 0; kj < 4; kj++) {
        int ix = (kj >> 1) * 4 + (kj & 1) * 2;
        mma16816(oa, pah[kj], vfa[ix], vfa[ix + 1]);
        mma16816(ob, pah[kj], vfb[ix], vfb[ix + 1]);
        mma16816(oa, pal[kj], vfa[ix], vfa[ix + 1]);
        mma16816(ob, pal[kj], vfb[ix], vfb[ix + 1]);
    }
}
__device__ __forceinline__ void pv_one(float* oa,
                                       const uint32_t pah[4][4], const uint32_t pal[4][4],
                                       uint32_t vh_b, int c0, int lane)
{
    uint32_t vfa[8];
    uint32_t ra = (uint32_t)(c0 + (lane & 7)) * 144;
#pragma unroll
    for (int kjp = 0; kjp < 2; kjp++) {
        uint32_t off = (uint32_t)(kjp * 32 + (lane >> 3) * 8) * 2;
        ldsm4(vh_b + ra + off, &vfa[4 * kjp]);
    }
#pragma unroll
    for (int kj = 0; kj < 4; kj++) {
        int ix = (kj >> 1) * 4 + (kj & 1) * 2;
        mma16816(oa, pah[kj], vfa[ix], vfa[ix + 1]);
        mma16816(oa, pal[kj], vfa[ix], vfa[ix + 1]);
    }
}

__global__ __launch_bounds__(256, 2)
void flash_mma_kernel(const __nv_bfloat16* __restrict__ Qh, const __nv_bfloat16* __restrict__ Ql,
                      const __nv_bfloat16* __restrict__ Kh, const __nv_bfloat16* __restrict__ Kl,
                      const __nv_bfloat16* __restrict__ Vh,
                      __nv_bfloat16* __restrict__ Oh, __nv_bfloat16* __restrict__ Ol)
{
    extern __shared__ char smem[];
    const uint32_t sb = smem_u32(smem);
    const int tid = threadIdx.x, lane = tid & 31, w = tid >> 5;
    const int qw = (w & 3) * 16;
    const int b = blockIdx.y, q0 = blockIdx.x * 64;

    // ---- prologue (all 256 threads): Q, K0, V0 | K1, V1 ----
    for (int i = tid; i < 512; i += 256) {
        int half = i >> 8, r = (i >> 2) & 63, ch = i & 3;
        const __nv_bfloat16* src = (half ? Ql : Qh) + ((size_t)b * N_ + q0 + r) * CQK_ + ch * 8;
        cpa16(sb + (half ? SQL : SQH) + r * 80 + ch * 16, src);
    }
    for (int t = 0; t < 2; t++) {
        const int j0 = t * 64;
        for (int i = tid; i < 512; i += 256) {
            int half = i >> 8, r = (i >> 2) & 63, ch = i & 3;
            const __nv_bfloat16* src = (half ? Kl : Kh) + ((size_t)b * N_ + j0 + r) * CQK_ + ch * 8;
            cpa16(sb + SKB + t * 10240 + half * 5120 + r * 80 + ch * 16, src);
        }
        for (int i = tid; i < 2048; i += 256) {
            int r = i >> 3, ch = i & 7;
            const __nv_bfloat16* src = Vh + ((size_t)b * C_ + r) * N_ + j0 + ch * 8;
            cpa16(sb + SVB + t * 36864 + r * 144 + ch * 16, src);
        }
        CPA_COMMIT();
    }
    CPA_WAIT(0);
    __syncthreads();

    float* sinv = (float*)(smem + S_INV);
    const int qg = q0 + qw + (lane >> 2);
    const size_t rbase0 = ((size_t)b * N_ + qg) * C_;
    const size_t rbase1 = ((size_t)b * N_ + qg + 8) * C_;

    if (w < 4) {
        // ========================= PRODUCER =========================
        uint32_t qa[2][2][4];
#pragma unroll
        for (int hl = 0; hl < 2; hl++)
#pragma unroll
            for (int kc = 0; kc < 2; kc++) {
                uint32_t addr = sb + (hl ? SQL : SQH)
                              + (uint32_t)(qw + (lane & 15)) * 80
                              + (uint32_t)(kc * 16 + (lane >> 4) * 8) * 2;
                ldsm4(addr, qa[hl][kc]);
            }
        BAR_SYNC(5, 128);

        float oacc[13][4];
#pragma unroll
        for (int i = 0; i < 13; i++)
#pragma unroll
            for (int j = 0; j < 4; j++) oacc[i][j] = 0.f;
        float rsum0 = 0.f, rsum1 = 0.f;

        char* ph_dst = smem + SP_HI + (w & 3) * 2048 + lane * 16;
        char* pl_dst = smem + SP_LO + (w & 3) * 2048 + lane * 16;

        for (int kt = 0; kt < 64; kt++) {
            const int bi = kt & 1;
            const uint32_t kh_b = sb + SKB + bi * 10240, kl_b = kh_b + 5120;
            const uint32_t vh_b = sb + SVB + bi * 36864;

            // S = QK^T (3-term)
            float sacc[8][4];
#pragma unroll
            for (int i = 0; i < 8; i++)
#pragma unroll
                for (int j = 0; j < 4; j++) sacc[i][j] = 0.f;
#pragma unroll
            for (int kc = 0; kc < 2; kc++)
#pragma unroll
                for (int nbp = 0; nbp < 4; nbp++) {
                    uint32_t off = (uint32_t)((nbp * 2 + ((lane >> 4) & 1)) * 8 + (lane & 7)) * 80
                                 + (uint32_t)(kc * 16 + ((lane >> 3) & 1) * 8) * 2;
                    uint32_t bh[4], bl[4];
                    ldsm4(kh_b + off, bh);
                    ldsm4(kl_b + off, bl);
                    mma16816(sacc[2*nbp],   qa[0][kc], bh[0], bh[1]);
                    mma16816(sacc[2*nbp+1], qa[0][kc], bh[2], bh[3]);
                    mma16816(sacc[2*nbp],   qa[1][kc], bh[0], bh[1]);
                    mma16816(sacc[2*nbp+1], qa[1][kc], bh[2], bh[3]);
                    mma16816(sacc[2*nbp],   qa[0][kc], bl[0], bl[1]);
                    mma16816(sacc[2*nbp+1], qa[0][kc], bl[2], bl[3]);
                }

            // P = exp(S)
            uint32_t pah[4][4], pal[4][4];
#pragma unroll
            for (int nb = 0; nb < 8; nb++) {
                float e0 = __expf(sacc[nb][0]);
                float e1 = __expf(sacc[nb][1]);
                float e2 = __expf(sacc[nb][2]);
                float e3 = __expf(sacc[nb][3]);
                rsum0 += e0 + e1;
                rsum1 += e2 + e3;
                int kj = nb >> 1, o = (nb & 1) * 2;
                uint32_t h01 = pack_bf16x2(e0, e1);
                uint32_t h23 = pack_bf16x2(e2, e3);
                pah[kj][o]     = h01;
                pah[kj][o + 1] = h23;
                pal[kj][o]     = pack_bf16x2(e0 - lo_bf16_f(h01), e1 - hi_bf16_f(h01));
                pal[kj][o + 1] = pack_bf16x2(e2 - lo_bf16_f(h23), e3 - hi_bf16_f(h23));
            }

            if (kt > 0) BAR_SYNC(2, 256);
#pragma unroll
            for (int kj = 0; kj < 4; kj++) {
                *(uint4*)(ph_dst + kj * 512) = make_uint4(pah[kj][0], pah[kj][1], pah[kj][2], pah[kj][3]);
                *(uint4*)(pl_dst + kj * 512) = make_uint4(pal[kj][0], pal[kj][1], pal[kj][2], pal[kj][3]);
            }
            BAR_ARRIVE(1, 256);

            if (kt > 0) BAR_SYNC(3, 256);

            // PV channels 0..103 : 6 pairs + tail (ILP=2)
#pragma unroll
            for (int cp = 0; cp < 6; cp++)
                pv_pair(oacc[2*cp], oacc[2*cp+1], pah, pal, vh_b,
                        (2*cp) * 8, (2*cp+1) * 8, lane);
            pv_one(oacc[12], pah, pal, vh_b, 96, lane);
            BAR_ARRIVE(4, 256);

            if (kt + 2 < 64) {
                const int j0 = (kt + 2) * 64;
                const uint32_t kd = sb + SKB + bi * 10240;
                for (int i = tid; i < 512; i += 128) {
                    int half = i >> 8, r = (i >> 2) & 63, ch = i & 3;
                    const __nv_bfloat16* src = (half ? Kl : Kh) + ((size_t)b * N_ + j0 + r) * CQK_ + ch * 8;
                    cpa16(kd + half * 5120 + r * 80 + ch * 16, src);
                }
            }
            CPA_COMMIT();
            CPA_WAIT(1);
            BAR_SYNC(5, 128);
        }

        rsum0 += __shfl_xor_sync(0xffffffffu, rsum0, 1);
        rsum0 += __shfl_xor_sync(0xffffffffu, rsum0, 2);
        rsum1 += __shfl_xor_sync(0xffffffffu, rsum1, 1);
        rsum1 += __shfl_xor_sync(0xffffffffu, rsum1, 2);
        if ((lane & 3) == 0) {
            sinv[qw + (lane >> 2)]     = rsum0;
            sinv[qw + 8 + (lane >> 2)] = rsum1;
        }
        __syncwarp();
        BAR_ARRIVE(7, 256);

        const float inv0 = 1.f / sinv[qw + (lane >> 2)];
        const float inv1 = 1.f / sinv[qw + 8 + (lane >> 2)];
#pragma unroll
        for (int cb = 0; cb < 13; cb++) {
            int c = cb * 8 + (lane & 3) * 2;
            float v0 = oacc[cb][0] * inv0, v1 = oacc[cb][1] * inv0;
            float v2 = oacc[cb][2] * inv1, v3 = oacc[cb][3] * inv1;
            uint32_t h01 = pack_bf16x2(v0, v1);
            uint32_t l01 = pack_bf16x2(v0 - lo_bf16_f(h01), v1 - hi_bf16_f(h01));
            uint32_t h23 = pack_bf16x2(v2, v3);
            uint32_t l23 = pack_bf16x2(v2 - lo_bf16_f(h23), v3 - hi_bf16_f(h23));
            *(uint32_t*)&Oh[rbase0 + c] = h01;
            *(uint32_t*)&Ol[rbase0 + c] = l01;
            *(uint32_t*)&Oh[rbase1 + c] = h23;
            *(uint32_t*)&Ol[rbase1 + c] = l23;
        }
    } else {
        // ========================= CONSUMER =========================
        float oacc[19][4];
#pragma unroll
        for (int i = 0; i < 19; i++)
#pragma unroll
            for (int j = 0; j < 4; j++) oacc[i][j] = 0.f;

        const char* ph_src = smem + SP_HI + (w & 3) * 2048 + lane * 16;
        const char* pl_src = smem + SP_LO + (w & 3) * 2048 + lane * 16;
        const int ctid = tid - 128;

        for (int kt = 0; kt < 64; kt++) {
            const int bi = kt & 1;
            const uint32_t vh_b = sb + SVB + bi * 36864;

            BAR_SYNC(1, 256);
            uint32_t pah[4][4], pal[4][4];
#pragma unroll
            for (int kj = 0; kj < 4; kj++) {
                uint4 h4 = *(const uint4*)(ph_src + kj * 512);
                uint4 l4 = *(const uint4*)(pl_src + kj * 512);
                pah[kj][0] = h4.x; pah[kj][1] = h4.y; pah[kj][2] = h4.z; pah[kj][3] = h4.w;
                pal[kj][0] = l4.x; pal[kj][1] = l4.y; pal[kj][2] = l4.z; pal[kj][3] = l4.w;
            }
            if (kt + 1 < 64) BAR_ARRIVE(2, 256);

            // PV channels 104..255 : 9 pairs + tail (ILP=2)
#pragma unroll
            for (int cp = 0; cp < 9; cp++)
                pv_pair(oacc[2*cp], oacc[2*cp+1], pah, pal, vh_b,
                        104 + (2*cp) * 8, 104 + (2*cp+1) * 8, lane);
            pv_one(oacc[18], pah, pal, vh_b, 104 + 144, lane);

            BAR_SYNC(4, 256);
            if (kt + 2 < 64) {
                const int j0 = (kt + 2) * 64;
                const uint32_t vd = sb + SVB + bi * 36864;
                for (int i = ctid; i < 2048; i += 128) {
                    int r = i >> 3, ch = i & 7;
                    const __nv_bfloat16* src = Vh + ((size_t)b * C_ + r) * N_ + j0 + ch * 8;
                    cpa16(vd + r * 144 + ch * 16, src);
                }
            }
            CPA_COMMIT();
            CPA_WAIT(1);
            BAR_SYNC(6, 128);
            if (kt + 1 < 64) BAR_ARRIVE(3, 256);
        }

        BAR_SYNC(7, 256);
        const float inv0 = 1.f / sinv[qw + (lane >> 2)];
        const float inv1 = 1.f / sinv[qw + 8 + (lane >> 2)];
#pragma unroll
        for (int cb = 0; cb < 19; cb++) {
            int c = 104 + cb * 8 + (lane & 3) * 2;
            float v0 = oacc[cb][0] * inv0, v1 = oacc[cb][1] * inv0;
            float v2 = oacc[cb][2] * inv1, v3 = oacc[cb][3] * inv1;
            uint32_t h01 = pack_bf16x2(v0, v1);
            uint32_t l01 = pack_bf16x2(v0 - lo_bf16_f(h01), v1 - hi_bf16_f(h01));
            uint32_t h23 = pack_bf16x2(v2, v3);
            uint32_t l23 = pack_bf16x2(v2 - lo_bf16_f(h23), v3 - hi_bf16_f(h23));
            *(uint32_t*)&Oh[rbase0 + c] = h01;
            *(uint32_t*)&Ol[rbase0 + c] = l01;
            *(uint32_t*)&Oh[rbase1 + c] = h23;
            *(uint32_t*)&Ol[rbase1 + c] = l23;
        }
    }
}

// ---------------- kernel_launch ----------------
extern "C" void kernel_launch(void* const* d_in, const int* in_sizes, int n_in,
                              void* d_out, int out_size)
{
    (void)in_sizes; (void)n_in; (void)out_size;
    const float* x  = (const float*)d_in[0];
    const float* Wq = (const float*)d_in[1];
    const float* bq = (const float*)d_in[2];
    const float* Wk = (const float*)d_in[3];
    const float* bk = (const float*)d_in[4];
    const float* Wv = (const float*)d_in[5];
    const float* bv = (const float*)d_in[6];
    const float* Wf = (const float*)d_in[7];
    const float* bf = (const float*)d_in[8];
    float* out = (float*)d_out;

    __nv_bfloat16 *qh, *ql, *kh, *kl, *vh, *xth, *xtl, *oth, *otl;
    __nv_bfloat16 *wvh, *wvl, *wfh, *wfl, *wqkh, *wqkl;
    cudaGetSymbolAddress((void**)&qh,   g_qh);
    cudaGetSymbolAddress((void**)&ql,   g_ql);
    cudaGetSymbolAddress((void**)&kh,   g_kh);
    cudaGetSymbolAddress((void**)&kl,   g_kl);
    cudaGetSymbolAddress((void**)&vh,   g_vh);
    cudaGetSymbolAddress((void**)&xth,  g_xth);
    cudaGetSymbolAddress((void**)&xtl,  g_xtl);
    cudaGetSymbolAddress((void**)&oth,  g_oth);
    cudaGetSymbolAddress((void**)&otl,  g_otl);
    cudaGetSymbolAddress((void**)&wvh,  g_wvh);
    cudaGetSymbolAddress((void**)&wvl,  g_wvl);
    cudaGetSymbolAddress((void**)&wfh,  g_wfh);
    cudaGetSymbolAddress((void**)&wfl,  g_wfl);
    cudaGetSymbolAddress((void**)&wqkh, g_wqkh);
    cudaGetSymbolAddress((void**)&wqkl, g_wqkl);

    cudaFuncSetAttribute(flash_mma_kernel,
                         cudaFuncAttributeMaxDynamicSharedMemorySize, FL_SMEM);
    cudaFuncSetAttribute(proj_mma_kernel<0>,
                         cudaFuncAttributeMaxDynamicSharedMemorySize, PM_SMEM);
    cudaFuncSetAttribute(proj_mma_kernel<1>,
                         cudaFuncAttributeMaxDynamicSharedMemorySize, PM_SMEM);
    cudaFuncSetAttribute(proj_qk_mma_kernel,
                         cudaFuncAttributeMaxDynamicSharedMemorySize, PM_SMEM);

    // operand prep
    wsplit_kernel<<<C_ * C_ / 256, 256>>>(Wv, wvh, wvl);
    wsplit_kernel<<<C_ * C_ / 256, 256>>>(Wf, wfh, wfl);
    wqksplit_kernel<<<64 * C_ / 256, 256>>>(Wq, Wk, wqkh, wqkl);
    xsplit_kernel<<<dim3(N_ / 64, C_ / 64, B_), 256>>>(x, xth, xtl);

    // Q+K projection on tensor cores -> bf16 hi/lo [b][N][32]
    proj_qk_mma_kernel<<<dim3(1, N_ / 128, B_), 256, PM_SMEM>>>(
        xth, xtl, wqkh, wqkl, bq, bk, qh, ql, kh, kl);

    // V projection on tensor cores -> bf16 [b][C][N]
    proj_mma_kernel<0><<<dim3(N_ / 64, 2, B_), 256, PM_SMEM>>>(wvh, wvl, xth, xtl, bv, vh);

    // attention (pipelined, ILP-2 PV) -> O bf16 hi/lo [b][N][C]
    flash_mma_kernel<<<dim3(N_ / 64, B_), 256, FL_SMEM>>>(qh, ql, kh, kl, vh, oth, otl);

    // final projection on tensor cores -> fp32 out
    proj_mma_kernel<1><<<dim3(N_ / 64, 2, B_), 256, PM_SMEM>>>(wfh, wfl, oth, otl, bf, out);
}

// round 14
// speedup vs baseline: 1.5494x; 1.0120x over previous
#include <cuda_runtime.h>
#include <cuda_bf16.h>
#include <cstdint>

static constexpr int B_   = 8;
static constexpr int C_   = 256;
static constexpr int CQK_ = 32;
static constexpr int N_   = 4096;

// Scratch
__device__ __align__(256) __nv_bfloat16 g_qh[(size_t)B_ * N_ * CQK_];
__device__ __align__(256) __nv_bfloat16 g_ql[(size_t)B_ * N_ * CQK_];
__device__ __align__(256) __nv_bfloat16 g_kh[(size_t)B_ * N_ * CQK_];
__device__ __align__(256) __nv_bfloat16 g_kl[(size_t)B_ * N_ * CQK_];
__device__ __align__(256) __nv_bfloat16 g_vh[(size_t)B_ * C_ * N_];
__device__ __align__(256) __nv_bfloat16 g_xth[(size_t)B_ * N_ * C_];
__device__ __align__(256) __nv_bfloat16 g_xtl[(size_t)B_ * N_ * C_];
__device__ __align__(256) __nv_bfloat16 g_oth[(size_t)B_ * N_ * C_];
__device__ __align__(256) __nv_bfloat16 g_otl[(size_t)B_ * N_ * C_];
__device__ __align__(256) __nv_bfloat16 g_wvh[C_ * C_], g_wvl[C_ * C_];
__device__ __align__(256) __nv_bfloat16 g_wfh[C_ * C_], g_wfl[C_ * C_];
__device__ __align__(256) __nv_bfloat16 g_wqkh[64 * C_], g_wqkl[64 * C_];

// ---------------- helpers ----------------
__device__ __forceinline__ uint32_t smem_u32(const void* p) {
    uint32_t a;
    asm("{ .reg .u64 t; cvta.to.shared.u64 t, %1; cvt.u32.u64 %0, t; }" : "=r"(a) : "l"(p));
    return a;
}
__device__ __forceinline__ void cpa16(uint32_t dst, const void* src) {
    asm volatile("cp.async.cg.shared.global [%0], [%1], 16;" :: "r"(dst), "l"(src) : "memory");
}
#define CPA_COMMIT() asm volatile("cp.async.commit_group;" ::: "memory")
#define CPA_WAIT(n)  asm volatile("cp.async.wait_group %0;" :: "n"(n) : "memory")
#define BAR_SYNC(id, cnt)   asm volatile("bar.sync %0, %1;"   :: "r"(id), "r"(cnt) : "memory")
#define BAR_ARRIVE(id, cnt) asm volatile("bar.arrive %0, %1;" :: "r"(id), "r"(cnt) : "memory")

__device__ __forceinline__ void ldsm4(uint32_t addr, uint32_t* r) {
    asm volatile("ldmatrix.sync.aligned.m8n8.x4.shared.b16 {%0,%1,%2,%3}, [%4];"
                 : "=r"(r[0]), "=r"(r[1]), "=r"(r[2]), "=r"(r[3]) : "r"(addr));
}
__device__ __forceinline__ void mma16816(float* d, const uint32_t* a, uint32_t b0, uint32_t b1) {
    asm volatile("mma.sync.aligned.m16n8k16.row.col.f32.bf16.bf16.f32 "
                 "{%0,%1,%2,%3}, {%4,%5,%6,%7}, {%8,%9}, {%0,%1,%2,%3};"
                 : "+f"(d[0]), "+f"(d[1]), "+f"(d[2]), "+f"(d[3])
                 : "r"(a[0]), "r"(a[1]), "r"(a[2]), "r"(a[3]), "r"(b0), "r"(b1));
}
__device__ __forceinline__ uint32_t pack_bf16x2(float e0, float e1) {
    uint32_t r; asm("cvt.rn.bf16x2.f32 %0, %1, %2;" : "=r"(r) : "f"(e1), "f"(e0)); return r;
}
__device__ __forceinline__ float lo_bf16_f(uint32_t u) { return __uint_as_float(u << 16); }
__device__ __forceinline__ float hi_bf16_f(uint32_t u) { return __uint_as_float(u & 0xffff0000u); }
__device__ __forceinline__ void bf16_split(float v, __nv_bfloat16& h, __nv_bfloat16& l) {
    h = __float2bfloat16(v);
    l = __float2bfloat16(v - __bfloat162float(h));
}

// ---------------- fused prep: xsplit + Wv/Wf split + Wq||Wk split --------------
// grid: [0,2048) xsplit; [2048,2304) Wv; [2304,2560) Wf; [2560,2624) Wqk
__global__ __launch_bounds__(256)
void prep_kernel(const float* __restrict__ X,
                 const float* __restrict__ Wq, const float* __restrict__ Wk,
                 const float* __restrict__ Wv, const float* __restrict__ Wf,
                 __nv_bfloat16* __restrict__ Xh, __nv_bfloat16* __restrict__ Xl,
                 __nv_bfloat16* __restrict__ Wvh, __nv_bfloat16* __restrict__ Wvl,
                 __nv_bfloat16* __restrict__ Wfh, __nv_bfloat16* __restrict__ Wfl,
                 __nv_bfloat16* __restrict__ Wqkh, __nv_bfloat16* __restrict__ Wqkl)
{
    __shared__ float t[64][65];
    const int id  = blockIdx.x;
    const int tid = threadIdx.x;

    if (id < 2048) {
        // x split-transpose: fp32 [b][C][N] -> bf16 hi/lo [b][N][C]
        const int bx = id & 63, by = (id >> 6) & 3, bz = id >> 8;
        const int n0 = bx * 64, c0 = by * 64, b = bz;
        for (int i = tid; i < 4096; i += 256) {
            int c = i >> 6, n = i & 63;
            t[c][n] = X[(size_t)b * C_ * N_ + (size_t)(c0 + c) * N_ + n0 + n];
        }
        __syncthreads();
        for (int i = tid; i < 2048; i += 256) {
            int n = i >> 5, c2 = (i & 31) * 2;
            float v0 = t[c2][n], v1 = t[c2 + 1][n];
            __nv_bfloat16 h0, l0, h1, l1;
            bf16_split(v0, h0, l0);
            bf16_split(v1, h1, l1);
            __nv_bfloat162 hh, ll;
            hh.x = h0; hh.y = h1; ll.x = l0; ll.y = l1;
            size_t o = ((size_t)b * N_ + n0 + n) * C_ + c0 + c2;
            *(__nv_bfloat162*)&Xh[o] = hh;
            *(__nv_bfloat162*)&Xl[o] = ll;
        }
    } else if (id < 2304) {
        int i = (id - 2048) * 256 + tid;
        float v = Wv[i];
        __nv_bfloat16 h, l; bf16_split(v, h, l);
        Wvh[i] = h; Wvl[i] = l;
    } else if (id < 2560) {
        int i = (id - 2304) * 256 + tid;
        float v = Wf[i];
        __nv_bfloat16 h, l; bf16_split(v, h, l);
        Wfh[i] = h; Wfl[i] = l;
    } else {
        int i = (id - 2560) * 256 + tid;   // 64*256 = 16384 total
        int row = i >> 8, col = i & 255;
        float v = (row < 32) ? Wq[(size_t)row * 256 + col]
                             : Wk[(size_t)(row - 32) * 256 + col];
        __nv_bfloat16 h, l; bf16_split(v, h, l);
        Wqkh[i] = h; Wqkl[i] = l;
    }
}

// ---------------- fused projection kernel: V path (y<2) + QK path (y==2) ------
static constexpr int PM_SW   = 0;
static constexpr int PM_SX   = 73728;
static constexpr int PM_SMEM = 110592;

__global__ __launch_bounds__(256, 2)
void proj_qkv_kernel(const __nv_bfloat16* __restrict__ Wvh, const __nv_bfloat16* __restrict__ Wvl,
                     const __nv_bfloat16* __restrict__ Xh, const __nv_bfloat16* __restrict__ Xl,
                     const float* __restrict__ bv, __nv_bfloat16* __restrict__ Vh,
                     const __nv_bfloat16* __restrict__ Wqkh, const __nv_bfloat16* __restrict__ Wqkl,
                     const float* __restrict__ bq, const float* __restrict__ bk,
                     __nv_bfloat16* __restrict__ Qh, __nv_bfloat16* __restrict__ Ql,
                     __nv_bfloat16* __restrict__ Kh, __nv_bfloat16* __restrict__ Kl)
{
    extern __shared__ char smem[];
    const uint32_t sb = smem_u32(smem);
    const int tid = threadIdx.x, lane = tid & 31, w = tid >> 5;
    const int b  = blockIdx.z;
    const int mw = w * 16;

    if (blockIdx.y < 2) {
        // ===== V path: out[m][n] = bv[m] + sum_k Wv[m][k] X[k][n], bf16 out =====
        const int m0 = blockIdx.y * 128;
        const int n0 = blockIdx.x * 64;

        auto load_wx = [&](int ks, int bi) {
            const int k0 = ks * 64;
            for (int i = tid; i < 2048; i += 256) {
                int half = i >> 10, r = (i >> 3) & 127, ch = i & 7;
                const __nv_bfloat16* src = (half ? Wvl : Wvh) + (size_t)(m0 + r) * 256 + k0 + ch * 8;
                cpa16(sb + PM_SW + bi * 36864 + half * 18432 + r * 144 + ch * 16, src);
            }
            for (int i = tid; i < 1024; i += 256) {
                int half = i >> 9, r = (i >> 3) & 63, ch = i & 7;
                const __nv_bfloat16* src = (half ? Xl : Xh) + ((size_t)b * N_ + n0 + r) * 256 + k0 + ch * 8;
                cpa16(sb + PM_SX + bi * 18432 + half * 9216 + r * 144 + ch * 16, src);
            }
        };

        load_wx(0, 0); CPA_COMMIT();
        load_wx(1, 1); CPA_COMMIT();

        float oacc[8][4];
#pragma unroll
        for (int i = 0; i < 8; i++)
#pragma unroll
            for (int j = 0; j < 4; j++) oacc[i][j] = 0.f;

#pragma unroll
        for (int ks = 0; ks < 4; ks++) {
            const int bi = ks & 1;
            if (ks < 2) { CPA_WAIT(1); } else { CPA_WAIT(0); }
            __syncthreads();

            const uint32_t wb_hi = sb + PM_SW + bi * 36864;
            const uint32_t xb_hi = sb + PM_SX + bi * 18432;

            uint32_t ah[4][4], al[4][4];
#pragma unroll
            for (int kc = 0; kc < 4; kc++) {
                uint32_t addr = wb_hi + (uint32_t)(mw + (lane & 15)) * 144
                              + (uint32_t)(kc * 16 + (lane >> 4) * 8) * 2;
                ldsm4(addr, ah[kc]);
                ldsm4(addr + 18432, al[kc]);
            }

#pragma unroll
            for (int nb = 0; nb < 8; nb++) {
                uint32_t rowoff = xb_hi + (uint32_t)(nb * 8 + (lane & 7)) * 144;
                uint32_t bh[8], bl[8];
#pragma unroll
                for (int kk = 0; kk < 2; kk++) {
                    uint32_t off = (uint32_t)(kk * 32 + (lane >> 3) * 8) * 2;
                    ldsm4(rowoff + off, &bh[4 * kk]);
                    ldsm4(rowoff + off + 9216, &bl[4 * kk]);
                }
#pragma unroll
                for (int kc = 0; kc < 4; kc++) {
                    int ix = (kc >> 1) * 4 + (kc & 1) * 2;
                    mma16816(oacc[nb], ah[kc], bh[ix], bh[ix + 1]);
                    mma16816(oacc[nb], al[kc], bh[ix], bh[ix + 1]);
                    mma16816(oacc[nb], ah[kc], bl[ix], bl[ix + 1]);
                }
            }

            __syncthreads();
            if (ks + 2 < 4) { load_wx(ks + 2, bi); CPA_COMMIT(); }
        }

        const int r0 = m0 + mw + (lane >> 2);
        const float b0f = bv[r0], b1f = bv[r0 + 8];
#pragma unroll
        for (int nb = 0; nb < 8; nb++) {
            int col = n0 + nb * 8 + (lane & 3) * 2;
            float v0 = oacc[nb][0] + b0f, v1 = oacc[nb][1] + b0f;
            float v2 = oacc[nb][2] + b1f, v3 = oacc[nb][3] + b1f;
            __nv_bfloat16* Yb = Vh + (size_t)b * C_ * N_;
            *(uint32_t*)&Yb[(size_t)r0 * N_ + col]       = pack_bf16x2(v0, v1);
            *(uint32_t*)&Yb[(size_t)(r0 + 8) * N_ + col] = pack_bf16x2(v2, v3);
        }
    } else {
        // ===== QK path: A = x tokens, B = Wq||Wk; out bf16 hi/lo [b][N][32] =====
        if (blockIdx.x >= 32) return;
        const int m0 = blockIdx.x * 128;   // token tile

        auto load_ab = [&](int ks, int bi) {
            const int k0 = ks * 64;
            for (int i = tid; i < 2048; i += 256) {
                int half = i >> 10, r = (i >> 3) & 127, ch = i & 7;
                const __nv_bfloat16* src = (half ? Xl : Xh) + ((size_t)b * N_ + m0 + r) * 256 + k0 + ch * 8;
                cpa16(sb + PM_SW + bi * 36864 + half * 18432 + r * 144 + ch * 16, src);
            }
            for (int i = tid; i < 1024; i += 256) {
                int half = i >> 9, r = (i >> 3) & 63, ch = i & 7;
                const __nv_bfloat16* src = (half ? Wqkl : Wqkh) + (size_t)r * 256 + k0 + ch * 8;
                cpa16(sb + PM_SX + bi * 18432 + half * 9216 + r * 144 + ch * 16, src);
            }
        };

        load_ab(0, 0); CPA_COMMIT();
        load_ab(1, 1); CPA_COMMIT();

        float oacc[8][4];
#pragma unroll
        for (int i = 0; i < 8; i++)
#pragma unroll
            for (int j = 0; j < 4; j++) oacc[i][j] = 0.f;

#pragma unroll
        for (int ks = 0; ks < 4; ks++) {
            const int bi = ks & 1;
            if (ks < 2) { CPA_WAIT(1); } else { CPA_WAIT(0); }
            __syncthreads();

            const uint32_t ab_hi = sb + PM_SW + bi * 36864;
            const uint32_t bb_hi = sb + PM_SX + bi * 18432;

            uint32_t ah[4][4], al[4][4];
#pragma unroll
            for (int kc = 0; kc < 4; kc++) {
                uint32_t addr = ab_hi + (uint32_t)(mw + (lane & 15)) * 144
                              + (uint32_t)(kc * 16 + (lane >> 4) * 8) * 2;
                ldsm4(addr, ah[kc]);
                ldsm4(addr + 18432, al[kc]);
            }

#pragma unroll
            for (int nb = 0; nb < 8; nb++) {
                uint32_t rowoff = bb_hi + (uint32_t)(nb * 8 + (lane & 7)) * 144;
                uint32_t bh[8], bl[8];
#pragma unroll
                for (int kk = 0; kk < 2; kk++) {
                    uint32_t off = (uint32_t)(kk * 32 + (lane >> 3) * 8) * 2;
                    ldsm4(rowoff + off, &bh[4 * kk]);
                    ldsm4(rowoff + off + 9216, &bl[4 * kk]);
                }
#pragma unroll
                for (int kc = 0; kc < 4; kc++) {
                    int ix = (kc >> 1) * 4 + (kc & 1) * 2;
                    mma16816(oacc[nb], ah[kc], bh[ix], bh[ix + 1]);
                    mma16816(oacc[nb], al[kc], bh[ix], bh[ix + 1]);
                    mma16816(oacc[nb], ah[kc], bl[ix], bl[ix + 1]);
                }
            }

            __syncthreads();
            if (ks + 2 < 4) { load_ab(ks + 2, bi); CPA_COMMIT(); }
        }

        const int r0 = m0 + mw + (lane >> 2);
#pragma unroll
        for (int nb = 0; nb < 8; nb++) {
            int c = nb * 8 + (lane & 3) * 2;
            const bool isQ = (c < 32);
            const int cc = isQ ? c : c - 32;
            const float bb0 = isQ ? bq[cc] : bk[cc];
            const float bb1 = isQ ? bq[cc + 1] : bk[cc + 1];
            float v0 = oacc[nb][0] + bb0, v1 = oacc[nb][1] + bb1;
            float v2 = oacc[nb][2] + bb0, v3 = oacc[nb][3] + bb1;
            uint32_t h01 = pack_bf16x2(v0, v1);
            uint32_t l01 = pack_bf16x2(v0 - lo_bf16_f(h01), v1 - hi_bf16_f(h01));
            uint32_t h23 = pack_bf16x2(v2, v3);
            uint32_t l23 = pack_bf16x2(v2 - lo_bf16_f(h23), v3 - hi_bf16_f(h23));
            __nv_bfloat16* dh = isQ ? Qh : Kh;
            __nv_bfloat16* dl = isQ ? Ql : Kl;
            size_t o0 = ((size_t)b * N_ + r0) * CQK_ + cc;
            size_t o1 = ((size_t)b * N_ + r0 + 8) * CQK_ + cc;
            *(uint32_t*)&dh[o0] = h01;
            *(uint32_t*)&dl[o0] = l01;
            *(uint32_t*)&dh[o1] = h23;
            *(uint32_t*)&dl[o1] = l23;
        }
    }
}

// ---------------- final projection (tensor cores, fp32 out) -------------------
__global__ __launch_bounds__(256, 2)
void proj_f_mma_kernel(const __nv_bfloat16* __restrict__ Wh, const __nv_bfloat16* __restrict__ Wl,
                       const __nv_bfloat16* __restrict__ Xh, const __nv_bfloat16* __restrict__ Xl,
                       const float* __restrict__ bias, float* __restrict__ Yout)
{
    extern __shared__ char smem[];
    const uint32_t sb = smem_u32(smem);
    const int tid = threadIdx.x, lane = tid & 31, w = tid >> 5;
    const int b  = blockIdx.z;
    const int m0 = blockIdx.y * 128;
    const int n0 = blockIdx.x * 64;
    const int mw = w * 16;

    auto load_wx = [&](int ks, int bi) {
        const int k0 = ks * 64;
        for (int i = tid; i < 2048; i += 256) {
            int half = i >> 10, r = (i >> 3) & 127, ch = i & 7;
            const __nv_bfloat16* src = (half ? Wl : Wh) + (size_t)(m0 + r) * 256 + k0 + ch * 8;
            cpa16(sb + PM_SW + bi * 36864 + half * 18432 + r * 144 + ch * 16, src);
        }
        for (int i = tid; i < 1024; i += 256) {
            int half = i >> 9, r = (i >> 3) & 63, ch = i & 7;
            const __nv_bfloat16* src = (half ? Xl : Xh) + ((size_t)b * N_ + n0 + r) * 256 + k0 + ch * 8;
            cpa16(sb + PM_SX + bi * 18432 + half * 9216 + r * 144 + ch * 16, src);
        }
    };

    load_wx(0, 0); CPA_COMMIT();
    load_wx(1, 1); CPA_COMMIT();

    float oacc[8][4];
#pragma unroll
    for (int i = 0; i < 8; i++)
#pragma unroll
        for (int j = 0; j < 4; j++) oacc[i][j] = 0.f;

#pragma unroll
    for (int ks = 0; ks < 4; ks++) {
        const int bi = ks & 1;
        if (ks < 2) { CPA_WAIT(1); } else { CPA_WAIT(0); }
        __syncthreads();

        const uint32_t wb_hi = sb + PM_SW + bi * 36864;
        const uint32_t xb_hi = sb + PM_SX + bi * 18432;

        uint32_t ah[4][4], al[4][4];
#pragma unroll
        for (int kc = 0; kc < 4; kc++) {
            uint32_t addr = wb_hi + (uint32_t)(mw + (lane & 15)) * 144
                          + (uint32_t)(kc * 16 + (lane >> 4) * 8) * 2;
            ldsm4(addr, ah[kc]);
            ldsm4(addr + 18432, al[kc]);
        }

#pragma unroll
        for (int nb = 0; nb < 8; nb++) {
            uint32_t rowoff = xb_hi + (uint32_t)(nb * 8 + (lane & 7)) * 144;
            uint32_t bh[8], bl[8];
#pragma unroll
            for (int kk = 0; kk < 2; kk++) {
                uint32_t off = (uint32_t)(kk * 32 + (lane >> 3) * 8) * 2;
                ldsm4(rowoff + off, &bh[4 * kk]);
                ldsm4(rowoff + off + 9216, &bl[4 * kk]);
            }
#pragma unroll
            for (int kc = 0; kc < 4; kc++) {
                int ix = (kc >> 1) * 4 + (kc & 1) * 2;
                mma16816(oacc[nb], ah[kc], bh[ix], bh[ix + 1]);
                mma16816(oacc[nb], al[kc], bh[ix], bh[ix + 1]);
                mma16816(oacc[nb], ah[kc], bl[ix], bl[ix + 1]);
            }
        }

        __syncthreads();
        if (ks + 2 < 4) { load_wx(ks + 2, bi); CPA_COMMIT(); }
    }

    const int r0 = m0 + mw + (lane >> 2);
    const float b0f = bias[r0], b1f = bias[r0 + 8];
#pragma unroll
    for (int nb = 0; nb < 8; nb++) {
        int col = n0 + nb * 8 + (lane & 3) * 2;
        float* Yf = Yout + (size_t)b * C_ * N_;
        *(float2*)&Yf[(size_t)r0 * N_ + col] =
            make_float2(oacc[nb][0] + b0f, oacc[nb][1] + b0f);
        *(float2*)&Yf[(size_t)(r0 + 8) * N_ + col] =
            make_float2(oacc[nb][2] + b1f, oacc[nb][3] + b1f);
    }
}

// ---------------- flash attention (R13: pipelined + ILP-2 PV) ------------------
static constexpr int SP_HI = 0;
static constexpr int SP_LO = 8192;
static constexpr int S_INV = 16384;
static constexpr int SQH   = 0;
static constexpr int SQL   = 5120;
static constexpr int SKB   = 16640;
static constexpr int SVB   = 37120;
static constexpr int FL_SMEM = 110848;

__device__ __forceinline__ void pv_pair(float* oa, float* ob,
                                        const uint32_t pah[4][4], const uint32_t pal[4][4],
                                        uint32_t vh_b, int c0, int c1, int lane)
{
    uint32_t vfa[8], vfb[8];
    uint32_t ra = (uint32_t)(c0 + (lane & 7)) * 144;
    uint32_t rb = (uint32_t)(c1 + (lane & 7)) * 144;
#pragma unroll
    for (int kjp = 0; kjp < 2; kjp++) {
        uint32_t off = (uint32_t)(kjp * 32 + (lane >> 3) * 8) * 2;
        ldsm4(vh_b + ra + off, &vfa[4 * kjp]);
        ldsm4(vh_b + rb + off, &vfb[4 * kjp]);
    }
#pragma unroll
    for (int kj = 0; kj < 4; kj++) {
        int ix = (kj >> 1) * 4 + (kj & 1) * 2;
        mma16816(oa, pah[kj], vfa[ix], vfa[ix + 1]);
        mma16816(ob, pah[kj], vfb[ix], vfb[ix + 1]);
        mma16816(oa, pal[kj], vfa[ix], vfa[ix + 1]);
        mma16816(ob, pal[kj], vfb[ix], vfb[ix + 1]);
    }
}
__device__ __forceinline__ void pv_one(float* oa,
                                       const uint32_t pah[4][4], const uint32_t pal[4][4],
                                       uint32_t vh_b, int c0, int lane)
{
    uint32_t vfa[8];
    uint32_t ra = (uint32_t)(c0 + (lane & 7)) * 144;
#pragma unroll
    for (int kjp = 0; kjp < 2; kjp++) {
        uint32_t off = (uint32_t)(kjp * 32 + (lane >> 3) * 8) * 2;
        ldsm4(vh_b + ra + off, &vfa[4 * kjp]);
    }
#pragma unroll
    for (int kj = 0; kj < 4; kj++) {
        int ix = (kj >> 1) * 4 + (kj & 1) * 2;
        mma16816(oa, pah[kj], vfa[ix], vfa[ix + 1]);
        mma16816(oa, pal[kj], vfa[ix], vfa[ix + 1]);
    }
}

__global__ __launch_bounds__(256, 2)
void flash_mma_kernel(const __nv_bfloat16* __restrict__ Qh, const __nv_bfloat16* __restrict__ Ql,
                      const __nv_bfloat16* __restrict__ Kh, const __nv_bfloat16* __restrict__ Kl,
                      const __nv_bfloat16* __restrict__ Vh,
                      __nv_bfloat16* __restrict__ Oh, __nv_bfloat16* __restrict__ Ol)
{
    extern __shared__ char smem[];
    const uint32_t sb = smem_u32(smem);
    const int tid = threadIdx.x, lane = tid & 31, w = tid >> 5;
    const int qw = (w & 3) * 16;
    const int b = blockIdx.y, q0 = blockIdx.x * 64;

    for (int i = tid; i < 512; i += 256) {
        int half = i >> 8, r = (i >> 2) & 63, ch = i & 3;
        const __nv_bfloat16* src = (half ? Ql : Qh) + ((size_t)b * N_ + q0 + r) * CQK_ + ch * 8;
        cpa16(sb + (half ? SQL : SQH) + r * 80 + ch * 16, src);
    }
    for (int t = 0; t < 2; t++) {
        const int j0 = t * 64;
        for (int i = tid; i < 512; i += 256) {
            int half = i >> 8, r = (i >> 2) & 63, ch = i & 3;
            const __nv_bfloat16* src = (half ? Kl : Kh) + ((size_t)b * N_ + j0 + r) * CQK_ + ch * 8;
            cpa16(sb + SKB + t * 10240 + half * 5120 + r * 80 + ch * 16, src);
        }
        for (int i = tid; i < 2048; i += 256) {
            int r = i >> 3, ch = i & 7;
            const __nv_bfloat16* src = Vh + ((size_t)b * C_ + r) * N_ + j0 + ch * 8;
            cpa16(sb + SVB + t * 36864 + r * 144 + ch * 16, src);
        }
        CPA_COMMIT();
    }
    CPA_WAIT(0);
    __syncthreads();

    float* sinv = (float*)(smem + S_INV);
    const int qg = q0 + qw + (lane >> 2);
    const size_t rbase0 = ((size_t)b * N_ + qg) * C_;
    const size_t rbase1 = ((size_t)b * N_ + qg + 8) * C_;

    if (w < 4) {
        // ========================= PRODUCER =========================
        uint32_t qa[2][2][4];
#pragma unroll
        for (int hl = 0; hl < 2; hl++)
#pragma unroll
            for (int kc = 0; kc < 2; kc++) {
                uint32_t addr = sb + (hl ? SQL : SQH)
                              + (uint32_t)(qw + (lane & 15)) * 80
                              + (uint32_t)(kc * 16 + (lane >> 4) * 8) * 2;
                ldsm4(addr, qa[hl][kc]);
            }
        BAR_SYNC(5, 128);

        float oacc[13][4];
#pragma unroll
        for (int i = 0; i < 13; i++)
#pragma unroll
            for (int j = 0; j < 4; j++) oacc[i][j] = 0.f;
        float rsum0 = 0.f, rsum1 = 0.f;

        char* ph_dst = smem + SP_HI + (w & 3) * 2048 + lane * 16;
        char* pl_dst = smem + SP_LO + (w & 3) * 2048 + lane * 16;

        for (int kt = 0; kt < 64; kt++) {
            const int bi = kt & 1;
            const uint32_t kh_b = sb + SKB + bi * 10240, kl_b = kh_b + 5120;
            const uint32_t vh_b = sb + SVB + bi * 36864;

            float sacc[8][4];
#pragma unroll
            for (int i = 0; i < 8; i++)
#pragma unroll
                for (int j = 0; j < 4; j++) sacc[i][j] = 0.f;
#pragma unroll
            for (int kc = 0; kc < 2; kc++)
#pragma unroll
                for (int nbp = 0; nbp < 4; nbp++) {
                    uint32_t off = (uint32_t)((nbp * 2 + ((lane >> 4) & 1)) * 8 + (lane & 7)) * 80
                                 + (uint32_t)(kc * 16 + ((lane >> 3) & 1) * 8) * 2;
                    uint32_t bh[4], bl[4];
                    ldsm4(kh_b + off, bh);
                    ldsm4(kl_b + off, bl);
                    mma16816(sacc[2*nbp],   qa[0][kc], bh[0], bh[1]);
                    mma16816(sacc[2*nbp+1], qa[0][kc], bh[2], bh[3]);
                    mma16816(sacc[2*nbp],   qa[1][kc], bh[0], bh[1]);
                    mma16816(sacc[2*nbp+1], qa[1][kc], bh[2], bh[3]);
                    mma16816(sacc[2*nbp],   qa[0][kc], bl[0], bl[1]);
                    mma16816(sacc[2*nbp+1], qa[0][kc], bl[2], bl[3]);
                }

            uint32_t pah[4][4], pal[4][4];
#pragma unroll
            for (int nb = 0; nb < 8; nb++) {
                float e0 = __expf(sacc[nb][0]);
                float e1 = __expf(sacc[nb][1]);
                float e2 = __expf(sacc[nb][2]);
                float e3 = __expf(sacc[nb][3]);
                rsum0 += e0 + e1;
                rsum1 += e2 + e3;
                int kj = nb >> 1, o = (nb & 1) * 2;
                uint32_t h01 = pack_bf16x2(e0, e1);
                uint32_t h23 = pack_bf16x2(e2, e3);
                pah[kj][o]     = h01;
                pah[kj][o + 1] = h23;
                pal[kj][o]     = pack_bf16x2(e0 - lo_bf16_f(h01), e1 - hi_bf16_f(h01));
                pal[kj][o + 1] = pack_bf16x2(e2 - lo_bf16_f(h23), e3 - hi_bf16_f(h23));
            }

            if (kt > 0) BAR_SYNC(2, 256);
#pragma unroll
            for (int kj = 0; kj < 4; kj++) {
                *(uint4*)(ph_dst + kj * 512) = make_uint4(pah[kj][0], pah[kj][1], pah[kj][2], pah[kj][3]);
                *(uint4*)(pl_dst + kj * 512) = make_uint4(pal[kj][0], pal[kj][1], pal[kj][2], pal[kj][3]);
            }
            BAR_ARRIVE(1, 256);

            if (kt > 0) BAR_SYNC(3, 256);

#pragma unroll
            for (int cp = 0; cp < 6; cp++)
                pv_pair(oacc[2*cp], oacc[2*cp+1], pah, pal, vh_b,
                        (2*cp) * 8, (2*cp+1) * 8, lane);
            pv_one(oacc[12], pah, pal, vh_b, 96, lane);
            BAR_ARRIVE(4, 256);

            if (kt + 2 < 64) {
                const int j0 = (kt + 2) * 64;
                const uint32_t kd = sb + SKB + bi * 10240;
                for (int i = tid; i < 512; i += 128) {
                    int half = i >> 8, r = (i >> 2) & 63, ch = i & 3;
                    const __nv_bfloat16* src = (half ? Kl : Kh) + ((size_t)b * N_ + j0 + r) * CQK_ + ch * 8;
                    cpa16(kd + half * 5120 + r * 80 + ch * 16, src);
                }
            }
            CPA_COMMIT();
            CPA_WAIT(1);
            BAR_SYNC(5, 128);
        }

        rsum0 += __shfl_xor_sync(0xffffffffu, rsum0, 1);
        rsum0 += __shfl_xor_sync(0xffffffffu, rsum0, 2);
        rsum1 += __shfl_xor_sync(0xffffffffu, rsum1, 1);
        rsum1 += __shfl_xor_sync(0xffffffffu, rsum1, 2);
        if ((lane & 3) == 0) {
            sinv[qw + (lane >> 2)]     = rsum0;
            sinv[qw + 8 + (lane >> 2)] = rsum1;
        }
        __syncwarp();
        BAR_ARRIVE(7, 256);

        const float inv0 = 1.f / sinv[qw + (lane >> 2)];
        const float inv1 = 1.f / sinv[qw + 8 + (lane >> 2)];
#pragma unroll
        for (int cb = 0; cb < 13; cb++) {
            int c = cb * 8 + (lane & 3) * 2;
            float v0 = oacc[cb][0] * inv0, v1 = oacc[cb][1] * inv0;
            float v2 = oacc[cb][2] * inv1, v3 = oacc[cb][3] * inv1;
            uint32_t h01 = pack_bf16x2(v0, v1);
            uint32_t l01 = pack_bf16x2(v0 - lo_bf16_f(h01), v1 - hi_bf16_f(h01));
            uint32_t h23 = pack_bf16x2(v2, v3);
            uint32_t l23 = pack_bf16x2(v2 - lo_bf16_f(h23), v3 - hi_bf16_f(h23));
            *(uint32_t*)&Oh[rbase0 + c] = h01;
            *(uint32_t*)&Ol[rbase0 + c] = l01;
            *(uint32_t*)&Oh[rbase1 + c] = h23;
            *(uint32_t*)&Ol[rbase1 + c] = l23;
        }
    } else {
        // ========================= CONSUMER =========================
        float oacc[19][4];
#pragma unroll
        for (int i = 0; i < 19; i++)
#pragma unroll
            for (int j = 0; j < 4; j++) oacc[i][j] = 0.f;

        const char* ph_src = smem + SP_HI + (w & 3) * 2048 + lane * 16;
        const char* pl_src = smem + SP_LO + (w & 3) * 2048 + lane * 16;
        const int ctid = tid - 128;

        for (int kt = 0; kt < 64; kt++) {
            const int bi = kt & 1;
            const uint32_t vh_b = sb + SVB + bi * 36864;

            BAR_SYNC(1, 256);
            uint32_t pah[4][4], pal[4][4];
#pragma unroll
            for (int kj = 0; kj < 4; kj++) {
                uint4 h4 = *(const uint4*)(ph_src + kj * 512);
                uint4 l4 = *(const uint4*)(pl_src + kj * 512);
                pah[kj][0] = h4.x; pah[kj][1] = h4.y; pah[kj][2] = h4.z; pah[kj][3] = h4.w;
                pal[kj][0] = l4.x; pal[kj][1] = l4.y; pal[kj][2] = l4.z; pal[kj][3] = l4.w;
            }
            if (kt + 1 < 64) BAR_ARRIVE(2, 256);

#pragma unroll
            for (int cp = 0; cp < 9; cp++)
                pv_pair(oacc[2*cp], oacc[2*cp+1], pah, pal, vh_b,
                        104 + (2*cp) * 8, 104 + (2*cp+1) * 8, lane);
            pv_one(oacc[18], pah, pal, vh_b, 104 + 144, lane);

            BAR_SYNC(4, 256);
            if (kt + 2 < 64) {
                const int j0 = (kt + 2) * 64;
                const uint32_t vd = sb + SVB + bi * 36864;
                for (int i = ctid; i < 2048; i += 128) {
                    int r = i >> 3, ch = i & 7;
                    const __nv_bfloat16* src = Vh + ((size_t)b * C_ + r) * N_ + j0 + ch * 8;
                    cpa16(vd + r * 144 + ch * 16, src);
                }
            }
            CPA_COMMIT();
            CPA_WAIT(1);
            BAR_SYNC(6, 128);
            if (kt + 1 < 64) BAR_ARRIVE(3, 256);
        }

        BAR_SYNC(7, 256);
        const float inv0 = 1.f / sinv[qw + (lane >> 2)];
        const float inv1 = 1.f / sinv[qw + 8 + (lane >> 2)];
#pragma unroll
        for (int cb = 0; cb < 19; cb++) {
            int c = 104 + cb * 8 + (lane & 3) * 2;
            float v0 = oacc[cb][0] * inv0, v1 = oacc[cb][1] * inv0;
            float v2 = oacc[cb][2] * inv1, v3 = oacc[cb][3] * inv1;
            uint32_t h01 = pack_bf16x2(v0, v1);
            uint32_t l01 = pack_bf16x2(v0 - lo_bf16_f(h01), v1 - hi_bf16_f(h01));
            uint32_t h23 = pack_bf16x2(v2, v3);
            uint32_t l23 = pack_bf16x2(v2 - lo_bf16_f(h23), v3 - hi_bf16_f(h23));
            *(uint32_t*)&Oh[rbase0 + c] = h01;
            *(uint32_t*)&Ol[rbase0 + c] = l01;
            *(uint32_t*)&Oh[rbase1 + c] = h23;
            *(uint32_t*)&Ol[rbase1 + c] = l23;
        }
    }
}

// ---------------- kernel_launch ----------------
extern "C" void kernel_launch(void* const* d_in, const int* in_sizes, int n_in,
                              void* d_out, int out_size)
{
    (void)in_sizes; (void)n_in; (void)out_size;
    const float* x  = (const float*)d_in[0];
    const float* Wq = (const float*)d_in[1];
    const float* bq = (const float*)d_in[2];
    const float* Wk = (const float*)d_in[3];
    const float* bk = (const float*)d_in[4];
    const float* Wv = (const float*)d_in[5];
    const float* bv = (const float*)d_in[6];
    const float* Wf = (const float*)d_in[7];
    const float* bf = (const float*)d_in[8];
    float* out = (float*)d_out;

    __nv_bfloat16 *qh, *ql, *kh, *kl, *vh, *xth, *xtl, *oth, *otl;
    __nv_bfloat16 *wvh, *wvl, *wfh, *wfl, *wqkh, *wqkl;
    cudaGetSymbolAddress((void**)&qh,   g_qh);
    cudaGetSymbolAddress((void**)&ql,   g_ql);
    cudaGetSymbolAddress((void**)&kh,   g_kh);
    cudaGetSymbolAddress((void**)&kl,   g_kl);
    cudaGetSymbolAddress((void**)&vh,   g_vh);
    cudaGetSymbolAddress((void**)&xth,  g_xth);
    cudaGetSymbolAddress((void**)&xtl,  g_xtl);
    cudaGetSymbolAddress((void**)&oth,  g_oth);
    cudaGetSymbolAddress((void**)&otl,  g_otl);
    cudaGetSymbolAddress((void**)&wvh,  g_wvh);
    cudaGetSymbolAddress((void**)&wvl,  g_wvl);
    cudaGetSymbolAddress((void**)&wfh,  g_wfh);
    cudaGetSymbolAddress((void**)&wfl,  g_wfl);
    cudaGetSymbolAddress((void**)&wqkh, g_wqkh);
    cudaGetSymbolAddress((void**)&wqkl, g_wqkl);

    cudaFuncSetAttribute(flash_mma_kernel,
                         cudaFuncAttributeMaxDynamicSharedMemorySize, FL_SMEM);
    cudaFuncSetAttribute(proj_qkv_kernel,
                         cudaFuncAttributeMaxDynamicSharedMemorySize, PM_SMEM);
    cudaFuncSetAttribute(proj_f_mma_kernel,
                         cudaFuncAttributeMaxDynamicSharedMemorySize, PM_SMEM);

    // fused operand prep (xsplit + W splits)
    prep_kernel<<<2624, 256>>>(x, Wq, Wk, Wv, Wf,
                               xth, xtl, wvh, wvl, wfh, wfl, wqkh, wqkl);

    // fused Q/K/V projections on tensor cores
    proj_qkv_kernel<<<dim3(64, 3, B_), 256, PM_SMEM>>>(
        wvh, wvl, xth, xtl, bv, vh,
        wqkh, wqkl, bq, bk, qh, ql, kh, kl);

    // attention (pipelined, ILP-2 PV) -> O bf16 hi/lo [b][N][C]
    flash_mma_kernel<<<dim3(N_ / 64, B_), 256, FL_SMEM>>>(qh, ql, kh, kl, vh, oth, otl);

    // final projection on tensor cores -> fp32 out
    proj_f_mma_kernel<<<dim3(N_ / 64, 2, B_), 256, PM_SMEM>>>(wfh, wfl, oth, otl, bf, out);
}

// round 16
// speedup vs baseline: 2.1189x; 1.3675x over previous
#include <cuda_runtime.h>
#include <cuda_bf16.h>
#include <cuda_fp16.h>
#include <cstdint>

static constexpr int B_   = 8;
static constexpr int C_   = 256;
static constexpr int CQK_ = 32;
static constexpr int N_   = 4096;

// Scratch
__device__ __align__(256) __nv_bfloat16 g_qh[(size_t)B_ * N_ * CQK_];
__device__ __align__(256) __nv_bfloat16 g_ql[(size_t)B_ * N_ * CQK_];
__device__ __align__(256) __nv_bfloat16 g_kh[(size_t)B_ * N_ * CQK_];
__device__ __align__(256) __nv_bfloat16 g_kl[(size_t)B_ * N_ * CQK_];
__device__ __align__(256) __half        g_vh[(size_t)B_ * C_ * N_];    // fp16 V
__device__ __align__(256) __nv_bfloat16 g_xth[(size_t)B_ * N_ * C_];
__device__ __align__(256) __nv_bfloat16 g_xtl[(size_t)B_ * N_ * C_];
__device__ __align__(256) __nv_bfloat16 g_oth[(size_t)B_ * N_ * C_];
__device__ __align__(256) __nv_bfloat16 g_otl[(size_t)B_ * N_ * C_];
__device__ __align__(256) __nv_bfloat16 g_wvh[C_ * C_], g_wvl[C_ * C_];
__device__ __align__(256) __nv_bfloat16 g_wfh[C_ * C_], g_wfl[C_ * C_];
__device__ __align__(256) __nv_bfloat16 g_wqkh[64 * C_], g_wqkl[64 * C_];

// ---------------- helpers ----------------
__device__ __forceinline__ uint32_t smem_u32(const void* p) {
    uint32_t a;
    asm("{ .reg .u64 t; cvta.to.shared.u64 t, %1; cvt.u32.u64 %0, t; }" : "=r"(a) : "l"(p));
    return a;
}
__device__ __forceinline__ void cpa16(uint32_t dst, const void* src) {
    asm volatile("cp.async.cg.shared.global [%0], [%1], 16;" :: "r"(dst), "l"(src) : "memory");
}
#define CPA_COMMIT() asm volatile("cp.async.commit_group;" ::: "memory")
#define CPA_WAIT(n)  asm volatile("cp.async.wait_group %0;" :: "n"(n) : "memory")
#define BAR_SYNC(id, cnt)   asm volatile("bar.sync %0, %1;"   :: "r"(id), "r"(cnt) : "memory")
#define BAR_ARRIVE(id, cnt) asm volatile("bar.arrive %0, %1;" :: "r"(id), "r"(cnt) : "memory")

__device__ __forceinline__ void ldsm4(uint32_t addr, uint32_t* r) {
    asm volatile("ldmatrix.sync.aligned.m8n8.x4.shared.b16 {%0,%1,%2,%3}, [%4];"
                 : "=r"(r[0]), "=r"(r[1]), "=r"(r[2]), "=r"(r[3]) : "r"(addr));
}
// bf16 MMA (QK, projections)
__device__ __forceinline__ void mma16816(float* d, const uint32_t* a, uint32_t b0, uint32_t b1) {
    asm volatile("mma.sync.aligned.m16n8k16.row.col.f32.bf16.bf16.f32 "
                 "{%0,%1,%2,%3}, {%4,%5,%6,%7}, {%8,%9}, {%0,%1,%2,%3};"
                 : "+f"(d[0]), "+f"(d[1]), "+f"(d[2]), "+f"(d[3])
                 : "r"(a[0]), "r"(a[1]), "r"(a[2]), "r"(a[3]), "r"(b0), "r"(b1));
}
// fp16 MMA (PV)
__device__ __forceinline__ void mma16816h(float* d, const uint32_t* a, uint32_t b0, uint32_t b1) {
    asm volatile("mma.sync.aligned.m16n8k16.row.col.f32.f16.f16.f32 "
                 "{%0,%1,%2,%3}, {%4,%5,%6,%7}, {%8,%9}, {%0,%1,%2,%3};"
                 : "+f"(d[0]), "+f"(d[1]), "+f"(d[2]), "+f"(d[3])
                 : "r"(a[0]), "r"(a[1]), "r"(a[2]), "r"(a[3]), "r"(b0), "r"(b1));
}
__device__ __forceinline__ uint32_t pack_bf16x2(float e0, float e1) {
    uint32_t r; asm("cvt.rn.bf16x2.f32 %0, %1, %2;" : "=r"(r) : "f"(e1), "f"(e0)); return r;
}
__device__ __forceinline__ uint32_t pack_f16x2(float e0, float e1) {
    uint32_t r; asm("cvt.rn.f16x2.f32 %0, %1, %2;" : "=r"(r) : "f"(e1), "f"(e0)); return r;
}
__device__ __forceinline__ float lo_bf16_f(uint32_t u) { return __uint_as_float(u << 16); }
__device__ __forceinline__ float hi_bf16_f(uint32_t u) { return __uint_as_float(u & 0xffff0000u); }
__device__ __forceinline__ void bf16_split(float v, __nv_bfloat16& h, __nv_bfloat16& l) {
    h = __float2bfloat16(v);
    l = __float2bfloat16(v - __bfloat162float(h));
}

// ---------------- fused prep: xsplit + Wv/Wf split + Wq||Wk split --------------
__global__ __launch_bounds__(256)
void prep_kernel(const float* __restrict__ X,
                 const float* __restrict__ Wq, const float* __restrict__ Wk,
                 const float* __restrict__ Wv, const float* __restrict__ Wf,
                 __nv_bfloat16* __restrict__ Xh, __nv_bfloat16* __restrict__ Xl,
                 __nv_bfloat16* __restrict__ Wvh, __nv_bfloat16* __restrict__ Wvl,
                 __nv_bfloat16* __restrict__ Wfh, __nv_bfloat16* __restrict__ Wfl,
                 __nv_bfloat16* __restrict__ Wqkh, __nv_bfloat16* __restrict__ Wqkl)
{
    __shared__ float t[64][65];
    const int id  = blockIdx.x;
    const int tid = threadIdx.x;

    if (id < 2048) {
        const int bx = id & 63, by = (id >> 6) & 3, bz = id >> 8;
        const int n0 = bx * 64, c0 = by * 64, b = bz;
        for (int i = tid; i < 4096; i += 256) {
            int c = i >> 6, n = i & 63;
            t[c][n] = X[(size_t)b * C_ * N_ + (size_t)(c0 + c) * N_ + n0 + n];
        }
        __syncthreads();
        for (int i = tid; i < 2048; i += 256) {
            int n = i >> 5, c2 = (i & 31) * 2;
            float v0 = t[c2][n], v1 = t[c2 + 1][n];
            __nv_bfloat16 h0, l0, h1, l1;
            bf16_split(v0, h0, l0);
            bf16_split(v1, h1, l1);
            __nv_bfloat162 hh, ll;
            hh.x = h0; hh.y = h1; ll.x = l0; ll.y = l1;
            size_t o = ((size_t)b * N_ + n0 + n) * C_ + c0 + c2;
            *(__nv_bfloat162*)&Xh[o] = hh;
            *(__nv_bfloat162*)&Xl[o] = ll;
        }
    } else if (id < 2304) {
        int i = (id - 2048) * 256 + tid;
        float v = Wv[i];
        __nv_bfloat16 h, l; bf16_split(v, h, l);
        Wvh[i] = h; Wvl[i] = l;
    } else if (id < 2560) {
        int i = (id - 2304) * 256 + tid;
        float v = Wf[i];
        __nv_bfloat16 h, l; bf16_split(v, h, l);
        Wfh[i] = h; Wfl[i] = l;
    } else {
        int i = (id - 2560) * 256 + tid;
        int row = i >> 8, col = i & 255;
        float v = (row < 32) ? Wq[(size_t)row * 256 + col]
                             : Wk[(size_t)(row - 32) * 256 + col];
        __nv_bfloat16 h, l; bf16_split(v, h, l);
        Wqkh[i] = h; Wqkl[i] = l;
    }
}

// ---------------- fused projection kernel: V path (y<2, fp16 out) + QK (y==2) -
static constexpr int PM_SW   = 0;
static constexpr int PM_SX   = 73728;
static constexpr int PM_SMEM = 110592;

__global__ __launch_bounds__(256, 2)
void proj_qkv_kernel(const __nv_bfloat16* __restrict__ Wvh, const __nv_bfloat16* __restrict__ Wvl,
                     const __nv_bfloat16* __restrict__ Xh, const __nv_bfloat16* __restrict__ Xl,
                     const float* __restrict__ bv, __half* __restrict__ Vh,
                     const __nv_bfloat16* __restrict__ Wqkh, const __nv_bfloat16* __restrict__ Wqkl,
                     const float* __restrict__ bq, const float* __restrict__ bk,
                     __nv_bfloat16* __restrict__ Qh, __nv_bfloat16* __restrict__ Ql,
                     __nv_bfloat16* __restrict__ Kh, __nv_bfloat16* __restrict__ Kl)
{
    extern __shared__ char smem[];
    const uint32_t sb = smem_u32(smem);
    const int tid = threadIdx.x, lane = tid & 31, w = tid >> 5;
    const int b  = blockIdx.z;
    const int mw = w * 16;

    if (blockIdx.y < 2) {
        const int m0 = blockIdx.y * 128;
        const int n0 = blockIdx.x * 64;

        auto load_wx = [&](int ks, int bi) {
            const int k0 = ks * 64;
            for (int i = tid; i < 2048; i += 256) {
                int half = i >> 10, r = (i >> 3) & 127, ch = i & 7;
                const __nv_bfloat16* src = (half ? Wvl : Wvh) + (size_t)(m0 + r) * 256 + k0 + ch * 8;
                cpa16(sb + PM_SW + bi * 36864 + half * 18432 + r * 144 + ch * 16, src);
            }
            for (int i = tid; i < 1024; i += 256) {
                int half = i >> 9, r = (i >> 3) & 63, ch = i & 7;
                const __nv_bfloat16* src = (half ? Xl : Xh) + ((size_t)b * N_ + n0 + r) * 256 + k0 + ch * 8;
                cpa16(sb + PM_SX + bi * 18432 + half * 9216 + r * 144 + ch * 16, src);
            }
        };

        load_wx(0, 0); CPA_COMMIT();
        load_wx(1, 1); CPA_COMMIT();

        float oacc[8][4];
#pragma unroll
        for (int i = 0; i < 8; i++)
#pragma unroll
            for (int j = 0; j < 4; j++) oacc[i][j] = 0.f;

#pragma unroll
        for (int ks = 0; ks < 4; ks++) {
            const int bi = ks & 1;
            if (ks < 2) { CPA_WAIT(1); } else { CPA_WAIT(0); }
            __syncthreads();

            const uint32_t wb_hi = sb + PM_SW + bi * 36864;
            const uint32_t xb_hi = sb + PM_SX + bi * 18432;

            uint32_t ah[4][4], al[4][4];
#pragma unroll
            for (int kc = 0; kc < 4; kc++) {
                uint32_t addr = wb_hi + (uint32_t)(mw + (lane & 15)) * 144
                              + (uint32_t)(kc * 16 + (lane >> 4) * 8) * 2;
                ldsm4(addr, ah[kc]);
                ldsm4(addr + 18432, al[kc]);
            }

#pragma unroll
            for (int nb = 0; nb < 8; nb++) {
                uint32_t rowoff = xb_hi + (uint32_t)(nb * 8 + (lane & 7)) * 144;
                uint32_t bh[8], bl[8];
#pragma unroll
                for (int kk = 0; kk < 2; kk++) {
                    uint32_t off = (uint32_t)(kk * 32 + (lane >> 3) * 8) * 2;
                    ldsm4(rowoff + off, &bh[4 * kk]);
                    ldsm4(rowoff + off + 9216, &bl[4 * kk]);
                }
#pragma unroll
                for (int kc = 0; kc < 4; kc++) {
                    int ix = (kc >> 1) * 4 + (kc & 1) * 2;
                    mma16816(oacc[nb], ah[kc], bh[ix], bh[ix + 1]);
                    mma16816(oacc[nb], al[kc], bh[ix], bh[ix + 1]);
                    mma16816(oacc[nb], ah[kc], bl[ix], bl[ix + 1]);
                }
            }

            __syncthreads();
            if (ks + 2 < 4) { load_wx(ks + 2, bi); CPA_COMMIT(); }
        }

        const int r0 = m0 + mw + (lane >> 2);
        const float b0f = bv[r0], b1f = bv[r0 + 8];
#pragma unroll
        for (int nb = 0; nb < 8; nb++) {
            int col = n0 + nb * 8 + (lane & 3) * 2;
            float v0 = oacc[nb][0] + b0f, v1 = oacc[nb][1] + b0f;
            float v2 = oacc[nb][2] + b1f, v3 = oacc[nb][3] + b1f;
            __half* Yb = Vh + (size_t)b * C_ * N_;
            *(uint32_t*)&Yb[(size_t)r0 * N_ + col]       = pack_f16x2(v0, v1);
            *(uint32_t*)&Yb[(size_t)(r0 + 8) * N_ + col] = pack_f16x2(v2, v3);
        }
    } else {
        if (blockIdx.x >= 32) return;
        const int m0 = blockIdx.x * 128;

        auto load_ab = [&](int ks, int bi) {
            const int k0 = ks * 64;
            for (int i = tid; i < 2048; i += 256) {
                int half = i >> 10, r = (i >> 3) & 127, ch = i & 7;
                const __nv_bfloat16* src = (half ? Xl : Xh) + ((size_t)b * N_ + m0 + r) * 256 + k0 + ch * 8;
                cpa16(sb + PM_SW + bi * 36864 + half * 18432 + r * 144 + ch * 16, src);
            }
            for (int i = tid; i < 1024; i += 256) {
                int half = i >> 9, r = (i >> 3) & 63, ch = i & 7;
                const __nv_bfloat16* src = (half ? Wqkl : Wqkh) + (size_t)r * 256 + k0 + ch * 8;
                cpa16(sb + PM_SX + bi * 18432 + half * 9216 + r * 144 + ch * 16, src);
            }
        };

        load_ab(0, 0); CPA_COMMIT();
        load_ab(1, 1); CPA_COMMIT();

        float oacc[8][4];
#pragma unroll
        for (int i = 0; i < 8; i++)
#pragma unroll
            for (int j = 0; j < 4; j++) oacc[i][j] = 0.f;

#pragma unroll
        for (int ks = 0; ks < 4; ks++) {
            const int bi = ks & 1;
            if (ks < 2) { CPA_WAIT(1); } else { CPA_WAIT(0); }
            __syncthreads();

            const uint32_t ab_hi = sb + PM_SW + bi * 36864;
            const uint32_t bb_hi = sb + PM_SX + bi * 18432;

            uint32_t ah[4][4], al[4][4];
#pragma unroll
            for (int kc = 0; kc < 4; kc++) {
                uint32_t addr = ab_hi + (uint32_t)(mw + (lane & 15)) * 144
                              + (uint32_t)(kc * 16 + (lane >> 4) * 8) * 2;
                ldsm4(addr, ah[kc]);
                ldsm4(addr + 18432, al[kc]);
            }

#pragma unroll
            for (int nb = 0; nb < 8; nb++) {
                uint32_t rowoff = bb_hi + (uint32_t)(nb * 8 + (lane & 7)) * 144;
                uint32_t bh[8], bl[8];
#pragma unroll
                for (int kk = 0; kk < 2; kk++) {
                    uint32_t off = (uint32_t)(kk * 32 + (lane >> 3) * 8) * 2;
                    ldsm4(rowoff + off, &bh[4 * kk]);
                    ldsm4(rowoff + off + 9216, &bl[4 * kk]);
                }
#pragma unroll
                for (int kc = 0; kc < 4; kc++) {
                    int ix = (kc >> 1) * 4 + (kc & 1) * 2;
                    mma16816(oacc[nb], ah[kc], bh[ix], bh[ix + 1]);
                    mma16816(oacc[nb], al[kc], bh[ix], bh[ix + 1]);
                    mma16816(oacc[nb], ah[kc], bl[ix], bl[ix + 1]);
                }
            }

            __syncthreads();
            if (ks + 2 < 4) { load_ab(ks + 2, bi); CPA_COMMIT(); }
        }

        const int r0 = m0 + mw + (lane >> 2);
#pragma unroll
        for (int nb = 0; nb < 8; nb++) {
            int c = nb * 8 + (lane & 3) * 2;
            const bool isQ = (c < 32);
            const int cc = isQ ? c : c - 32;
            const float bb0 = isQ ? bq[cc] : bk[cc];
            const float bb1 = isQ ? bq[cc + 1] : bk[cc + 1];
            float v0 = oacc[nb][0] + bb0, v1 = oacc[nb][1] + bb1;
            float v2 = oacc[nb][2] + bb0, v3 = oacc[nb][3] + bb1;
            uint32_t h01 = pack_bf16x2(v0, v1);
            uint32_t l01 = pack_bf16x2(v0 - lo_bf16_f(h01), v1 - hi_bf16_f(h01));
            uint32_t h23 = pack_bf16x2(v2, v3);
            uint32_t l23 = pack_bf16x2(v2 - lo_bf16_f(h23), v3 - hi_bf16_f(h23));
            __nv_bfloat16* dh = isQ ? Qh : Kh;
            __nv_bfloat16* dl = isQ ? Ql : Kl;
            size_t o0 = ((size_t)b * N_ + r0) * CQK_ + cc;
            size_t o1 = ((size_t)b * N_ + r0 + 8) * CQK_ + cc;
            *(uint32_t*)&dh[o0] = h01;
            *(uint32_t*)&dl[o0] = l01;
            *(uint32_t*)&dh[o1] = h23;
            *(uint32_t*)&dl[o1] = l23;
        }
    }
}

// ---------------- final projection (tensor cores, fp32 out) -------------------
__global__ __launch_bounds__(256, 2)
void proj_f_mma_kernel(const __nv_bfloat16* __restrict__ Wh, const __nv_bfloat16* __restrict__ Wl,
                       const __nv_bfloat16* __restrict__ Xh, const __nv_bfloat16* __restrict__ Xl,
                       const float* __restrict__ bias, float* __restrict__ Yout)
{
    extern __shared__ char smem[];
    const uint32_t sb = smem_u32(smem);
    const int tid = threadIdx.x, lane = tid & 31, w = tid >> 5;
    const int b  = blockIdx.z;
    const int m0 = blockIdx.y * 128;
    const int n0 = blockIdx.x * 64;
    const int mw = w * 16;

    auto load_wx = [&](int ks, int bi) {
        const int k0 = ks * 64;
        for (int i = tid; i < 2048; i += 256) {
            int half = i >> 10, r = (i >> 3) & 127, ch = i & 7;
            const __nv_bfloat16* src = (half ? Wl : Wh) + (size_t)(m0 + r) * 256 + k0 + ch * 8;
            cpa16(sb + PM_SW + bi * 36864 + half * 18432 + r * 144 + ch * 16, src);
        }
        for (int i = tid; i < 1024; i += 256) {
            int half = i >> 9, r = (i >> 3) & 63, ch = i & 7;
            const __nv_bfloat16* src = (half ? Xl : Xh) + ((size_t)b * N_ + n0 + r) * 256 + k0 + ch * 8;
            cpa16(sb + PM_SX + bi * 18432 + half * 9216 + r * 144 + ch * 16, src);
        }
    };

    load_wx(0, 0); CPA_COMMIT();
    load_wx(1, 1); CPA_COMMIT();

    float oacc[8][4];
#pragma unroll
    for (int i = 0; i < 8; i++)
#pragma unroll
        for (int j = 0; j < 4; j++) oacc[i][j] = 0.f;

#pragma unroll
    for (int ks = 0; ks < 4; ks++) {
        const int bi = ks & 1;
        if (ks < 2) { CPA_WAIT(1); } else { CPA_WAIT(0); }
        __syncthreads();

        const uint32_t wb_hi = sb + PM_SW + bi * 36864;
        const uint32_t xb_hi = sb + PM_SX + bi * 18432;

        uint32_t ah[4][4], al[4][4];
#pragma unroll
        for (int kc = 0; kc < 4; kc++) {
            uint32_t addr = wb_hi + (uint32_t)(mw + (lane & 15)) * 144
                          + (uint32_t)(kc * 16 + (lane >> 4) * 8) * 2;
            ldsm4(addr, ah[kc]);
            ldsm4(addr + 18432, al[kc]);
        }

#pragma unroll
        for (int nb = 0; nb < 8; nb++) {
            uint32_t rowoff = xb_hi + (uint32_t)(nb * 8 + (lane & 7)) * 144;
            uint32_t bh[8], bl[8];
#pragma unroll
            for (int kk = 0; kk < 2; kk++) {
                uint32_t off = (uint32_t)(kk * 32 + (lane >> 3) * 8) * 2;
                ldsm4(rowoff + off, &bh[4 * kk]);
                ldsm4(rowoff + off + 9216, &bl[4 * kk]);
            }
#pragma unroll
            for (int kc = 0; kc < 4; kc++) {
                int ix = (kc >> 1) * 4 + (kc & 1) * 2;
                mma16816(oacc[nb], ah[kc], bh[ix], bh[ix + 1]);
                mma16816(oacc[nb], al[kc], bh[ix], bh[ix + 1]);
                mma16816(oacc[nb], ah[kc], bl[ix], bl[ix + 1]);
            }
        }

        __syncthreads();
        if (ks + 2 < 4) { load_wx(ks + 2, bi); CPA_COMMIT(); }
    }

    const int r0 = m0 + mw + (lane >> 2);
    const float b0f = bias[r0], b1f = bias[r0 + 8];
#pragma unroll
    for (int nb = 0; nb < 8; nb++) {
        int col = n0 + nb * 8 + (lane & 3) * 2;
        float* Yf = Yout + (size_t)b * C_ * N_;
        *(float2*)&Yf[(size_t)r0 * N_ + col] =
            make_float2(oacc[nb][0] + b0f, oacc[nb][1] + b0f);
        *(float2*)&Yf[(size_t)(r0 + 8) * N_ + col] =
            make_float2(oacc[nb][2] + b1f, oacc[nb][3] + b1f);
    }
}

// ---------------- flash attention: 3-term bf16 QK, single-term fp16 PV --------
// smem: P exchange (hi only) [0,8192); sinv [8192,8448);
//       K bufs 2 x 10240 (hi|lo) [10240,30720); V bufs 2 x 36864 [30720,104448).
// Q tile overlays [0,10240) until qa fragments loaded.
static constexpr int SP_HI = 0;
static constexpr int S_INV = 8192;
static constexpr int SQH   = 0;
static constexpr int SQL   = 5120;
static constexpr int SKB   = 10240;
static constexpr int SVB   = 30720;
static constexpr int FL_SMEM = 104448;
static constexpr float EXP_BIAS = 6.0f;

// single-term fp16 PV, ILP=2
__device__ __forceinline__ void pv_pair(float* oa, float* ob,
                                        const uint32_t pah[4][4],
                                        uint32_t vh_b, int c0, int c1, int lane)
{
    uint32_t vfa[8], vfb[8];
    uint32_t ra = (uint32_t)(c0 + (lane & 7)) * 144;
    uint32_t rb = (uint32_t)(c1 + (lane & 7)) * 144;
#pragma unroll
    for (int kjp = 0; kjp < 2; kjp++) {
        uint32_t off = (uint32_t)(kjp * 32 + (lane >> 3) * 8) * 2;
        ldsm4(vh_b + ra + off, &vfa[4 * kjp]);
        ldsm4(vh_b + rb + off, &vfb[4 * kjp]);
    }
#pragma unroll
    for (int kj = 0; kj < 4; kj++) {
        int ix = (kj >> 1) * 4 + (kj & 1) * 2;
        mma16816h(oa, pah[kj], vfa[ix], vfa[ix + 1]);
        mma16816h(ob, pah[kj], vfb[ix], vfb[ix + 1]);
    }
}

__global__ __launch_bounds__(256, 2)
void flash_mma_kernel(const __nv_bfloat16* __restrict__ Qh, const __nv_bfloat16* __restrict__ Ql,
                      const __nv_bfloat16* __restrict__ Kh, const __nv_bfloat16* __restrict__ Kl,
                      const __half* __restrict__ Vh,
                      __nv_bfloat16* __restrict__ Oh, __nv_bfloat16* __restrict__ Ol)
{
    extern __shared__ char smem[];
    const uint32_t sb = smem_u32(smem);
    const int tid = threadIdx.x, lane = tid & 31, w = tid >> 5;
    const int qw = (w & 3) * 16;
    const int b = blockIdx.y, q0 = blockIdx.x * 64;

    // ---- prologue: Q (hi+lo), K0/K1 (hi+lo), V0/V1 ----
    for (int i = tid; i < 512; i += 256) {
        int half = i >> 8, r = (i >> 2) & 63, ch = i & 3;
        const __nv_bfloat16* src = (half ? Ql : Qh) + ((size_t)b * N_ + q0 + r) * CQK_ + ch * 8;
        cpa16(sb + (half ? SQL : SQH) + r * 80 + ch * 16, src);
    }
    for (int t = 0; t < 2; t++) {
        const int j0 = t * 64;
        for (int i = tid; i < 512; i += 256) {
            int half = i >> 8, r = (i >> 2) & 63, ch = i & 3;
            const __nv_bfloat16* src = (half ? Kl : Kh) + ((size_t)b * N_ + j0 + r) * CQK_ + ch * 8;
            cpa16(sb + SKB + t * 10240 + half * 5120 + r * 80 + ch * 16, src);
        }
        for (int i = tid; i < 2048; i += 256) {
            int r = i >> 3, ch = i & 7;
            const __half* src = Vh + ((size_t)b * C_ + r) * N_ + j0 + ch * 8;
            cpa16(sb + SVB + t * 36864 + r * 144 + ch * 16, src);
        }
        CPA_COMMIT();
    }
    CPA_WAIT(0);
    __syncthreads();

    float* sinv = (float*)(smem + S_INV);
    const int qg = q0 + qw + (lane >> 2);
    const size_t rbase0 = ((size_t)b * N_ + qg) * C_;
    const size_t rbase1 = ((size_t)b * N_ + qg + 8) * C_;

    if (w < 4) {
        // ========================= PRODUCER =========================
        uint32_t qa[2][2][4];
#pragma unroll
        for (int hl = 0; hl < 2; hl++)
#pragma unroll
            for (int kc = 0; kc < 2; kc++) {
                uint32_t addr = sb + (hl ? SQL : SQH)
                              + (uint32_t)(qw + (lane & 15)) * 80
                              + (uint32_t)(kc * 16 + (lane >> 4) * 8) * 2;
                ldsm4(addr, qa[hl][kc]);
            }
        BAR_SYNC(5, 128);

        float oacc[10][4];
#pragma unroll
        for (int i = 0; i < 10; i++)
#pragma unroll
            for (int j = 0; j < 4; j++) oacc[i][j] = 0.f;
        float rsum0 = 0.f, rsum1 = 0.f;

        char* ph_dst = smem + SP_HI + (w & 3) * 2048 + lane * 16;

        for (int kt = 0; kt < 64; kt++) {
            const int bi = kt & 1;
            const uint32_t kh_b = sb + SKB + bi * 10240, kl_b = kh_b + 5120;
            const uint32_t vh_b = sb + SVB + bi * 36864;

            // S = QK^T (3-term bf16)
            float sacc[8][4];
#pragma unroll
            for (int i = 0; i < 8; i++)
#pragma unroll
                for (int j = 0; j < 4; j++) sacc[i][j] = 0.f;
#pragma unroll
            for (int kc = 0; kc < 2; kc++)
#pragma unroll
                for (int nbp = 0; nbp < 4; nbp++) {
                    uint32_t off = (uint32_t)((nbp * 2 + ((lane >> 4) & 1)) * 8 + (lane & 7)) * 80
                                 + (uint32_t)(kc * 16 + ((lane >> 3) & 1) * 8) * 2;
                    uint32_t bh[4], bl[4];
                    ldsm4(kh_b + off, bh);
                    ldsm4(kl_b + off, bl);
                    mma16816(sacc[2*nbp],   qa[0][kc], bh[0], bh[1]);
                    mma16816(sacc[2*nbp+1], qa[0][kc], bh[2], bh[3]);
                    mma16816(sacc[2*nbp],   qa[1][kc], bh[0], bh[1]);
                    mma16816(sacc[2*nbp+1], qa[1][kc], bh[2], bh[3]);
                    mma16816(sacc[2*nbp],   qa[0][kc], bl[0], bl[1]);
                    mma16816(sacc[2*nbp+1], qa[0][kc], bl[2], bl[3]);
                }

            // P = exp(S - bias), fp16 single (bias cancels in normalization)
            uint32_t pah[4][4];
#pragma unroll
            for (int nb = 0; nb < 8; nb++) {
                float e0 = __expf(sacc[nb][0] - EXP_BIAS);
                float e1 = __expf(sacc[nb][1] - EXP_BIAS);
                float e2 = __expf(sacc[nb][2] - EXP_BIAS);
                float e3 = __expf(sacc[nb][3] - EXP_BIAS);
                rsum0 += e0 + e1;
                rsum1 += e2 + e3;
                int kj = nb >> 1, o = (nb & 1) * 2;
                pah[kj][o]     = pack_f16x2(e0, e1);
                pah[kj][o + 1] = pack_f16x2(e2, e3);
            }

            if (kt > 0) BAR_SYNC(2, 256);   // P buffer free
#pragma unroll
            for (int kj = 0; kj < 4; kj++)
                *(uint4*)(ph_dst + kj * 512) = make_uint4(pah[kj][0], pah[kj][1], pah[kj][2], pah[kj][3]);
            BAR_ARRIVE(1, 256);             // P(kt) ready

            if (kt > 0) BAR_SYNC(3, 256);   // V(kt) ready

            // PV channels 0..79 : 5 pairs (single-term fp16)
#pragma unroll
            for (int cp = 0; cp < 5; cp++)
                pv_pair(oacc[2*cp], oacc[2*cp+1], pah, vh_b,
                        (2*cp) * 8, (2*cp+1) * 8, lane);
            BAR_ARRIVE(4, 256);             // done with V(kt)

            if (kt + 2 < 64) {
                const int j0 = (kt + 2) * 64;
                const uint32_t kd = sb + SKB + bi * 10240;
                for (int i = tid; i < 512; i += 128) {
                    int half = i >> 8, r = (i >> 2) & 63, ch = i & 3;
                    const __nv_bfloat16* src = (half ? Kl : Kh) + ((size_t)b * N_ + j0 + r) * CQK_ + ch * 8;
                    cpa16(kd + half * 5120 + r * 80 + ch * 16, src);
                }
            }
            CPA_COMMIT();
            CPA_WAIT(1);
            BAR_SYNC(5, 128);
        }

        rsum0 += __shfl_xor_sync(0xffffffffu, rsum0, 1);
        rsum0 += __shfl_xor_sync(0xffffffffu, rsum0, 2);
        rsum1 += __shfl_xor_sync(0xffffffffu, rsum1, 1);
        rsum1 += __shfl_xor_sync(0xffffffffu, rsum1, 2);
        if ((lane & 3) == 0) {
            sinv[qw + (lane >> 2)]     = rsum0;
            sinv[qw + 8 + (lane >> 2)] = rsum1;
        }
        __syncwarp();
        BAR_ARRIVE(7, 256);

        const float inv0 = 1.f / sinv[qw + (lane >> 2)];
        const float inv1 = 1.f / sinv[qw + 8 + (lane >> 2)];
#pragma unroll
        for (int cb = 0; cb < 10; cb++) {
            int c = cb * 8 + (lane & 3) * 2;
            float v0 = oacc[cb][0] * inv0, v1 = oacc[cb][1] * inv0;
            float v2 = oacc[cb][2] * inv1, v3 = oacc[cb][3] * inv1;
            uint32_t h01 = pack_bf16x2(v0, v1);
            uint32_t l01 = pack_bf16x2(v0 - lo_bf16_f(h01), v1 - hi_bf16_f(h01));
            uint32_t h23 = pack_bf16x2(v2, v3);
            uint32_t l23 = pack_bf16x2(v2 - lo_bf16_f(h23), v3 - hi_bf16_f(h23));
            *(uint32_t*)&Oh[rbase0 + c] = h01;
            *(uint32_t*)&Ol[rbase0 + c] = l01;
            *(uint32_t*)&Oh[rbase1 + c] = h23;
            *(uint32_t*)&Ol[rbase1 + c] = l23;
        }
    } else {
        // ========================= CONSUMER =========================
        float oacc[22][4];
#pragma unroll
        for (int i = 0; i < 22; i++)
#pragma unroll
            for (int j = 0; j < 4; j++) oacc[i][j] = 0.f;

        const char* ph_src = smem + SP_HI + (w & 3) * 2048 + lane * 16;
        const int ctid = tid - 128;

        for (int kt = 0; kt < 64; kt++) {
            const int bi = kt & 1;
            const uint32_t vh_b = sb + SVB + bi * 36864;

            BAR_SYNC(1, 256);               // P(kt) ready
            uint32_t pah[4][4];
#pragma unroll
            for (int kj = 0; kj < 4; kj++) {
                uint4 h4 = *(const uint4*)(ph_src + kj * 512);
                pah[kj][0] = h4.x; pah[kj][1] = h4.y; pah[kj][2] = h4.z; pah[kj][3] = h4.w;
            }
            if (kt + 1 < 64) BAR_ARRIVE(2, 256);   // P buffer free

            // PV channels 80..255 : 11 pairs (single-term fp16)
#pragma unroll
            for (int cp = 0; cp < 11; cp++)
                pv_pair(oacc[2*cp], oacc[2*cp+1], pah, vh_b,
                        80 + (2*cp) * 8, 80 + (2*cp+1) * 8, lane);

            BAR_SYNC(4, 256);               // producers done with V(kt)
            if (kt + 2 < 64) {
                const int j0 = (kt + 2) * 64;
                const uint32_t vd = sb + SVB + bi * 36864;
                for (int i = ctid; i < 2048; i += 128) {
                    int r = i >> 3, ch = i & 7;
                    const __half* src = Vh + ((size_t)b * C_ + r) * N_ + j0 + ch * 8;
                    cpa16(vd + r * 144 + ch * 16, src);
                }
            }
            CPA_COMMIT();
            CPA_WAIT(1);
            BAR_SYNC(6, 128);
            if (kt + 1 < 64) BAR_ARRIVE(3, 256);   // V(kt+1) ready
        }

        BAR_SYNC(7, 256);
        const float inv0 = 1.f / sinv[qw + (lane >> 2)];
        const float inv1 = 1.f / sinv[qw + 8 + (lane >> 2)];
#pragma unroll
        for (int cb = 0; cb < 22; cb++) {
            int c = 80 + cb * 8 + (lane & 3) * 2;
            float v0 = oacc[cb][0] * inv0, v1 = oacc[cb][1] * inv0;
            float v2 = oacc[cb][2] * inv1, v3 = oacc[cb][3] * inv1;
            uint32_t h01 = pack_bf16x2(v0, v1);
            uint32_t l01 = pack_bf16x2(v0 - lo_bf16_f(h01), v1 - hi_bf16_f(h01));
            uint32_t h23 = pack_bf16x2(v2, v3);
            uint32_t l23 = pack_bf16x2(v2 - lo_bf16_f(h23), v3 - hi_bf16_f(h23));
            *(uint32_t*)&Oh[rbase0 + c] = h01;
            *(uint32_t*)&Ol[rbase0 + c] = l01;
            *(uint32_t*)&Oh[rbase1 + c] = h23;
            *(uint32_t*)&Ol[rbase1 + c] = l23;
        }
    }
}

// ---------------- kernel_launch ----------------
extern "C" void kernel_launch(void* const* d_in, const int* in_sizes, int n_in,
                              void* d_out, int out_size)
{
    (void)in_sizes; (void)n_in; (void)out_size;
    const float* x  = (const float*)d_in[0];
    const float* Wq = (const float*)d_in[1];
    const float* bq = (const float*)d_in[2];
    const float* Wk = (const float*)d_in[3];
    const float* bk = (const float*)d_in[4];
    const float* Wv = (const float*)d_in[5];
    const float* bv = (const float*)d_in[6];
    const float* Wf = (const float*)d_in[7];
    const float* bf = (const float*)d_in[8];
    float* out = (float*)d_out;

    __nv_bfloat16 *qh, *ql, *kh, *kl, *xth, *xtl, *oth, *otl;
    __nv_bfloat16 *wvh, *wvl, *wfh, *wfl, *wqkh, *wqkl;
    __half *vh;
    cudaGetSymbolAddress((void**)&qh,   g_qh);
    cudaGetSymbolAddress((void**)&ql,   g_ql);
    cudaGetSymbolAddress((void**)&kh,   g_kh);
    cudaGetSymbolAddress((void**)&kl,   g_kl);
    cudaGetSymbolAddress((void**)&vh,   g_vh);
    cudaGetSymbolAddress((void**)&xth,  g_xth);
    cudaGetSymbolAddress((void**)&xtl,  g_xtl);
    cudaGetSymbolAddress((void**)&oth,  g_oth);
    cudaGetSymbolAddress((void**)&otl,  g_otl);
    cudaGetSymbolAddress((void**)&wvh,  g_wvh);
    cudaGetSymbolAddress((void**)&wvl,  g_wvl);
    cudaGetSymbolAddress((void**)&wfh,  g_wfh);
    cudaGetSymbolAddress((void**)&wfl,  g_wfl);
    cudaGetSymbolAddress((void**)&wqkh, g_wqkh);
    cudaGetSymbolAddress((void**)&wqkl, g_wqkl);

    cudaFuncSetAttribute(flash_mma_kernel,
                         cudaFuncAttributeMaxDynamicSharedMemorySize, FL_SMEM);
    cudaFuncSetAttribute(proj_qkv_kernel,
                         cudaFuncAttributeMaxDynamicSharedMemorySize, PM_SMEM);
    cudaFuncSetAttribute(proj_f_mma_kernel,
                         cudaFuncAttributeMaxDynamicSharedMemorySize, PM_SMEM);

    // fused operand prep (xsplit + W splits)
    prep_kernel<<<2624, 256>>>(x, Wq, Wk, Wv, Wf,
                               xth, xtl, wvh, wvl, wfh, wfl, wqkh, wqkl);

    // fused Q/K/V projections on tensor cores (V -> fp16)
    proj_qkv_kernel<<<dim3(64, 3, B_), 256, PM_SMEM>>>(
        wvh, wvl, xth, xtl, bv, vh,
        wqkh, wqkl, bq, bk, qh, ql, kh, kl);

    // attention (3-term QK, single-term fp16 PV) -> O bf16 hi/lo [b][N][C]
    flash_mma_kernel<<<dim3(N_ / 64, B_), 256, FL_SMEM>>>(qh, ql, kh, kl, vh, oth, otl);

    // final projection on tensor cores -> fp32 out
    proj_f_mma_kernel<<<dim3(N_ / 64, 2, B_), 256, PM_SMEM>>>(wfh, wfl, oth, otl, bf, out);
}